// round 10
// baseline (speedup 1.0000x reference)
#include <cuda_runtime.h>
#include <cuda_bf16.h>
#include <math.h>
#include <stdint.h>

// Shapes (fixed): B=4, C=256, H=W=64, HW=4096, C8=32, C2=128
#define BB 4
#define CC 256
#define HW 4096
#define C8 32
#define C2 128

// ---------------- device scratch (allocation-free) ----------------
__device__ float g_q[BB * C8 * HW];            // 2 MB
__device__ float g_k[BB * C8 * HW];            // 2 MB
__device__ float g_v[BB * CC * HW];            // 16 MB
__device__ float g_v2[BB * CC * HW];           // 16 MB
__device__ float g_spA[BB * CC * HW];          // 16 MB
__device__ float g_aff[(size_t)BB * HW * HW];  // 268 MB
__device__ float g_wt[256 * 9 * 64];           // transposed q/k conv weights
__device__ float g_gate[BB * CC];
__device__ float g_cmean[BB * CC];
__device__ float g_cmax[BB * CC];
__device__ float g_sm[BB * 2 * HW];
__device__ float g_att[BB * HW];
__device__ float g_a[BB * 64 * 64];

// ---------------- K0: transpose conv weights to [ic][tap][64oc] ----------------
__global__ void k_wt(const float* __restrict__ qw, const float* __restrict__ kw) {
    int i = blockIdx.x * blockDim.x + threadIdx.x;  // over 256*9*32
    if (i >= 256 * 9 * 32) return;
    int oc = i % 32;
    int t  = (i / 32) % 9;
    int ic = i / (32 * 9);
    g_wt[(ic * 9 + t) * 64 + oc]      = qw[(oc * 256 + ic) * 9 + t];
    g_wt[(ic * 9 + t) * 64 + 32 + oc] = kw[(oc * 256 + ic) * 9 + t];
}

// ---------------- K1: fused q/k conv3x3 + BN + ReLU ----------------
// tile 8(h) x 16(w), block (16,8)=128 threads, each thread 64 accumulators
__global__ __launch_bounds__(128) void k_qkconv(
    const float* __restrict__ x,
    const float* __restrict__ qb, const float* __restrict__ qs,
    const float* __restrict__ qbb, const float* __restrict__ qm, const float* __restrict__ qv,
    const float* __restrict__ kb, const float* __restrict__ ks_,
    const float* __restrict__ kbb, const float* __restrict__ km, const float* __restrict__ kv)
{
    __shared__ float xt[10][18];
    __shared__ float wsm[576];
    int b  = blockIdx.z;
    int th = blockIdx.y;   // 0..7
    int tw = blockIdx.x;   // 0..3
    int tx = threadIdx.x, ty = threadIdx.y;
    int tid = ty * 16 + tx;

    float acc[64];
#pragma unroll
    for (int i = 0; i < 64; i++) acc[i] = 0.f;

    const float* xb = x + (size_t)b * CC * HW;

    for (int ic = 0; ic < 256; ic++) {
        // load 10x18 halo tile (zero pad)
        for (int i = tid; i < 180; i += 128) {
            int r = i / 18, c = i % 18;
            int gh = th * 8 + r - 1, gw = tw * 16 + c - 1;
            float v = 0.f;
            if (gh >= 0 && gh < 64 && gw >= 0 && gw < 64)
                v = xb[ic * HW + gh * 64 + gw];
            xt[r][c] = v;
        }
        // load 9*64 weights (float4)
        for (int i = tid; i < 144; i += 128)
            ((float4*)wsm)[i] = ((const float4*)(g_wt + ic * 576))[i];
        __syncthreads();

        float xv[9];
#pragma unroll
        for (int dy = 0; dy < 3; dy++)
#pragma unroll
            for (int dx = 0; dx < 3; dx++)
                xv[dy * 3 + dx] = xt[ty + dy][tx + dx];

#pragma unroll
        for (int t = 0; t < 9; t++) {
            float xvt = xv[t];
            const float4* wrow = (const float4*)(wsm + t * 64);
#pragma unroll
            for (int o4 = 0; o4 < 16; o4++) {
                float4 wv = wrow[o4];
                acc[o4 * 4 + 0] += xvt * wv.x;
                acc[o4 * 4 + 1] += xvt * wv.y;
                acc[o4 * 4 + 2] += xvt * wv.z;
                acc[o4 * 4 + 3] += xvt * wv.w;
            }
        }
        __syncthreads();
    }

    int h = th * 8 + ty, w = tw * 16 + tx;
    int p = h * 64 + w;
#pragma unroll
    for (int oc = 0; oc < 32; oc++) {
        float A  = rsqrtf(qv[oc] + 1e-5f) * qs[oc];
        float Bc = (qb[oc] - qm[oc]) * A + qbb[oc];
        g_q[((size_t)b * 32 + oc) * HW + p] = fmaxf(acc[oc] * A + Bc, 0.f);
    }
#pragma unroll
    for (int oc = 0; oc < 32; oc++) {
        float A  = rsqrtf(kv[oc] + 1e-5f) * ks_[oc];
        float Bc = (kb[oc] - km[oc]) * A + kbb[oc];
        g_k[((size_t)b * 32 + oc) * HW + p] = fmaxf(acc[32 + oc] * A + Bc, 0.f);
    }
}

// ---------------- K2: S[b][n][m] = sum_c q[b][c][n] * k[b][c][m] ----------------
__global__ __launch_bounds__(256) void k_qk_gemm() {
    __shared__ float Qs[32][64];
    __shared__ float Ks[32][64];
    int b  = blockIdx.z;
    int n0 = blockIdx.y * 64;
    int m0 = blockIdx.x * 64;
    int tid = threadIdx.x;
    const float* qbp = g_q + (size_t)b * C8 * HW;
    const float* kbp = g_k + (size_t)b * C8 * HW;

    for (int i = tid; i < 512; i += 256) {
        int r = i / 16, c4 = i % 16;
        ((float4*)&Qs[r][0])[c4] = *(const float4*)&qbp[r * HW + n0 + c4 * 4];
        ((float4*)&Ks[r][0])[c4] = *(const float4*)&kbp[r * HW + m0 + c4 * 4];
    }
    __syncthreads();

    int tx = tid % 16, ty = tid / 16;
    float acc[4][4] = {};
#pragma unroll
    for (int kk = 0; kk < 32; kk++) {
        float4 q4 = *(const float4*)&Qs[kk][ty * 4];
        float4 k4 = *(const float4*)&Ks[kk][tx * 4];
        float qa[4] = {q4.x, q4.y, q4.z, q4.w};
        float ka[4] = {k4.x, k4.y, k4.z, k4.w};
#pragma unroll
        for (int i = 0; i < 4; i++)
#pragma unroll
            for (int j = 0; j < 4; j++) acc[i][j] += qa[i] * ka[j];
    }
    float* out = g_aff + (size_t)b * HW * HW;
#pragma unroll
    for (int i = 0; i < 4; i++) {
        float4 v4 = make_float4(acc[i][0], acc[i][1], acc[i][2], acc[i][3]);
        *(float4*)&out[(size_t)(n0 + ty * 4 + i) * HW + m0 + tx * 4] = v4;
    }
}

// ---------------- K3: row softmax of aff (rows of 4096) ----------------
__global__ __launch_bounds__(256) void k_softmax() {
    size_t row = blockIdx.x;
    float* p = g_aff + row * HW;
    int tid = threadIdx.x;
    __shared__ float red[256];

    float4 v[4];
#pragma unroll
    for (int i = 0; i < 4; i++) v[i] = ((const float4*)p)[i * 256 + tid];

    float mx = -INFINITY;
#pragma unroll
    for (int i = 0; i < 4; i++) {
        mx = fmaxf(mx, fmaxf(fmaxf(v[i].x, v[i].y), fmaxf(v[i].z, v[i].w)));
    }
    red[tid] = mx; __syncthreads();
    for (int s = 128; s > 0; s >>= 1) {
        if (tid < s) red[tid] = fmaxf(red[tid], red[tid + s]);
        __syncthreads();
    }
    mx = red[0]; __syncthreads();

    float sum = 0.f;
#pragma unroll
    for (int i = 0; i < 4; i++) {
        v[i].x = expf(v[i].x - mx); v[i].y = expf(v[i].y - mx);
        v[i].z = expf(v[i].z - mx); v[i].w = expf(v[i].w - mx);
        sum += v[i].x + v[i].y + v[i].z + v[i].w;
    }
    red[tid] = sum; __syncthreads();
    for (int s = 128; s > 0; s >>= 1) {
        if (tid < s) red[tid] += red[tid + s];
        __syncthreads();
    }
    float inv = 1.f / red[0];
#pragma unroll
    for (int i = 0; i < 4; i++) {
        v[i].x *= inv; v[i].y *= inv; v[i].z *= inv; v[i].w *= inv;
        ((float4*)p)[i * 256 + tid] = v[i];
    }
}

// ---------------- 1x1 conv GEMM: out[b][o][p] = sum_c W[o][c]*x[b][c][p] + bias[o] ---
// 'which' selects the destination DEVICE global (0 -> g_v, 1 -> g_v2). The
// destination must be resolved in device code: passing a __device__ symbol as a
// host-side kernel argument passes the host shadow address (this was the bug).
__global__ __launch_bounds__(256) void k_1x1(
    const float* __restrict__ W, const float* __restrict__ bias,
    const float* __restrict__ x, int which)
{
    __shared__ float Ws[16][68];
    __shared__ float Xs[16][64];
    float* out = which ? g_v2 : g_v;
    int b  = blockIdx.z;
    int m0 = blockIdx.y * 64;   // output channel
    int n0 = blockIdx.x * 64;   // pixel
    int tid = threadIdx.x;
    const float* xb = x + (size_t)b * CC * HW;
    int tx = tid % 16, ty = tid / 16;
    float acc[4][4] = {};

    int mm = tid / 4, kq = tid % 4;
    int kkx = tid / 16, nq = tid % 16;

    for (int k0 = 0; k0 < 256; k0 += 16) {
        float4 wv = *(const float4*)&W[(m0 + mm) * 256 + k0 + kq * 4];
        Ws[kq * 4 + 0][mm] = wv.x; Ws[kq * 4 + 1][mm] = wv.y;
        Ws[kq * 4 + 2][mm] = wv.z; Ws[kq * 4 + 3][mm] = wv.w;
        *(float4*)&Xs[kkx][nq * 4] = *(const float4*)&xb[(size_t)(k0 + kkx) * HW + n0 + nq * 4];
        __syncthreads();
#pragma unroll
        for (int kk = 0; kk < 16; kk++) {
            float4 a4 = *(const float4*)&Ws[kk][ty * 4];
            float4 b4 = *(const float4*)&Xs[kk][tx * 4];
            float av[4] = {a4.x, a4.y, a4.z, a4.w};
            float bv[4] = {b4.x, b4.y, b4.z, b4.w};
#pragma unroll
            for (int i = 0; i < 4; i++)
#pragma unroll
                for (int j = 0; j < 4; j++) acc[i][j] += av[i] * bv[j];
        }
        __syncthreads();
    }
    float* ob = out + (size_t)b * CC * HW;
#pragma unroll
    for (int i = 0; i < 4; i++) {
        int o = m0 + ty * 4 + i;
        float bo = bias[o];
        float4 v4 = make_float4(acc[i][0] + bo, acc[i][1] + bo, acc[i][2] + bo, acc[i][3] + bo);
        *(float4*)&ob[(size_t)o * HW + n0 + tx * 4] = v4;
    }
}

// ---------------- channel stats: mean/max over HW per (b,c) ----------------
__global__ __launch_bounds__(256) void k_chanstats(const float* __restrict__ x) {
    int bc = blockIdx.x;  // 0..1023
    const float* p = x + (size_t)bc * HW;
    int tid = threadIdx.x;
    float s = 0.f, m = -INFINITY;
#pragma unroll
    for (int i = 0; i < 4; i++) {
        float4 v = ((const float4*)p)[i * 256 + tid];
        s += v.x + v.y + v.z + v.w;
        m = fmaxf(m, fmaxf(fmaxf(v.x, v.y), fmaxf(v.z, v.w)));
    }
    __shared__ float rs[256], rm[256];
    rs[tid] = s; rm[tid] = m; __syncthreads();
    for (int st = 128; st > 0; st >>= 1) {
        if (tid < st) { rs[tid] += rs[tid + st]; rm[tid] = fmaxf(rm[tid], rm[tid + st]); }
        __syncthreads();
    }
    if (tid == 0) { g_cmean[bc] = rs[0] * (1.f / 4096.f); g_cmax[bc] = rm[0]; }
}

// ---------------- channel gate FC ----------------
__global__ __launch_bounds__(256) void k_gate(
    const float* __restrict__ cw1, const float* __restrict__ cb1,
    const float* __restrict__ cw2, const float* __restrict__ cb2)
{
    int b = blockIdx.x;
    __shared__ float hsum[128];
    __shared__ float sme[256], sma[256];
    int tid = threadIdx.x;
    sme[tid] = g_cmean[b * 256 + tid];
    sma[tid] = g_cmax[b * 256 + tid];
    __syncthreads();
    if (tid < 128) {
        float am = cb1[tid], ax = cb1[tid];
        const float* wr = cw1 + tid * 256;
        for (int c = 0; c < 256; c++) { float w = wr[c]; am += w * sme[c]; ax += w * sma[c]; }
        hsum[tid] = fmaxf(am, 0.f) + fmaxf(ax, 0.f);
    }
    __syncthreads();
    float o = 2.f * cb2[tid];
    const float* wr = cw2 + tid * 128;
    for (int j = 0; j < 128; j++) o += wr[j] * hsum[j];
    g_gate[b * 256 + tid] = 1.f / (1.f + expf(-o));
}

// ---------------- v2 channel max/mean per pixel ----------------
__global__ __launch_bounds__(256) void k_smreduce() {
    int b = blockIdx.y;
    int p = blockIdx.x * 256 + threadIdx.x;
    const float* v2 = g_v2 + (size_t)b * CC * HW + p;
    float mx = -INFINITY, s = 0.f;
    for (int c = 0; c < 256; c++) {
        float v = v2[(size_t)c * HW];
        mx = fmaxf(mx, v); s += v;
    }
    g_sm[b * 8192 + p] = mx;
    g_sm[b * 8192 + 4096 + p] = s * (1.f / 256.f);
}

// ---------------- spatial conv 3x3 (2->1) + BN ----------------
__global__ __launch_bounds__(256) void k_sconv(
    const float* __restrict__ scw, const float* __restrict__ scb,
    const float* __restrict__ bs, const float* __restrict__ bbi,
    const float* __restrict__ bm, const float* __restrict__ bv)
{
    int b = blockIdx.y;
    int p = blockIdx.x * 256 + threadIdx.x;
    int h = p / 64, w = p % 64;
    float acc = 0.f;
    const float* smb = g_sm + b * 8192;
    for (int ci = 0; ci < 2; ci++)
#pragma unroll
        for (int dy = 0; dy < 3; dy++)
#pragma unroll
            for (int dx = 0; dx < 3; dx++) {
                int hh = h + dy - 1, ww = w + dx - 1;
                if (hh >= 0 && hh < 64 && ww >= 0 && ww < 64)
                    acc += scw[ci * 9 + dy * 3 + dx] * smb[ci * 4096 + hh * 64 + ww];
            }
    float A = rsqrtf(bv[0] + 1e-5f) * bs[0];
    g_att[b * 4096 + p] = (acc + scb[0] - bm[0]) * A + bbi[0];
}

// ---------------- softmax over W (rows of 64) -> g_a ----------------
__global__ __launch_bounds__(64) void k_rowsoftmax() {
    int row = blockIdx.x;  // b*64 + h : 256 rows
    int tid = threadIdx.x;
    float v = g_att[row * 64 + tid];
    __shared__ float red[64];
    red[tid] = v; __syncthreads();
    for (int s = 32; s > 0; s >>= 1) {
        if (tid < s) red[tid] = fmaxf(red[tid], red[tid + s]);
        __syncthreads();
    }
    float mx = red[0]; __syncthreads();
    float e = expf(v - mx);
    red[tid] = e; __syncthreads();
    for (int s = 32; s > 0; s >>= 1) {
        if (tid < s) red[tid] += red[tid + s];
        __syncthreads();
    }
    g_a[row * 64 + tid] = e / red[0];
}

// ---------------- spatialA[b,c,h,k] = sum_w x[b,c,h,w] * a[b,w,k] ----------------
__global__ __launch_bounds__(256) void k_spatial(const float* __restrict__ x) {
    int b = blockIdx.y, h = blockIdx.x;
    __shared__ float a_s[64 * 64];
    __shared__ float xs[4][64];
    int tid = threadIdx.x;
    for (int i = tid; i < 4096; i += 256) a_s[i] = g_a[b * 4096 + i];  // a_s[w*64+k]
    int cg = tid / 64, k = tid % 64;
    const float* xb = x + (size_t)b * CC * HW + h * 64;
    float* ob = g_spA + (size_t)b * CC * HW + h * 64;
    for (int c0 = 0; c0 < 256; c0 += 4) {
        __syncthreads();
        xs[cg][k] = xb[(size_t)(c0 + cg) * HW + k];
        __syncthreads();
        float acc = 0.f;
#pragma unroll 8
        for (int w = 0; w < 64; w++) acc += xs[cg][w] * a_s[w * 64 + k];
        ob[(size_t)(c0 + cg) * HW + k] = acc;
    }
}

// ---------------- K6: out = gamma * (v @ aff^T) + x*(1+gate) + spA ----------------
__global__ __launch_bounds__(256) void k_attn_out(
    const float* __restrict__ x, const float* __restrict__ gamma, float* __restrict__ out)
{
    __shared__ float As[16][68];  // [kk][c]
    __shared__ float Bs[16][68];  // [kk][n]
    int b  = blockIdx.z;
    int c0 = blockIdx.y * 64;
    int n0 = blockIdx.x * 64;
    int tid = threadIdx.x;
    const float* vb   = g_v + (size_t)b * CC * HW;
    const float* affb = g_aff + (size_t)b * HW * HW;
    int tx = tid % 16, ty = tid / 16;
    int rr = tid / 4, kq = tid % 4;
    float acc[4][4] = {};

    for (int k0 = 0; k0 < 4096; k0 += 16) {
        float4 av = *(const float4*)&vb[(size_t)(c0 + rr) * HW + k0 + kq * 4];
        float4 bv = *(const float4*)&affb[(size_t)(n0 + rr) * HW + k0 + kq * 4];
        As[kq * 4 + 0][rr] = av.x; As[kq * 4 + 1][rr] = av.y;
        As[kq * 4 + 2][rr] = av.z; As[kq * 4 + 3][rr] = av.w;
        Bs[kq * 4 + 0][rr] = bv.x; Bs[kq * 4 + 1][rr] = bv.y;
        Bs[kq * 4 + 2][rr] = bv.z; Bs[kq * 4 + 3][rr] = bv.w;
        __syncthreads();
#pragma unroll
        for (int kk = 0; kk < 16; kk++) {
            float4 a4 = *(const float4*)&As[kk][ty * 4];
            float4 b4 = *(const float4*)&Bs[kk][tx * 4];
            float a_[4] = {a4.x, a4.y, a4.z, a4.w};
            float b_[4] = {b4.x, b4.y, b4.z, b4.w};
#pragma unroll
            for (int i = 0; i < 4; i++)
#pragma unroll
                for (int j = 0; j < 4; j++) acc[i][j] += a_[i] * b_[j];
        }
        __syncthreads();
    }

    float g = gamma[0];
    const float* xb = x + (size_t)b * CC * HW;
    const float* sb = g_spA + (size_t)b * CC * HW;
#pragma unroll
    for (int i = 0; i < 4; i++) {
        int c = c0 + ty * 4 + i;
        float gt = 1.f + g_gate[b * 256 + c];
        float4 xv = *(const float4*)&xb[(size_t)c * HW + n0 + tx * 4];
        float4 sv = *(const float4*)&sb[(size_t)c * HW + n0 + tx * 4];
        float4 o;
        o.x = g * acc[i][0] + xv.x * gt + sv.x;
        o.y = g * acc[i][1] + xv.y * gt + sv.y;
        o.z = g * acc[i][2] + xv.z * gt + sv.z;
        o.w = g * acc[i][3] + xv.w * gt + sv.w;
        *(float4*)&out[((size_t)b * CC + c) * HW + n0 + tx * 4] = o;
    }
}

// ---------------- launch ----------------
extern "C" void kernel_launch(void* const* d_in, const int* in_sizes, int n_in,
                              void* d_out, int out_size) {
    const float* x     = (const float*)d_in[0];
    const float* q_w   = (const float*)d_in[1];
    const float* q_b   = (const float*)d_in[2];
    const float* q_bs  = (const float*)d_in[3];
    const float* q_bb  = (const float*)d_in[4];
    const float* q_bm  = (const float*)d_in[5];
    const float* q_bv  = (const float*)d_in[6];
    const float* k_w   = (const float*)d_in[7];
    const float* k_b   = (const float*)d_in[8];
    const float* k_bs  = (const float*)d_in[9];
    const float* k_bb  = (const float*)d_in[10];
    const float* k_bm  = (const float*)d_in[11];
    const float* k_bv  = (const float*)d_in[12];
    const float* v_w   = (const float*)d_in[13];
    const float* v_b   = (const float*)d_in[14];
    const float* gamma = (const float*)d_in[15];
    const float* c_w1  = (const float*)d_in[16];
    const float* c_b1  = (const float*)d_in[17];
    const float* c_w2  = (const float*)d_in[18];
    const float* c_b2  = (const float*)d_in[19];
    const float* s_vw  = (const float*)d_in[20];
    const float* s_vb  = (const float*)d_in[21];
    const float* s_cw  = (const float*)d_in[22];
    const float* s_cb  = (const float*)d_in[23];
    const float* s_bs  = (const float*)d_in[24];
    const float* s_bb  = (const float*)d_in[25];
    const float* s_bm  = (const float*)d_in[26];
    const float* s_bv  = (const float*)d_in[27];
    float* out = (float*)d_out;

    // weight transpose for q/k conv
    k_wt<<<288, 256>>>(q_w, k_w);
    // q/k conv + bn + relu
    k_qkconv<<<dim3(4, 8, BB), dim3(16, 8)>>>(x,
        q_b, q_bs, q_bb, q_bm, q_bv,
        k_b, k_bs, k_bb, k_bm, k_bv);
    // S = q^T k
    k_qk_gemm<<<dim3(64, 64, BB), 256>>>();
    // softmax rows
    k_softmax<<<BB * HW, 256>>>();
    // v = v_w @ x + v_b  (which=0 -> g_v) ; v2 = s_vw @ x + s_vb (which=1 -> g_v2)
    k_1x1<<<dim3(64, 4, BB), 256>>>(v_w, v_b, x, 0);
    k_1x1<<<dim3(64, 4, BB), 256>>>(s_vw, s_vb, x, 1);
    // channel gate
    k_chanstats<<<BB * CC, 256>>>(x);
    k_gate<<<BB, 256>>>(c_w1, c_b1, c_w2, c_b2);
    // spatial attention pipeline
    k_smreduce<<<dim3(16, BB), 256>>>();
    k_sconv<<<dim3(16, BB), 256>>>(s_cw, s_cb, s_bs, s_bb, s_bm, s_bv);
    k_rowsoftmax<<<BB * 64, 64>>>();
    k_spatial<<<dim3(64, BB), 256>>>(x);
    // final GEMM + fused epilogue
    k_attn_out<<<dim3(64, 4, BB), 256>>>(x, gamma, out);
    (void)in_sizes; (void)n_in; (void)out_size;
}

// round 11
// speedup vs baseline: 1.6987x; 1.6987x over previous
#include <cuda_runtime.h>
#include <cuda_bf16.h>
#include <mma.h>
#include <math.h>
#include <stdint.h>

using namespace nvcuda;

// Shapes (fixed): B=4, C=256, H=W=64, HW=4096, C8=32, C2=128
#define BB 4
#define CC 256
#define HW 4096
#define C8 32
#define C2 128

// ---------------- device scratch (allocation-free) ----------------
__device__ float g_q[BB * C8 * HW];                      // 2 MB
__device__ float g_k[BB * C8 * HW];                      // 2 MB
__device__ __nv_bfloat16 g_vh[BB * CC * HW];             // 8 MB  (v in bf16 for HMMA)
__device__ float g_v2[BB * CC * HW];                     // 16 MB
__device__ float g_spA[BB * CC * HW];                    // 16 MB
__device__ float g_aff[(size_t)BB * HW * HW];            // 268 MB (logits, fp32)
__device__ __nv_bfloat16 g_affh[(size_t)BB * HW * HW];   // 134 MB (softmax out, bf16)
__device__ float g_wt[256 * 9 * 64];                     // transposed q/k conv weights
__device__ float g_gate[BB * CC];
__device__ float g_cmean[BB * CC];
__device__ float g_cmax[BB * CC];
__device__ float g_sm[BB * 2 * HW];
__device__ float g_att[BB * HW];
__device__ float g_a[BB * 64 * 64];

// ---------------- K0: transpose conv weights to [ic][tap][64oc] ----------------
__global__ void k_wt(const float* __restrict__ qw, const float* __restrict__ kw) {
    int i = blockIdx.x * blockDim.x + threadIdx.x;  // over 256*9*32
    if (i >= 256 * 9 * 32) return;
    int oc = i % 32;
    int t  = (i / 32) % 9;
    int ic = i / (32 * 9);
    g_wt[(ic * 9 + t) * 64 + oc]      = qw[(oc * 256 + ic) * 9 + t];
    g_wt[(ic * 9 + t) * 64 + 32 + oc] = kw[(oc * 256 + ic) * 9 + t];
}

// ---------------- K1: fused q/k conv3x3 + BN + ReLU ----------------
__global__ __launch_bounds__(128) void k_qkconv(
    const float* __restrict__ x,
    const float* __restrict__ qb, const float* __restrict__ qs,
    const float* __restrict__ qbb, const float* __restrict__ qm, const float* __restrict__ qv,
    const float* __restrict__ kb, const float* __restrict__ ks_,
    const float* __restrict__ kbb, const float* __restrict__ km, const float* __restrict__ kv)
{
    __shared__ float xt[10][18];
    __shared__ float wsm[576];
    int b  = blockIdx.z;
    int th = blockIdx.y;   // 0..7
    int tw = blockIdx.x;   // 0..3
    int tx = threadIdx.x, ty = threadIdx.y;
    int tid = ty * 16 + tx;

    float acc[64];
#pragma unroll
    for (int i = 0; i < 64; i++) acc[i] = 0.f;

    const float* xb = x + (size_t)b * CC * HW;

    for (int ic = 0; ic < 256; ic++) {
        for (int i = tid; i < 180; i += 128) {
            int r = i / 18, c = i % 18;
            int gh = th * 8 + r - 1, gw = tw * 16 + c - 1;
            float v = 0.f;
            if (gh >= 0 && gh < 64 && gw >= 0 && gw < 64)
                v = xb[ic * HW + gh * 64 + gw];
            xt[r][c] = v;
        }
        for (int i = tid; i < 144; i += 128)
            ((float4*)wsm)[i] = ((const float4*)(g_wt + ic * 576))[i];
        __syncthreads();

        float xv[9];
#pragma unroll
        for (int dy = 0; dy < 3; dy++)
#pragma unroll
            for (int dx = 0; dx < 3; dx++)
                xv[dy * 3 + dx] = xt[ty + dy][tx + dx];

#pragma unroll
        for (int t = 0; t < 9; t++) {
            float xvt = xv[t];
            const float4* wrow = (const float4*)(wsm + t * 64);
#pragma unroll
            for (int o4 = 0; o4 < 16; o4++) {
                float4 wv = wrow[o4];
                acc[o4 * 4 + 0] += xvt * wv.x;
                acc[o4 * 4 + 1] += xvt * wv.y;
                acc[o4 * 4 + 2] += xvt * wv.z;
                acc[o4 * 4 + 3] += xvt * wv.w;
            }
        }
        __syncthreads();
    }

    int h = th * 8 + ty, w = tw * 16 + tx;
    int p = h * 64 + w;
#pragma unroll
    for (int oc = 0; oc < 32; oc++) {
        float A  = rsqrtf(qv[oc] + 1e-5f) * qs[oc];
        float Bc = (qb[oc] - qm[oc]) * A + qbb[oc];
        g_q[((size_t)b * 32 + oc) * HW + p] = fmaxf(acc[oc] * A + Bc, 0.f);
    }
#pragma unroll
    for (int oc = 0; oc < 32; oc++) {
        float A  = rsqrtf(kv[oc] + 1e-5f) * ks_[oc];
        float Bc = (kb[oc] - km[oc]) * A + kbb[oc];
        g_k[((size_t)b * 32 + oc) * HW + p] = fmaxf(acc[32 + oc] * A + Bc, 0.f);
    }
}

// ---------------- K2: S[b][n][m] = sum_c q[b][c][n] * k[b][c][m] ----------------
__global__ __launch_bounds__(256) void k_qk_gemm() {
    __shared__ float Qs[32][64];
    __shared__ float Ks[32][64];
    int b  = blockIdx.z;
    int n0 = blockIdx.y * 64;
    int m0 = blockIdx.x * 64;
    int tid = threadIdx.x;
    const float* qbp = g_q + (size_t)b * C8 * HW;
    const float* kbp = g_k + (size_t)b * C8 * HW;

    for (int i = tid; i < 512; i += 256) {
        int r = i / 16, c4 = i % 16;
        ((float4*)&Qs[r][0])[c4] = *(const float4*)&qbp[r * HW + n0 + c4 * 4];
        ((float4*)&Ks[r][0])[c4] = *(const float4*)&kbp[r * HW + m0 + c4 * 4];
    }
    __syncthreads();

    int tx = tid % 16, ty = tid / 16;
    float acc[4][4] = {};
#pragma unroll
    for (int kk = 0; kk < 32; kk++) {
        float4 q4 = *(const float4*)&Qs[kk][ty * 4];
        float4 k4 = *(const float4*)&Ks[kk][tx * 4];
        float qa[4] = {q4.x, q4.y, q4.z, q4.w};
        float ka[4] = {k4.x, k4.y, k4.z, k4.w};
#pragma unroll
        for (int i = 0; i < 4; i++)
#pragma unroll
            for (int j = 0; j < 4; j++) acc[i][j] += qa[i] * ka[j];
    }
    float* out = g_aff + (size_t)b * HW * HW;
#pragma unroll
    for (int i = 0; i < 4; i++) {
        float4 v4 = make_float4(acc[i][0], acc[i][1], acc[i][2], acc[i][3]);
        *(float4*)&out[(size_t)(n0 + ty * 4 + i) * HW + m0 + tx * 4] = v4;
    }
}

// ---------------- K3: row softmax of aff (rows of 4096), fp32 in -> bf16 out ----------------
__global__ __launch_bounds__(256) void k_softmax() {
    size_t row = blockIdx.x;
    const float* p = g_aff + row * HW;
    __nv_bfloat162* ph = (__nv_bfloat162*)(g_affh + row * HW);
    int tid = threadIdx.x;
    __shared__ float red[256];

    float4 v[4];
#pragma unroll
    for (int i = 0; i < 4; i++) v[i] = ((const float4*)p)[i * 256 + tid];

    float mx = -INFINITY;
#pragma unroll
    for (int i = 0; i < 4; i++) {
        mx = fmaxf(mx, fmaxf(fmaxf(v[i].x, v[i].y), fmaxf(v[i].z, v[i].w)));
    }
    red[tid] = mx; __syncthreads();
    for (int s = 128; s > 0; s >>= 1) {
        if (tid < s) red[tid] = fmaxf(red[tid], red[tid + s]);
        __syncthreads();
    }
    mx = red[0]; __syncthreads();

    float sum = 0.f;
#pragma unroll
    for (int i = 0; i < 4; i++) {
        v[i].x = expf(v[i].x - mx); v[i].y = expf(v[i].y - mx);
        v[i].z = expf(v[i].z - mx); v[i].w = expf(v[i].w - mx);
        sum += v[i].x + v[i].y + v[i].z + v[i].w;
    }
    red[tid] = sum; __syncthreads();
    for (int s = 128; s > 0; s >>= 1) {
        if (tid < s) red[tid] += red[tid + s];
        __syncthreads();
    }
    float inv = 1.f / red[0];
#pragma unroll
    for (int i = 0; i < 4; i++) {
        int idx = i * 512 + tid * 2;  // bf162 index (elements /2)
        ph[idx]     = __floats2bfloat162_rn(v[i].x * inv, v[i].y * inv);
        ph[idx + 1] = __floats2bfloat162_rn(v[i].z * inv, v[i].w * inv);
    }
}

// ---------------- 1x1 conv GEMM: out[b][o][p] = sum_c W[o][c]*x[b][c][p] + bias[o] ---
// which==0 -> g_vh (bf16, feeds HMMA K6); which==1 -> g_v2 (fp32).
__global__ __launch_bounds__(256) void k_1x1(
    const float* __restrict__ W, const float* __restrict__ bias,
    const float* __restrict__ x, int which)
{
    __shared__ float Ws[16][68];
    __shared__ float Xs[16][64];
    int b  = blockIdx.z;
    int m0 = blockIdx.y * 64;   // output channel
    int n0 = blockIdx.x * 64;   // pixel
    int tid = threadIdx.x;
    const float* xb = x + (size_t)b * CC * HW;
    int tx = tid % 16, ty = tid / 16;
    float acc[4][4] = {};

    int mm = tid / 4, kq = tid % 4;
    int kkx = tid / 16, nq = tid % 16;

    for (int k0 = 0; k0 < 256; k0 += 16) {
        float4 wv = *(const float4*)&W[(m0 + mm) * 256 + k0 + kq * 4];
        Ws[kq * 4 + 0][mm] = wv.x; Ws[kq * 4 + 1][mm] = wv.y;
        Ws[kq * 4 + 2][mm] = wv.z; Ws[kq * 4 + 3][mm] = wv.w;
        *(float4*)&Xs[kkx][nq * 4] = *(const float4*)&xb[(size_t)(k0 + kkx) * HW + n0 + nq * 4];
        __syncthreads();
#pragma unroll
        for (int kk = 0; kk < 16; kk++) {
            float4 a4 = *(const float4*)&Ws[kk][ty * 4];
            float4 b4 = *(const float4*)&Xs[kk][tx * 4];
            float av[4] = {a4.x, a4.y, a4.z, a4.w};
            float bv[4] = {b4.x, b4.y, b4.z, b4.w};
#pragma unroll
            for (int i = 0; i < 4; i++)
#pragma unroll
                for (int j = 0; j < 4; j++) acc[i][j] += av[i] * bv[j];
        }
        __syncthreads();
    }
    if (which) {
        float* ob = g_v2 + (size_t)b * CC * HW;
#pragma unroll
        for (int i = 0; i < 4; i++) {
            int o = m0 + ty * 4 + i;
            float bo = bias[o];
            float4 v4 = make_float4(acc[i][0] + bo, acc[i][1] + bo, acc[i][2] + bo, acc[i][3] + bo);
            *(float4*)&ob[(size_t)o * HW + n0 + tx * 4] = v4;
        }
    } else {
        __nv_bfloat16* ob = g_vh + (size_t)b * CC * HW;
#pragma unroll
        for (int i = 0; i < 4; i++) {
            int o = m0 + ty * 4 + i;
            float bo = bias[o];
            __nv_bfloat162* dst = (__nv_bfloat162*)&ob[(size_t)o * HW + n0 + tx * 4];
            dst[0] = __floats2bfloat162_rn(acc[i][0] + bo, acc[i][1] + bo);
            dst[1] = __floats2bfloat162_rn(acc[i][2] + bo, acc[i][3] + bo);
        }
    }
}

// ---------------- channel stats: mean/max over HW per (b,c) ----------------
__global__ __launch_bounds__(256) void k_chanstats(const float* __restrict__ x) {
    int bc = blockIdx.x;  // 0..1023
    const float* p = x + (size_t)bc * HW;
    int tid = threadIdx.x;
    float s = 0.f, m = -INFINITY;
#pragma unroll
    for (int i = 0; i < 4; i++) {
        float4 v = ((const float4*)p)[i * 256 + tid];
        s += v.x + v.y + v.z + v.w;
        m = fmaxf(m, fmaxf(fmaxf(v.x, v.y), fmaxf(v.z, v.w)));
    }
    __shared__ float rs[256], rm[256];
    rs[tid] = s; rm[tid] = m; __syncthreads();
    for (int st = 128; st > 0; st >>= 1) {
        if (tid < st) { rs[tid] += rs[tid + st]; rm[tid] = fmaxf(rm[tid], rm[tid + st]); }
        __syncthreads();
    }
    if (tid == 0) { g_cmean[bc] = rs[0] * (1.f / 4096.f); g_cmax[bc] = rm[0]; }
}

// ---------------- channel gate FC ----------------
__global__ __launch_bounds__(256) void k_gate(
    const float* __restrict__ cw1, const float* __restrict__ cb1,
    const float* __restrict__ cw2, const float* __restrict__ cb2)
{
    int b = blockIdx.x;
    __shared__ float hsum[128];
    __shared__ float sme[256], sma[256];
    int tid = threadIdx.x;
    sme[tid] = g_cmean[b * 256 + tid];
    sma[tid] = g_cmax[b * 256 + tid];
    __syncthreads();
    if (tid < 128) {
        float am = cb1[tid], ax = cb1[tid];
        const float* wr = cw1 + tid * 256;
        for (int c = 0; c < 256; c++) { float w = wr[c]; am += w * sme[c]; ax += w * sma[c]; }
        hsum[tid] = fmaxf(am, 0.f) + fmaxf(ax, 0.f);
    }
    __syncthreads();
    float o = 2.f * cb2[tid];
    const float* wr = cw2 + tid * 128;
    for (int j = 0; j < 128; j++) o += wr[j] * hsum[j];
    g_gate[b * 256 + tid] = 1.f / (1.f + expf(-o));
}

// ---------------- v2 channel max/mean per pixel ----------------
__global__ __launch_bounds__(256) void k_smreduce() {
    int b = blockIdx.y;
    int p = blockIdx.x * 256 + threadIdx.x;
    const float* v2 = g_v2 + (size_t)b * CC * HW + p;
    float mx = -INFINITY, s = 0.f;
    for (int c = 0; c < 256; c++) {
        float v = v2[(size_t)c * HW];
        mx = fmaxf(mx, v); s += v;
    }
    g_sm[b * 8192 + p] = mx;
    g_sm[b * 8192 + 4096 + p] = s * (1.f / 256.f);
}

// ---------------- spatial conv 3x3 (2->1) + BN ----------------
__global__ __launch_bounds__(256) void k_sconv(
    const float* __restrict__ scw, const float* __restrict__ scb,
    const float* __restrict__ bs, const float* __restrict__ bbi,
    const float* __restrict__ bm, const float* __restrict__ bv)
{
    int b = blockIdx.y;
    int p = blockIdx.x * 256 + threadIdx.x;
    int h = p / 64, w = p % 64;
    float acc = 0.f;
    const float* smb = g_sm + b * 8192;
    for (int ci = 0; ci < 2; ci++)
#pragma unroll
        for (int dy = 0; dy < 3; dy++)
#pragma unroll
            for (int dx = 0; dx < 3; dx++) {
                int hh = h + dy - 1, ww = w + dx - 1;
                if (hh >= 0 && hh < 64 && ww >= 0 && ww < 64)
                    acc += scw[ci * 9 + dy * 3 + dx] * smb[ci * 4096 + hh * 64 + ww];
            }
    float A = rsqrtf(bv[0] + 1e-5f) * bs[0];
    g_att[b * 4096 + p] = (acc + scb[0] - bm[0]) * A + bbi[0];
}

// ---------------- softmax over W (rows of 64) -> g_a ----------------
__global__ __launch_bounds__(64) void k_rowsoftmax() {
    int row = blockIdx.x;  // b*64 + h : 256 rows
    int tid = threadIdx.x;
    float v = g_att[row * 64 + tid];
    __shared__ float red[64];
    red[tid] = v; __syncthreads();
    for (int s = 32; s > 0; s >>= 1) {
        if (tid < s) red[tid] = fmaxf(red[tid], red[tid + s]);
        __syncthreads();
    }
    float mx = red[0]; __syncthreads();
    float e = expf(v - mx);
    red[tid] = e; __syncthreads();
    for (int s = 32; s > 0; s >>= 1) {
        if (tid < s) red[tid] += red[tid + s];
        __syncthreads();
    }
    g_a[row * 64 + tid] = e / red[0];
}

// ---------------- spatialA[b,c,h,k] = sum_w x[b,c,h,w] * a[b,w,k] ----------------
__global__ __launch_bounds__(256) void k_spatial(const float* __restrict__ x) {
    int b = blockIdx.y, h = blockIdx.x;
    __shared__ float a_s[64 * 64];
    __shared__ float xs[4][64];
    int tid = threadIdx.x;
    for (int i = tid; i < 4096; i += 256) a_s[i] = g_a[b * 4096 + i];  // a_s[w*64+k]
    int cg = tid / 64, k = tid % 64;
    const float* xb = x + (size_t)b * CC * HW + h * 64;
    float* ob = g_spA + (size_t)b * CC * HW + h * 64;
    for (int c0 = 0; c0 < 256; c0 += 4) {
        __syncthreads();
        xs[cg][k] = xb[(size_t)(c0 + cg) * HW + k];
        __syncthreads();
        float acc = 0.f;
#pragma unroll 8
        for (int w = 0; w < 64; w++) acc += xs[cg][w] * a_s[w * 64 + k];
        ob[(size_t)(c0 + cg) * HW + k] = acc;
    }
}

// ---------------- K6 (HMMA): out = gamma * (v @ aff^T) + x*(1+gate) + spA ----------------
// wts[c][n] = sum_m v[c][m] * aff[n][m]; bf16 operands, fp32 accumulate.
// Block tile 128(c) x 64(n), BK=64, 8 warps each computing 32x32 via wmma 16x16x16.
#define K6_LDA 72   // bf16 smem leading dim (mult of 8)
#define K6_LDC 68   // fp32 smem leading dim (mult of 4)
__global__ __launch_bounds__(256) void k_attn_out(
    const float* __restrict__ x, const float* __restrict__ gamma, float* __restrict__ out)
{
    __shared__ __align__(16) char raw[128 * K6_LDC * 4];  // 34816 B
    __nv_bfloat16* As = (__nv_bfloat16*)raw;                        // [128][72]
    __nv_bfloat16* Bs = (__nv_bfloat16*)(raw + 128 * K6_LDA * 2);   // [64][72]
    float* Cs = (float*)raw;                                        // [128][68] (reused)

    int b  = blockIdx.z;
    int c0 = blockIdx.y * 128;
    int n0 = blockIdx.x * 64;
    int tid = threadIdx.x;
    int wid = tid / 32;
    int wr = wid % 4;   // c-direction: 4 * 32 = 128
    int wc = wid / 4;   // n-direction: 2 * 32 = 64

    const __nv_bfloat16* vb = g_vh + (size_t)b * CC * HW;
    const __nv_bfloat16* ab = g_affh + (size_t)b * HW * HW;

    wmma::fragment<wmma::accumulator, 16, 16, 16, float> acc[2][2];
#pragma unroll
    for (int i = 0; i < 2; i++)
#pragma unroll
        for (int j = 0; j < 2; j++) wmma::fill_fragment(acc[i][j], 0.f);

    for (int m0 = 0; m0 < HW; m0 += 64) {
        // stage A: 128 rows x 64 bf16 (1024 float4), B: 64 rows x 64 bf16 (512 float4)
#pragma unroll
        for (int i = tid; i < 1024; i += 256) {
            int r = i / 8, q = i % 8;
            *(float4*)&As[r * K6_LDA + q * 8] =
                *(const float4*)&vb[(size_t)(c0 + r) * HW + m0 + q * 8];
        }
#pragma unroll
        for (int i = tid; i < 512; i += 256) {
            int r = i / 8, q = i % 8;
            *(float4*)&Bs[r * K6_LDA + q * 8] =
                *(const float4*)&ab[(size_t)(n0 + r) * HW + m0 + q * 8];
        }
        __syncthreads();

#pragma unroll
        for (int kk = 0; kk < 64; kk += 16) {
            wmma::fragment<wmma::matrix_a, 16, 16, 16, __nv_bfloat16, wmma::row_major> af[2];
            wmma::fragment<wmma::matrix_b, 16, 16, 16, __nv_bfloat16, wmma::col_major> bf[2];
            wmma::load_matrix_sync(af[0], &As[(wr * 32) * K6_LDA + kk], K6_LDA);
            wmma::load_matrix_sync(af[1], &As[(wr * 32 + 16) * K6_LDA + kk], K6_LDA);
            wmma::load_matrix_sync(bf[0], &Bs[(wc * 32) * K6_LDA + kk], K6_LDA);
            wmma::load_matrix_sync(bf[1], &Bs[(wc * 32 + 16) * K6_LDA + kk], K6_LDA);
#pragma unroll
            for (int i = 0; i < 2; i++)
#pragma unroll
                for (int j = 0; j < 2; j++)
                    wmma::mma_sync(acc[i][j], af[i], bf[j], acc[i][j]);
        }
        __syncthreads();
    }

    // write accumulators to smem (aliases As/Bs — all mma reads done)
#pragma unroll
    for (int i = 0; i < 2; i++)
#pragma unroll
        for (int j = 0; j < 2; j++)
            wmma::store_matrix_sync(&Cs[(wr * 32 + i * 16) * K6_LDC + wc * 32 + j * 16],
                                    acc[i][j], K6_LDC, wmma::mem_row_major);
    __syncthreads();

    // fused epilogue: 128x64 tile = 2048 float4
    float g = gamma[0];
    const float* xb = x + (size_t)b * CC * HW;
    const float* sb = g_spA + (size_t)b * CC * HW;
#pragma unroll
    for (int i = tid; i < 2048; i += 256) {
        int r = i / 16, q = i % 16;
        int c = c0 + r;
        float gt = 1.f + g_gate[b * 256 + c];
        float4 w4 = *(const float4*)&Cs[r * K6_LDC + q * 4];
        float4 xv = *(const float4*)&xb[(size_t)c * HW + n0 + q * 4];
        float4 sv = *(const float4*)&sb[(size_t)c * HW + n0 + q * 4];
        float4 o;
        o.x = g * w4.x + xv.x * gt + sv.x;
        o.y = g * w4.y + xv.y * gt + sv.y;
        o.z = g * w4.z + xv.z * gt + sv.z;
        o.w = g * w4.w + xv.w * gt + sv.w;
        *(float4*)&out[((size_t)b * CC + c) * HW + n0 + q * 4] = o;
    }
}

// ---------------- launch ----------------
extern "C" void kernel_launch(void* const* d_in, const int* in_sizes, int n_in,
                              void* d_out, int out_size) {
    const float* x     = (const float*)d_in[0];
    const float* q_w   = (const float*)d_in[1];
    const float* q_b   = (const float*)d_in[2];
    const float* q_bs  = (const float*)d_in[3];
    const float* q_bb  = (const float*)d_in[4];
    const float* q_bm  = (const float*)d_in[5];
    const float* q_bv  = (const float*)d_in[6];
    const float* k_w   = (const float*)d_in[7];
    const float* k_b   = (const float*)d_in[8];
    const float* k_bs  = (const float*)d_in[9];
    const float* k_bb  = (const float*)d_in[10];
    const float* k_bm  = (const float*)d_in[11];
    const float* k_bv  = (const float*)d_in[12];
    const float* v_w   = (const float*)d_in[13];
    const float* v_b   = (const float*)d_in[14];
    const float* gamma = (const float*)d_in[15];
    const float* c_w1  = (const float*)d_in[16];
    const float* c_b1  = (const float*)d_in[17];
    const float* c_w2  = (const float*)d_in[18];
    const float* c_b2  = (const float*)d_in[19];
    const float* s_vw  = (const float*)d_in[20];
    const float* s_vb  = (const float*)d_in[21];
    const float* s_cw  = (const float*)d_in[22];
    const float* s_cb  = (const float*)d_in[23];
    const float* s_bs  = (const float*)d_in[24];
    const float* s_bb  = (const float*)d_in[25];
    const float* s_bm  = (const float*)d_in[26];
    const float* s_bv  = (const float*)d_in[27];
    float* out = (float*)d_out;

    // weight transpose for q/k conv
    k_wt<<<288, 256>>>(q_w, k_w);
    // q/k conv + bn + relu
    k_qkconv<<<dim3(4, 8, BB), dim3(16, 8)>>>(x,
        q_b, q_bs, q_bb, q_bm, q_bv,
        k_b, k_bs, k_bb, k_bm, k_bv);
    // S = q^T k
    k_qk_gemm<<<dim3(64, 64, BB), 256>>>();
    // softmax rows (fp32 -> bf16)
    k_softmax<<<BB * HW, 256>>>();
    // v (bf16) and v2 (fp32)
    k_1x1<<<dim3(64, 4, BB), 256>>>(v_w, v_b, x, 0);
    k_1x1<<<dim3(64, 4, BB), 256>>>(s_vw, s_vb, x, 1);
    // channel gate
    k_chanstats<<<BB * CC, 256>>>(x);
    k_gate<<<BB, 256>>>(c_w1, c_b1, c_w2, c_b2);
    // spatial attention pipeline
    k_smreduce<<<dim3(16, BB), 256>>>();
    k_sconv<<<dim3(16, BB), 256>>>(s_cw, s_cb, s_bs, s_bb, s_bm, s_bv);
    k_rowsoftmax<<<BB * 64, 64>>>();
    k_spatial<<<dim3(64, BB), 256>>>(x);
    // final HMMA GEMM + fused epilogue
    k_attn_out<<<dim3(64, 2, BB), 256>>>(x, gamma, out);
    (void)in_sizes; (void)n_in; (void)out_size;
}

// round 12
// speedup vs baseline: 1.7167x; 1.0106x over previous
#include <cuda_runtime.h>
#include <cuda_bf16.h>
#include <mma.h>
#include <math.h>
#include <stdint.h>

using namespace nvcuda;

// Shapes (fixed): B=4, C=256, H=W=64, HW=4096, C8=32, C2=128
#define BB 4
#define CC 256
#define HW 4096
#define C8 32
#define C2 128

// ---------------- device scratch (allocation-free) ----------------
__device__ float g_q[BB * C8 * HW];                      // 2 MB
__device__ float g_k[BB * C8 * HW];                      // 2 MB
__device__ __nv_bfloat16 g_vh[BB * CC * HW];             // 8 MB  (v in bf16 for HMMA)
__device__ float g_v2[BB * CC * HW];                     // 16 MB
__device__ float g_spA[BB * CC * HW];                    // 16 MB
__device__ float g_aff[(size_t)BB * HW * HW];            // 268 MB (logits, fp32)
__device__ __nv_bfloat16 g_affh[(size_t)BB * HW * HW];   // 134 MB (softmax out, bf16)
__device__ float g_wt[256 * 9 * 64];                     // transposed q/k conv weights
__device__ float g_gate[BB * CC];
__device__ float g_cmean[BB * CC];
__device__ float g_cmax[BB * CC];
__device__ float g_sm[BB * 2 * HW];
__device__ float g_att[BB * HW];
__device__ float g_a[BB * 64 * 64];

// ---------------- K0: transpose conv weights to [ic][tap][64oc] ----------------
__global__ void k_wt(const float* __restrict__ qw, const float* __restrict__ kw) {
    int i = blockIdx.x * blockDim.x + threadIdx.x;  // over 256*9*32
    if (i >= 256 * 9 * 32) return;
    int oc = i % 32;
    int t  = (i / 32) % 9;
    int ic = i / (32 * 9);
    g_wt[(ic * 9 + t) * 64 + oc]      = qw[(oc * 256 + ic) * 9 + t];
    g_wt[(ic * 9 + t) * 64 + 32 + oc] = kw[(oc * 256 + ic) * 9 + t];
}

// ---------------- K1: fused q/k conv3x3 + BN + ReLU ----------------
__global__ __launch_bounds__(128) void k_qkconv(
    const float* __restrict__ x,
    const float* __restrict__ qb, const float* __restrict__ qs,
    const float* __restrict__ qbb, const float* __restrict__ qm, const float* __restrict__ qv,
    const float* __restrict__ kb, const float* __restrict__ ks_,
    const float* __restrict__ kbb, const float* __restrict__ km, const float* __restrict__ kv)
{
    __shared__ float xt[10][18];
    __shared__ float wsm[576];
    int b  = blockIdx.z;
    int th = blockIdx.y;   // 0..7
    int tw = blockIdx.x;   // 0..3
    int tx = threadIdx.x, ty = threadIdx.y;
    int tid = ty * 16 + tx;

    float acc[64];
#pragma unroll
    for (int i = 0; i < 64; i++) acc[i] = 0.f;

    const float* xb = x + (size_t)b * CC * HW;

    for (int ic = 0; ic < 256; ic++) {
        for (int i = tid; i < 180; i += 128) {
            int r = i / 18, c = i % 18;
            int gh = th * 8 + r - 1, gw = tw * 16 + c - 1;
            float v = 0.f;
            if (gh >= 0 && gh < 64 && gw >= 0 && gw < 64)
                v = xb[ic * HW + gh * 64 + gw];
            xt[r][c] = v;
        }
        for (int i = tid; i < 144; i += 128)
            ((float4*)wsm)[i] = ((const float4*)(g_wt + ic * 576))[i];
        __syncthreads();

        float xv[9];
#pragma unroll
        for (int dy = 0; dy < 3; dy++)
#pragma unroll
            for (int dx = 0; dx < 3; dx++)
                xv[dy * 3 + dx] = xt[ty + dy][tx + dx];

#pragma unroll
        for (int t = 0; t < 9; t++) {
            float xvt = xv[t];
            const float4* wrow = (const float4*)(wsm + t * 64);
#pragma unroll
            for (int o4 = 0; o4 < 16; o4++) {
                float4 wv = wrow[o4];
                acc[o4 * 4 + 0] += xvt * wv.x;
                acc[o4 * 4 + 1] += xvt * wv.y;
                acc[o4 * 4 + 2] += xvt * wv.z;
                acc[o4 * 4 + 3] += xvt * wv.w;
            }
        }
        __syncthreads();
    }

    int h = th * 8 + ty, w = tw * 16 + tx;
    int p = h * 64 + w;
#pragma unroll
    for (int oc = 0; oc < 32; oc++) {
        float A  = rsqrtf(qv[oc] + 1e-5f) * qs[oc];
        float Bc = (qb[oc] - qm[oc]) * A + qbb[oc];
        g_q[((size_t)b * 32 + oc) * HW + p] = fmaxf(acc[oc] * A + Bc, 0.f);
    }
#pragma unroll
    for (int oc = 0; oc < 32; oc++) {
        float A  = rsqrtf(kv[oc] + 1e-5f) * ks_[oc];
        float Bc = (kb[oc] - km[oc]) * A + kbb[oc];
        g_k[((size_t)b * 32 + oc) * HW + p] = fmaxf(acc[32 + oc] * A + Bc, 0.f);
    }
}

// ---------------- K2 (tf32 wmma): S[b][n][m] = sum_c q[b][c][n] * k[b][c][m] --------
// Block tile 128(n) x 128(m), K=32 in one staging. 8 warps, warp tile 64x32.
#define K2_LD 132
__global__ __launch_bounds__(256) void k_qk_gemm() {
    __shared__ float Qs[32 * K2_LD];  // [k][n]
    __shared__ float Ks[32 * K2_LD];  // [k][m]
    int b  = blockIdx.z;
    int n0 = blockIdx.y * 128;
    int m0 = blockIdx.x * 128;
    int tid = threadIdx.x;
    const float* qbp = g_q + (size_t)b * C8 * HW;
    const float* kbp = g_k + (size_t)b * C8 * HW;

#pragma unroll
    for (int i = tid; i < 1024; i += 256) {
        int r = i / 32, q4 = i % 32;
        *(float4*)&Qs[r * K2_LD + q4 * 4] = *(const float4*)&qbp[r * HW + n0 + q4 * 4];
        *(float4*)&Ks[r * K2_LD + q4 * 4] = *(const float4*)&kbp[r * HW + m0 + q4 * 4];
    }
    __syncthreads();

    int wid = tid / 32;
    int wn = wid % 2;   // 2 x 64 in n
    int wm = wid / 2;   // 4 x 32 in m

    wmma::fragment<wmma::accumulator, 16, 16, 8, float> acc[4][2];
#pragma unroll
    for (int i = 0; i < 4; i++)
#pragma unroll
        for (int j = 0; j < 2; j++) wmma::fill_fragment(acc[i][j], 0.f);

#pragma unroll
    for (int kk = 0; kk < 32; kk += 8) {
        wmma::fragment<wmma::matrix_a, 16, 16, 8, wmma::precision::tf32, wmma::col_major> af[4];
        wmma::fragment<wmma::matrix_b, 16, 16, 8, wmma::precision::tf32, wmma::row_major> bf[2];
#pragma unroll
        for (int i = 0; i < 4; i++) {
            wmma::load_matrix_sync(af[i], &Qs[kk * K2_LD + wn * 64 + i * 16], K2_LD);
#pragma unroll
            for (int t = 0; t < af[i].num_elements; t++)
                af[i].x[t] = wmma::__float_to_tf32(af[i].x[t]);
        }
#pragma unroll
        for (int j = 0; j < 2; j++) {
            wmma::load_matrix_sync(bf[j], &Ks[kk * K2_LD + wm * 32 + j * 16], K2_LD);
#pragma unroll
            for (int t = 0; t < bf[j].num_elements; t++)
                bf[j].x[t] = wmma::__float_to_tf32(bf[j].x[t]);
        }
#pragma unroll
        for (int i = 0; i < 4; i++)
#pragma unroll
            for (int j = 0; j < 2; j++)
                wmma::mma_sync(acc[i][j], af[i], bf[j], acc[i][j]);
    }

    float* outp = g_aff + (size_t)b * HW * HW;
#pragma unroll
    for (int i = 0; i < 4; i++)
#pragma unroll
        for (int j = 0; j < 2; j++)
            wmma::store_matrix_sync(
                &outp[(size_t)(n0 + wn * 64 + i * 16) * HW + m0 + wm * 32 + j * 16],
                acc[i][j], HW, wmma::mem_row_major);
}

// ---------------- K3: row softmax of aff (rows of 4096), fp32 in -> bf16 out ----------------
__global__ __launch_bounds__(256) void k_softmax() {
    size_t row = blockIdx.x;
    const float* p = g_aff + row * HW;
    __nv_bfloat162* ph = (__nv_bfloat162*)(g_affh + row * HW);
    int tid = threadIdx.x;
    __shared__ float red[256];

    float4 v[4];
#pragma unroll
    for (int i = 0; i < 4; i++) v[i] = ((const float4*)p)[i * 256 + tid];

    float mx = -INFINITY;
#pragma unroll
    for (int i = 0; i < 4; i++) {
        mx = fmaxf(mx, fmaxf(fmaxf(v[i].x, v[i].y), fmaxf(v[i].z, v[i].w)));
    }
    red[tid] = mx; __syncthreads();
    for (int s = 128; s > 0; s >>= 1) {
        if (tid < s) red[tid] = fmaxf(red[tid], red[tid + s]);
        __syncthreads();
    }
    mx = red[0]; __syncthreads();

    float sum = 0.f;
#pragma unroll
    for (int i = 0; i < 4; i++) {
        v[i].x = expf(v[i].x - mx); v[i].y = expf(v[i].y - mx);
        v[i].z = expf(v[i].z - mx); v[i].w = expf(v[i].w - mx);
        sum += v[i].x + v[i].y + v[i].z + v[i].w;
    }
    red[tid] = sum; __syncthreads();
    for (int s = 128; s > 0; s >>= 1) {
        if (tid < s) red[tid] += red[tid + s];
        __syncthreads();
    }
    float inv = 1.f / red[0];
#pragma unroll
    for (int i = 0; i < 4; i++) {
        int idx = i * 512 + tid * 2;
        ph[idx]     = __floats2bfloat162_rn(v[i].x * inv, v[i].y * inv);
        ph[idx + 1] = __floats2bfloat162_rn(v[i].z * inv, v[i].w * inv);
    }
}

// ---------------- K4 (tf32 wmma, fused): [v ; v2] = [v_w ; s_vw] @ x + bias ----------
// M=512 (rows 0..255 -> g_vh bf16, 256..511 -> g_v2 fp32), N=4096, K=256.
// Block tile 64(m) x 128(n), BK=32. 8 warps, warp tile 32x32.
#define K4_LDA 36
#define K4_LDB 132
__global__ __launch_bounds__(256) void k_1x1_fused(
    const float* __restrict__ vw, const float* __restrict__ vb,
    const float* __restrict__ sw, const float* __restrict__ sb,
    const float* __restrict__ x)
{
    __shared__ __align__(16) float smem[64 * K4_LDB];  // 33792 B union
    float* As = smem;                    // [64][36]  (m,k)
    float* Bs = smem + 64 * K4_LDA;      // [32][132] (k,n)
    float* Cs = smem;                    // [64][132] (reused after mma)

    int b  = blockIdx.z;
    int m0 = blockIdx.y * 64;
    int n0 = blockIdx.x * 128;
    int tid = threadIdx.x;
    int wid = tid / 32;
    int wm = wid % 2;  // 2 x 32 m
    int wn = wid / 2;  // 4 x 32 n

    bool vhalf = (m0 < 256);
    const float* W  = vhalf ? (vw + m0 * 256) : (sw + (m0 - 256) * 256);
    const float* bi = vhalf ? (vb + m0) : (sb + (m0 - 256));
    const float* xb = x + (size_t)b * CC * HW;

    wmma::fragment<wmma::accumulator, 16, 16, 8, float> acc[2][2];
#pragma unroll
    for (int i = 0; i < 2; i++)
#pragma unroll
        for (int j = 0; j < 2; j++) wmma::fill_fragment(acc[i][j], 0.f);

    for (int k0 = 0; k0 < 256; k0 += 32) {
        // As: 64 rows x 32 floats = 512 float4 (2/thread)
#pragma unroll
        for (int i = tid; i < 512; i += 256) {
            int r = i / 8, q = i % 8;
            *(float4*)&As[r * K4_LDA + q * 4] = *(const float4*)&W[r * 256 + k0 + q * 4];
        }
        // Bs: 32 rows x 128 floats = 1024 float4 (4/thread)
#pragma unroll
        for (int i = tid; i < 1024; i += 256) {
            int r = i / 32, q = i % 32;
            *(float4*)&Bs[r * K4_LDB + q * 4] =
                *(const float4*)&xb[(size_t)(k0 + r) * HW + n0 + q * 4];
        }
        __syncthreads();

#pragma unroll
        for (int kk = 0; kk < 32; kk += 8) {
            wmma::fragment<wmma::matrix_a, 16, 16, 8, wmma::precision::tf32, wmma::row_major> af[2];
            wmma::fragment<wmma::matrix_b, 16, 16, 8, wmma::precision::tf32, wmma::row_major> bf[2];
#pragma unroll
            for (int i = 0; i < 2; i++) {
                wmma::load_matrix_sync(af[i], &As[(wm * 32 + i * 16) * K4_LDA + kk], K4_LDA);
#pragma unroll
                for (int t = 0; t < af[i].num_elements; t++)
                    af[i].x[t] = wmma::__float_to_tf32(af[i].x[t]);
            }
#pragma unroll
            for (int j = 0; j < 2; j++) {
                wmma::load_matrix_sync(bf[j], &Bs[kk * K4_LDB + wn * 32 + j * 16], K4_LDB);
#pragma unroll
                for (int t = 0; t < bf[j].num_elements; t++)
                    bf[j].x[t] = wmma::__float_to_tf32(bf[j].x[t]);
            }
#pragma unroll
            for (int i = 0; i < 2; i++)
#pragma unroll
                for (int j = 0; j < 2; j++)
                    wmma::mma_sync(acc[i][j], af[i], bf[j], acc[i][j]);
        }
        __syncthreads();
    }

    // stage C to smem (aliases As/Bs)
#pragma unroll
    for (int i = 0; i < 2; i++)
#pragma unroll
        for (int j = 0; j < 2; j++)
            wmma::store_matrix_sync(&Cs[(wm * 32 + i * 16) * K4_LDB + wn * 32 + j * 16],
                                    acc[i][j], K4_LDB, wmma::mem_row_major);
    __syncthreads();

    // epilogue: 64 x 128 = 2048 float4 (8/thread)
    if (vhalf) {
        __nv_bfloat16* ob = g_vh + (size_t)b * CC * HW;
#pragma unroll
        for (int i = tid; i < 2048; i += 256) {
            int r = i / 32, q = i % 32;
            float bo = bi[r];
            float4 c4 = *(const float4*)&Cs[r * K4_LDB + q * 4];
            __nv_bfloat162* d = (__nv_bfloat162*)&ob[(size_t)(m0 + r) * HW + n0 + q * 4];
            d[0] = __floats2bfloat162_rn(c4.x + bo, c4.y + bo);
            d[1] = __floats2bfloat162_rn(c4.z + bo, c4.w + bo);
        }
    } else {
        float* ob = g_v2 + (size_t)b * CC * HW;
#pragma unroll
        for (int i = tid; i < 2048; i += 256) {
            int r = i / 32, q = i % 32;
            float bo = bi[r];
            float4 c4 = *(const float4*)&Cs[r * K4_LDB + q * 4];
            float4 o = make_float4(c4.x + bo, c4.y + bo, c4.z + bo, c4.w + bo);
            *(float4*)&ob[(size_t)(m0 - 256 + r) * HW + n0 + q * 4] = o;
        }
    }
}

// ---------------- channel stats: mean/max over HW per (b,c) ----------------
__global__ __launch_bounds__(256) void k_chanstats(const float* __restrict__ x) {
    int bc = blockIdx.x;  // 0..1023
    const float* p = x + (size_t)bc * HW;
    int tid = threadIdx.x;
    float s = 0.f, m = -INFINITY;
#pragma unroll
    for (int i = 0; i < 4; i++) {
        float4 v = ((const float4*)p)[i * 256 + tid];
        s += v.x + v.y + v.z + v.w;
        m = fmaxf(m, fmaxf(fmaxf(v.x, v.y), fmaxf(v.z, v.w)));
    }
    __shared__ float rs[256], rm[256];
    rs[tid] = s; rm[tid] = m; __syncthreads();
    for (int st = 128; st > 0; st >>= 1) {
        if (tid < st) { rs[tid] += rs[tid + st]; rm[tid] = fmaxf(rm[tid], rm[tid + st]); }
        __syncthreads();
    }
    if (tid == 0) { g_cmean[bc] = rs[0] * (1.f / 4096.f); g_cmax[bc] = rm[0]; }
}

// ---------------- channel gate FC ----------------
__global__ __launch_bounds__(256) void k_gate(
    const float* __restrict__ cw1, const float* __restrict__ cb1,
    const float* __restrict__ cw2, const float* __restrict__ cb2)
{
    int b = blockIdx.x;
    __shared__ float hsum[128];
    __shared__ float sme[256], sma[256];
    int tid = threadIdx.x;
    sme[tid] = g_cmean[b * 256 + tid];
    sma[tid] = g_cmax[b * 256 + tid];
    __syncthreads();
    if (tid < 128) {
        float am = cb1[tid], ax = cb1[tid];
        const float* wr = cw1 + tid * 256;
        for (int c = 0; c < 256; c++) { float w = wr[c]; am += w * sme[c]; ax += w * sma[c]; }
        hsum[tid] = fmaxf(am, 0.f) + fmaxf(ax, 0.f);
    }
    __syncthreads();
    float o = 2.f * cb2[tid];
    const float* wr = cw2 + tid * 128;
    for (int j = 0; j < 128; j++) o += wr[j] * hsum[j];
    g_gate[b * 256 + tid] = 1.f / (1.f + expf(-o));
}

// ---------------- v2 channel max/mean per pixel ----------------
__global__ __launch_bounds__(256) void k_smreduce() {
    int b = blockIdx.y;
    int p = blockIdx.x * 256 + threadIdx.x;
    const float* v2 = g_v2 + (size_t)b * CC * HW + p;
    float mx = -INFINITY, s = 0.f;
    for (int c = 0; c < 256; c++) {
        float v = v2[(size_t)c * HW];
        mx = fmaxf(mx, v); s += v;
    }
    g_sm[b * 8192 + p] = mx;
    g_sm[b * 8192 + 4096 + p] = s * (1.f / 256.f);
}

// ---------------- spatial conv 3x3 (2->1) + BN ----------------
__global__ __launch_bounds__(256) void k_sconv(
    const float* __restrict__ scw, const float* __restrict__ scb,
    const float* __restrict__ bs, const float* __restrict__ bbi,
    const float* __restrict__ bm, const float* __restrict__ bv)
{
    int b = blockIdx.y;
    int p = blockIdx.x * 256 + threadIdx.x;
    int h = p / 64, w = p % 64;
    float acc = 0.f;
    const float* smb = g_sm + b * 8192;
    for (int ci = 0; ci < 2; ci++)
#pragma unroll
        for (int dy = 0; dy < 3; dy++)
#pragma unroll
            for (int dx = 0; dx < 3; dx++) {
                int hh = h + dy - 1, ww = w + dx - 1;
                if (hh >= 0 && hh < 64 && ww >= 0 && ww < 64)
                    acc += scw[ci * 9 + dy * 3 + dx] * smb[ci * 4096 + hh * 64 + ww];
            }
    float A = rsqrtf(bv[0] + 1e-5f) * bs[0];
    g_att[b * 4096 + p] = (acc + scb[0] - bm[0]) * A + bbi[0];
}

// ---------------- softmax over W (rows of 64) -> g_a ----------------
__global__ __launch_bounds__(64) void k_rowsoftmax() {
    int row = blockIdx.x;  // b*64 + h : 256 rows
    int tid = threadIdx.x;
    float v = g_att[row * 64 + tid];
    __shared__ float red[64];
    red[tid] = v; __syncthreads();
    for (int s = 32; s > 0; s >>= 1) {
        if (tid < s) red[tid] = fmaxf(red[tid], red[tid + s]);
        __syncthreads();
    }
    float mx = red[0]; __syncthreads();
    float e = expf(v - mx);
    red[tid] = e; __syncthreads();
    for (int s = 32; s > 0; s >>= 1) {
        if (tid < s) red[tid] += red[tid + s];
        __syncthreads();
    }
    g_a[row * 64 + tid] = e / red[0];
}

// ---------------- spatialA[b,c,h,k] = sum_w x[b,c,h,w] * a[b,w,k] ----------------
__global__ __launch_bounds__(256) void k_spatial(const float* __restrict__ x) {
    int b = blockIdx.y, h = blockIdx.x;
    __shared__ float a_s[64 * 64];
    __shared__ float xs[4][64];
    int tid = threadIdx.x;
    for (int i = tid; i < 4096; i += 256) a_s[i] = g_a[b * 4096 + i];  // a_s[w*64+k]
    int cg = tid / 64, k = tid % 64;
    const float* xb = x + (size_t)b * CC * HW + h * 64;
    float* ob = g_spA + (size_t)b * CC * HW + h * 64;
    for (int c0 = 0; c0 < 256; c0 += 4) {
        __syncthreads();
        xs[cg][k] = xb[(size_t)(c0 + cg) * HW + k];
        __syncthreads();
        float acc = 0.f;
#pragma unroll 8
        for (int w = 0; w < 64; w++) acc += xs[cg][w] * a_s[w * 64 + k];
        ob[(size_t)(c0 + cg) * HW + k] = acc;
    }
}

// ---------------- K6 (HMMA): out = gamma * (v @ aff^T) + x*(1+gate) + spA ----------------
// c-tile = 256 (full) so aff is read exactly once; n-tile 32, BK=64.
// 8 warps, each 32(c) x 32(n) via bf16 wmma 16x16x16.
#define K6_LDA 72   // bf16 smem leading dim
#define K6_LDC 36   // fp32 smem leading dim
__global__ __launch_bounds__(256) void k_attn_out(
    const float* __restrict__ x, const float* __restrict__ gamma, float* __restrict__ out)
{
    __shared__ __align__(16) char raw[(256 + 32) * K6_LDA * 2];  // 41472 B union
    __nv_bfloat16* As = (__nv_bfloat16*)raw;                      // [256][72] (c,m)
    __nv_bfloat16* Bs = (__nv_bfloat16*)(raw + 256 * K6_LDA * 2); // [32][72]  (n,m)
    float* Cs = (float*)raw;                                      // [256][36] (c,n) reused

    int b  = blockIdx.z;
    int n0 = blockIdx.x * 32;
    int tid = threadIdx.x;
    int wid = tid / 32;   // c-range: wid*32

    const __nv_bfloat16* vb = g_vh + (size_t)b * CC * HW;
    const __nv_bfloat16* ab = g_affh + (size_t)b * HW * HW;

    wmma::fragment<wmma::accumulator, 16, 16, 16, float> acc[2][2];
#pragma unroll
    for (int i = 0; i < 2; i++)
#pragma unroll
        for (int j = 0; j < 2; j++) wmma::fill_fragment(acc[i][j], 0.f);

    for (int m0 = 0; m0 < HW; m0 += 64) {
        // A: 256 rows x 64 bf16 = 2048 float4 (8/thread)
#pragma unroll
        for (int i = tid; i < 2048; i += 256) {
            int r = i / 8, q = i % 8;
            *(float4*)&As[r * K6_LDA + q * 8] =
                *(const float4*)&vb[(size_t)r * HW + m0 + q * 8];
        }
        // B: 32 rows x 64 bf16 = 256 float4 (1/thread)
        {
            int r = tid / 8, q = tid % 8;
            *(float4*)&Bs[r * K6_LDA + q * 8] =
                *(const float4*)&ab[(size_t)(n0 + r) * HW + m0 + q * 8];
        }
        __syncthreads();

#pragma unroll
        for (int kk = 0; kk < 64; kk += 16) {
            wmma::fragment<wmma::matrix_a, 16, 16, 16, __nv_bfloat16, wmma::row_major> af[2];
            wmma::fragment<wmma::matrix_b, 16, 16, 16, __nv_bfloat16, wmma::col_major> bf[2];
            wmma::load_matrix_sync(af[0], &As[(wid * 32) * K6_LDA + kk], K6_LDA);
            wmma::load_matrix_sync(af[1], &As[(wid * 32 + 16) * K6_LDA + kk], K6_LDA);
            wmma::load_matrix_sync(bf[0], &Bs[0 * K6_LDA + kk], K6_LDA);
            wmma::load_matrix_sync(bf[1], &Bs[16 * K6_LDA + kk], K6_LDA);
#pragma unroll
            for (int i = 0; i < 2; i++)
#pragma unroll
                for (int j = 0; j < 2; j++)
                    wmma::mma_sync(acc[i][j], af[i], bf[j], acc[i][j]);
        }
        __syncthreads();
    }

    // write accumulators to smem (aliases As/Bs — all mma reads done)
#pragma unroll
    for (int i = 0; i < 2; i++)
#pragma unroll
        for (int j = 0; j < 2; j++)
            wmma::store_matrix_sync(&Cs[(wid * 32 + i * 16) * K6_LDC + j * 16],
                                    acc[i][j], K6_LDC, wmma::mem_row_major);
    __syncthreads();

    // fused epilogue: 256 x 32 tile = 2048 float4 (8/thread)
    float g = gamma[0];
    const float* xb = x + (size_t)b * CC * HW;
    const float* sb = g_spA + (size_t)b * CC * HW;
#pragma unroll
    for (int i = tid; i < 2048; i += 256) {
        int r = i / 8, q = i % 8;   // r = channel, q*4 = n offset
        float gt = 1.f + g_gate[b * 256 + r];
        float4 w4 = *(const float4*)&Cs[r * K6_LDC + q * 4];
        float4 xv = *(const float4*)&xb[(size_t)r * HW + n0 + q * 4];
        float4 sv = *(const float4*)&sb[(size_t)r * HW + n0 + q * 4];
        float4 o;
        o.x = g * w4.x + xv.x * gt + sv.x;
        o.y = g * w4.y + xv.y * gt + sv.y;
        o.z = g * w4.z + xv.z * gt + sv.z;
        o.w = g * w4.w + xv.w * gt + sv.w;
        *(float4*)&out[((size_t)b * CC + r) * HW + n0 + q * 4] = o;
    }
}

// ---------------- launch ----------------
extern "C" void kernel_launch(void* const* d_in, const int* in_sizes, int n_in,
                              void* d_out, int out_size) {
    const float* x     = (const float*)d_in[0];
    const float* q_w   = (const float*)d_in[1];
    const float* q_b   = (const float*)d_in[2];
    const float* q_bs  = (const float*)d_in[3];
    const float* q_bb  = (const float*)d_in[4];
    const float* q_bm  = (const float*)d_in[5];
    const float* q_bv  = (const float*)d_in[6];
    const float* k_w   = (const float*)d_in[7];
    const float* k_b   = (const float*)d_in[8];
    const float* k_bs  = (const float*)d_in[9];
    const float* k_bb  = (const float*)d_in[10];
    const float* k_bm  = (const float*)d_in[11];
    const float* k_bv  = (const float*)d_in[12];
    const float* v_w   = (const float*)d_in[13];
    const float* v_b   = (const float*)d_in[14];
    const float* gamma = (const float*)d_in[15];
    const float* c_w1  = (const float*)d_in[16];
    const float* c_b1  = (const float*)d_in[17];
    const float* c_w2  = (const float*)d_in[18];
    const float* c_b2  = (const float*)d_in[19];
    const float* s_vw  = (const float*)d_in[20];
    const float* s_vb  = (const float*)d_in[21];
    const float* s_cw  = (const float*)d_in[22];
    const float* s_cb  = (const float*)d_in[23];
    const float* s_bs  = (const float*)d_in[24];
    const float* s_bb  = (const float*)d_in[25];
    const float* s_bm  = (const float*)d_in[26];
    const float* s_bv  = (const float*)d_in[27];
    float* out = (float*)d_out;

    // weight transpose for q/k conv
    k_wt<<<288, 256>>>(q_w, k_w);
    // q/k conv + bn + relu
    k_qkconv<<<dim3(4, 8, BB), dim3(16, 8)>>>(x,
        q_b, q_bs, q_bb, q_bm, q_bv,
        k_b, k_bs, k_bb, k_bm, k_bv);
    // S = q^T k (tf32 tensor cores)
    k_qk_gemm<<<dim3(32, 32, BB), 256>>>();
    // softmax rows (fp32 -> bf16)
    k_softmax<<<BB * HW, 256>>>();
    // fused v (bf16) + v2 (fp32) 1x1 convs (tf32 tensor cores)
    k_1x1_fused<<<dim3(32, 8, BB), 256>>>(v_w, v_b, s_vw, s_vb, x);
    // channel gate
    k_chanstats<<<BB * CC, 256>>>(x);
    k_gate<<<BB, 256>>>(c_w1, c_b1, c_w2, c_b2);
    // spatial attention pipeline
    k_smreduce<<<dim3(16, BB), 256>>>();
    k_sconv<<<dim3(16, BB), 256>>>(s_cw, s_cb, s_bs, s_bb, s_bm, s_bv);
    k_rowsoftmax<<<BB * 64, 64>>>();
    k_spatial<<<dim3(64, BB), 256>>>(x);
    // final HMMA GEMM + fused epilogue (aff read once)
    k_attn_out<<<dim3(128, 1, BB), 256>>>(x, gamma, out);
    (void)in_sizes; (void)n_in; (void)out_size;
}

// round 14
// speedup vs baseline: 1.9650x; 1.1446x over previous
#include <cuda_runtime.h>
#include <cuda_bf16.h>
#include <mma.h>
#include <math.h>
#include <stdint.h>

using namespace nvcuda;

// Shapes (fixed): B=4, C=256, H=W=64, HW=4096, C8=32, C2=128
#define BB 4
#define CC 256
#define HW 4096
#define C8 32
#define C2 128

// ---------------- device scratch (allocation-free) ----------------
__device__ float g_q[BB * C8 * HW];                      // 2 MB
__device__ float g_k[BB * C8 * HW];                      // 2 MB
__device__ __nv_bfloat16 g_vh[BB * CC * HW];             // 8 MB  (v in bf16)
__device__ float g_v2[BB * CC * HW];                     // 16 MB
__device__ float g_spA[BB * CC * HW];                    // 16 MB
__device__ float g_aff[(size_t)BB * HW * HW];            // 268 MB (logits, fp32)
__device__ __nv_bfloat16 g_affh[(size_t)BB * HW * HW];   // 134 MB (softmax out, bf16)
__device__ float g_wt[256 * 9 * 64];                     // transposed q/k conv weights
__device__ float g_gate[BB * CC];
__device__ float g_cmean[BB * CC];
__device__ float g_cmax[BB * CC];
__device__ float g_sm[BB * 2 * HW];
__device__ float g_att[BB * HW];
__device__ float g_a[BB * 64 * 64];

__device__ __forceinline__ uint32_t smem_to_u32(const void* p) {
    uint32_t a;
    asm("{ .reg .u64 t; cvta.to.shared.u64 t, %1; cvt.u32.u64 %0, t; }" : "=r"(a) : "l"(p));
    return a;
}
#define CP_ASYNC_16(dst_u32, src_ptr) \
    asm volatile("cp.async.cg.shared.global [%0], [%1], 16;" :: "r"(dst_u32), "l"(src_ptr))
#define CP_ASYNC_COMMIT() asm volatile("cp.async.commit_group;" ::: "memory")
#define CP_ASYNC_WAIT_1() asm volatile("cp.async.wait_group 1;" ::: "memory")
#define CP_ASYNC_WAIT_0() asm volatile("cp.async.wait_group 0;" ::: "memory")

// ---------------- K0: transpose conv weights to [ic][tap][64oc] ----------------
__global__ void k_wt(const float* __restrict__ qw, const float* __restrict__ kw) {
    int i = blockIdx.x * blockDim.x + threadIdx.x;
    if (i >= 256 * 9 * 32) return;
    int oc = i % 32;
    int t  = (i / 32) % 9;
    int ic = i / (32 * 9);
    g_wt[(ic * 9 + t) * 64 + oc]      = qw[(oc * 256 + ic) * 9 + t];
    g_wt[(ic * 9 + t) * 64 + 32 + oc] = kw[(oc * 256 + ic) * 9 + t];
}

// ---------------- K1: fused q/k conv3x3 + BN + ReLU ----------------
__global__ __launch_bounds__(128) void k_qkconv(
    const float* __restrict__ x,
    const float* __restrict__ qb, const float* __restrict__ qs,
    const float* __restrict__ qbb, const float* __restrict__ qm, const float* __restrict__ qv,
    const float* __restrict__ kb, const float* __restrict__ ks_,
    const float* __restrict__ kbb, const float* __restrict__ km, const float* __restrict__ kv)
{
    __shared__ float xt[10][18];
    __shared__ float wsm[576];
    int b  = blockIdx.z;
    int th = blockIdx.y;
    int tw = blockIdx.x;
    int tx = threadIdx.x, ty = threadIdx.y;
    int tid = ty * 16 + tx;

    float acc[64];
#pragma unroll
    for (int i = 0; i < 64; i++) acc[i] = 0.f;

    const float* xb = x + (size_t)b * CC * HW;

    for (int ic = 0; ic < 256; ic++) {
        for (int i = tid; i < 180; i += 128) {
            int r = i / 18, c = i % 18;
            int gh = th * 8 + r - 1, gw = tw * 16 + c - 1;
            float v = 0.f;
            if (gh >= 0 && gh < 64 && gw >= 0 && gw < 64)
                v = xb[ic * HW + gh * 64 + gw];
            xt[r][c] = v;
        }
        for (int i = tid; i < 144; i += 128)
            ((float4*)wsm)[i] = ((const float4*)(g_wt + ic * 576))[i];
        __syncthreads();

        float xv[9];
#pragma unroll
        for (int dy = 0; dy < 3; dy++)
#pragma unroll
            for (int dx = 0; dx < 3; dx++)
                xv[dy * 3 + dx] = xt[ty + dy][tx + dx];

#pragma unroll
        for (int t = 0; t < 9; t++) {
            float xvt = xv[t];
            const float4* wrow = (const float4*)(wsm + t * 64);
#pragma unroll
            for (int o4 = 0; o4 < 16; o4++) {
                float4 wv = wrow[o4];
                acc[o4 * 4 + 0] += xvt * wv.x;
                acc[o4 * 4 + 1] += xvt * wv.y;
                acc[o4 * 4 + 2] += xvt * wv.z;
                acc[o4 * 4 + 3] += xvt * wv.w;
            }
        }
        __syncthreads();
    }

    int h = th * 8 + ty, w = tw * 16 + tx;
    int p = h * 64 + w;
#pragma unroll
    for (int oc = 0; oc < 32; oc++) {
        float A  = rsqrtf(qv[oc] + 1e-5f) * qs[oc];
        float Bc = (qb[oc] - qm[oc]) * A + qbb[oc];
        g_q[((size_t)b * 32 + oc) * HW + p] = fmaxf(acc[oc] * A + Bc, 0.f);
    }
#pragma unroll
    for (int oc = 0; oc < 32; oc++) {
        float A  = rsqrtf(kv[oc] + 1e-5f) * ks_[oc];
        float Bc = (kb[oc] - km[oc]) * A + kbb[oc];
        g_k[((size_t)b * 32 + oc) * HW + p] = fmaxf(acc[32 + oc] * A + Bc, 0.f);
    }
}

// ---------------- K2 (tf32 wmma): S[b][n][m] = sum_c q[b][c][n] * k[b][c][m] --------
#define K2_LD 132
__global__ __launch_bounds__(256) void k_qk_gemm() {
    __shared__ float Qs[32 * K2_LD];
    __shared__ float Ks[32 * K2_LD];
    int b  = blockIdx.z;
    int n0 = blockIdx.y * 128;
    int m0 = blockIdx.x * 128;
    int tid = threadIdx.x;
    const float* qbp = g_q + (size_t)b * C8 * HW;
    const float* kbp = g_k + (size_t)b * C8 * HW;

#pragma unroll
    for (int i = tid; i < 1024; i += 256) {
        int r = i / 32, q4 = i % 32;
        *(float4*)&Qs[r * K2_LD + q4 * 4] = *(const float4*)&qbp[r * HW + n0 + q4 * 4];
        *(float4*)&Ks[r * K2_LD + q4 * 4] = *(const float4*)&kbp[r * HW + m0 + q4 * 4];
    }
    __syncthreads();

    int wid = tid / 32;
    int wn = wid % 2;
    int wm = wid / 2;

    wmma::fragment<wmma::accumulator, 16, 16, 8, float> acc[4][2];
#pragma unroll
    for (int i = 0; i < 4; i++)
#pragma unroll
        for (int j = 0; j < 2; j++) wmma::fill_fragment(acc[i][j], 0.f);

#pragma unroll
    for (int kk = 0; kk < 32; kk += 8) {
        wmma::fragment<wmma::matrix_a, 16, 16, 8, wmma::precision::tf32, wmma::col_major> af[4];
        wmma::fragment<wmma::matrix_b, 16, 16, 8, wmma::precision::tf32, wmma::row_major> bf[2];
#pragma unroll
        for (int i = 0; i < 4; i++) {
            wmma::load_matrix_sync(af[i], &Qs[kk * K2_LD + wn * 64 + i * 16], K2_LD);
#pragma unroll
            for (int t = 0; t < af[i].num_elements; t++)
                af[i].x[t] = wmma::__float_to_tf32(af[i].x[t]);
        }
#pragma unroll
        for (int j = 0; j < 2; j++) {
            wmma::load_matrix_sync(bf[j], &Ks[kk * K2_LD + wm * 32 + j * 16], K2_LD);
#pragma unroll
            for (int t = 0; t < bf[j].num_elements; t++)
                bf[j].x[t] = wmma::__float_to_tf32(bf[j].x[t]);
        }
#pragma unroll
        for (int i = 0; i < 4; i++)
#pragma unroll
            for (int j = 0; j < 2; j++)
                wmma::mma_sync(acc[i][j], af[i], bf[j], acc[i][j]);
    }

    float* outp = g_aff + (size_t)b * HW * HW;
#pragma unroll
    for (int i = 0; i < 4; i++)
#pragma unroll
        for (int j = 0; j < 2; j++)
            wmma::store_matrix_sync(
                &outp[(size_t)(n0 + wn * 64 + i * 16) * HW + m0 + wm * 32 + j * 16],
                acc[i][j], HW, wmma::mem_row_major);
}

// ---------------- K3: row softmax of aff (rows of 4096), fp32 in -> bf16 out ----------------
__global__ __launch_bounds__(256) void k_softmax() {
    size_t row = blockIdx.x;
    const float* p = g_aff + row * HW;
    __nv_bfloat162* ph = (__nv_bfloat162*)(g_affh + row * HW);
    int tid = threadIdx.x;
    __shared__ float red[256];

    float4 v[4];
#pragma unroll
    for (int i = 0; i < 4; i++) v[i] = ((const float4*)p)[i * 256 + tid];

    float mx = -INFINITY;
#pragma unroll
    for (int i = 0; i < 4; i++) {
        mx = fmaxf(mx, fmaxf(fmaxf(v[i].x, v[i].y), fmaxf(v[i].z, v[i].w)));
    }
    red[tid] = mx; __syncthreads();
    for (int s = 128; s > 0; s >>= 1) {
        if (tid < s) red[tid] = fmaxf(red[tid], red[tid + s]);
        __syncthreads();
    }
    mx = red[0]; __syncthreads();

    float sum = 0.f;
#pragma unroll
    for (int i = 0; i < 4; i++) {
        v[i].x = expf(v[i].x - mx); v[i].y = expf(v[i].y - mx);
        v[i].z = expf(v[i].z - mx); v[i].w = expf(v[i].w - mx);
        sum += v[i].x + v[i].y + v[i].z + v[i].w;
    }
    red[tid] = sum; __syncthreads();
    for (int s = 128; s > 0; s >>= 1) {
        if (tid < s) red[tid] += red[tid + s];
        __syncthreads();
    }
    float inv = 1.f / red[0];
#pragma unroll
    for (int i = 0; i < 4; i++) {
        int idx = i * 512 + tid * 2;
        ph[idx]     = __floats2bfloat162_rn(v[i].x * inv, v[i].y * inv);
        ph[idx + 1] = __floats2bfloat162_rn(v[i].z * inv, v[i].w * inv);
    }
}

// ---------------- K4 (tf32 wmma, fused): [v ; v2] = [v_w ; s_vw] @ x + bias ----------
#define K4_LDA 36
#define K4_LDB 132
__global__ __launch_bounds__(256) void k_1x1_fused(
    const float* __restrict__ vw, const float* __restrict__ vb,
    const float* __restrict__ sw, const float* __restrict__ sb,
    const float* __restrict__ x)
{
    __shared__ __align__(16) float smem[64 * K4_LDB];
    float* As = smem;
    float* Bs = smem + 64 * K4_LDA;
    float* Cs = smem;

    int b  = blockIdx.z;
    int m0 = blockIdx.y * 64;
    int n0 = blockIdx.x * 128;
    int tid = threadIdx.x;
    int wid = tid / 32;
    int wm = wid % 2;
    int wn = wid / 2;

    bool vhalf = (m0 < 256);
    const float* W  = vhalf ? (vw + m0 * 256) : (sw + (m0 - 256) * 256);
    const float* bi = vhalf ? (vb + m0) : (sb + (m0 - 256));
    const float* xb = x + (size_t)b * CC * HW;

    wmma::fragment<wmma::accumulator, 16, 16, 8, float> acc[2][2];
#pragma unroll
    for (int i = 0; i < 2; i++)
#pragma unroll
        for (int j = 0; j < 2; j++) wmma::fill_fragment(acc[i][j], 0.f);

    for (int k0 = 0; k0 < 256; k0 += 32) {
#pragma unroll
        for (int i = tid; i < 512; i += 256) {
            int r = i / 8, q = i % 8;
            *(float4*)&As[r * K4_LDA + q * 4] = *(const float4*)&W[r * 256 + k0 + q * 4];
        }
#pragma unroll
        for (int i = tid; i < 1024; i += 256) {
            int r = i / 32, q = i % 32;
            *(float4*)&Bs[r * K4_LDB + q * 4] =
                *(const float4*)&xb[(size_t)(k0 + r) * HW + n0 + q * 4];
        }
        __syncthreads();

#pragma unroll
        for (int kk = 0; kk < 32; kk += 8) {
            wmma::fragment<wmma::matrix_a, 16, 16, 8, wmma::precision::tf32, wmma::row_major> af[2];
            wmma::fragment<wmma::matrix_b, 16, 16, 8, wmma::precision::tf32, wmma::row_major> bf[2];
#pragma unroll
            for (int i = 0; i < 2; i++) {
                wmma::load_matrix_sync(af[i], &As[(wm * 32 + i * 16) * K4_LDA + kk], K4_LDA);
#pragma unroll
                for (int t = 0; t < af[i].num_elements; t++)
                    af[i].x[t] = wmma::__float_to_tf32(af[i].x[t]);
            }
#pragma unroll
            for (int j = 0; j < 2; j++) {
                wmma::load_matrix_sync(bf[j], &Bs[kk * K4_LDB + wn * 32 + j * 16], K4_LDB);
#pragma unroll
                for (int t = 0; t < bf[j].num_elements; t++)
                    bf[j].x[t] = wmma::__float_to_tf32(bf[j].x[t]);
            }
#pragma unroll
            for (int i = 0; i < 2; i++)
#pragma unroll
                for (int j = 0; j < 2; j++)
                    wmma::mma_sync(acc[i][j], af[i], bf[j], acc[i][j]);
        }
        __syncthreads();
    }

#pragma unroll
    for (int i = 0; i < 2; i++)
#pragma unroll
        for (int j = 0; j < 2; j++)
            wmma::store_matrix_sync(&Cs[(wm * 32 + i * 16) * K4_LDB + wn * 32 + j * 16],
                                    acc[i][j], K4_LDB, wmma::mem_row_major);
    __syncthreads();

    if (vhalf) {
        __nv_bfloat16* ob = g_vh + (size_t)b * CC * HW;
#pragma unroll
        for (int i = tid; i < 2048; i += 256) {
            int r = i / 32, q = i % 32;
            float bo = bi[r];
            float4 c4 = *(const float4*)&Cs[r * K4_LDB + q * 4];
            __nv_bfloat162* d = (__nv_bfloat162*)&ob[(size_t)(m0 + r) * HW + n0 + q * 4];
            d[0] = __floats2bfloat162_rn(c4.x + bo, c4.y + bo);
            d[1] = __floats2bfloat162_rn(c4.z + bo, c4.w + bo);
        }
    } else {
        float* ob = g_v2 + (size_t)b * CC * HW;
#pragma unroll
        for (int i = tid; i < 2048; i += 256) {
            int r = i / 32, q = i % 32;
            float bo = bi[r];
            float4 c4 = *(const float4*)&Cs[r * K4_LDB + q * 4];
            float4 o = make_float4(c4.x + bo, c4.y + bo, c4.z + bo, c4.w + bo);
            *(float4*)&ob[(size_t)(m0 - 256 + r) * HW + n0 + q * 4] = o;
        }
    }
}

// ---------------- channel stats ----------------
__global__ __launch_bounds__(256) void k_chanstats(const float* __restrict__ x) {
    int bc = blockIdx.x;
    const float* p = x + (size_t)bc * HW;
    int tid = threadIdx.x;
    float s = 0.f, m = -INFINITY;
#pragma unroll
    for (int i = 0; i < 4; i++) {
        float4 v = ((const float4*)p)[i * 256 + tid];
        s += v.x + v.y + v.z + v.w;
        m = fmaxf(m, fmaxf(fmaxf(v.x, v.y), fmaxf(v.z, v.w)));
    }
    __shared__ float rs[256], rm[256];
    rs[tid] = s; rm[tid] = m; __syncthreads();
    for (int st = 128; st > 0; st >>= 1) {
        if (tid < st) { rs[tid] += rs[tid + st]; rm[tid] = fmaxf(rm[tid], rm[tid + st]); }
        __syncthreads();
    }
    if (tid == 0) { g_cmean[bc] = rs[0] * (1.f / 4096.f); g_cmax[bc] = rm[0]; }
}

// ---------------- channel gate FC ----------------
__global__ __launch_bounds__(256) void k_gate(
    const float* __restrict__ cw1, const float* __restrict__ cb1,
    const float* __restrict__ cw2, const float* __restrict__ cb2)
{
    int b = blockIdx.x;
    __shared__ float hsum[128];
    __shared__ float sme[256], sma[256];
    int tid = threadIdx.x;
    sme[tid] = g_cmean[b * 256 + tid];
    sma[tid] = g_cmax[b * 256 + tid];
    __syncthreads();
    if (tid < 128) {
        float am = cb1[tid], ax = cb1[tid];
        const float* wr = cw1 + tid * 256;
        for (int c = 0; c < 256; c++) { float w = wr[c]; am += w * sme[c]; ax += w * sma[c]; }
        hsum[tid] = fmaxf(am, 0.f) + fmaxf(ax, 0.f);
    }
    __syncthreads();
    float o = 2.f * cb2[tid];
    const float* wr = cw2 + tid * 128;
    for (int j = 0; j < 128; j++) o += wr[j] * hsum[j];
    g_gate[b * 256 + tid] = 1.f / (1.f + expf(-o));
}

// ---------------- v2 channel max/mean per pixel ----------------
__global__ __launch_bounds__(256) void k_smreduce() {
    int b = blockIdx.y;
    int p = blockIdx.x * 256 + threadIdx.x;
    const float* v2 = g_v2 + (size_t)b * CC * HW + p;
    float mx = -INFINITY, s = 0.f;
    for (int c = 0; c < 256; c++) {
        float v = v2[(size_t)c * HW];
        mx = fmaxf(mx, v); s += v;
    }
    g_sm[b * 8192 + p] = mx;
    g_sm[b * 8192 + 4096 + p] = s * (1.f / 256.f);
}

// ---------------- spatial conv 3x3 (2->1) + BN ----------------
__global__ __launch_bounds__(256) void k_sconv(
    const float* __restrict__ scw, const float* __restrict__ scb,
    const float* __restrict__ bs, const float* __restrict__ bbi,
    const float* __restrict__ bm, const float* __restrict__ bv)
{
    int b = blockIdx.y;
    int p = blockIdx.x * 256 + threadIdx.x;
    int h = p / 64, w = p % 64;
    float acc = 0.f;
    const float* smb = g_sm + b * 8192;
    for (int ci = 0; ci < 2; ci++)
#pragma unroll
        for (int dy = 0; dy < 3; dy++)
#pragma unroll
            for (int dx = 0; dx < 3; dx++) {
                int hh = h + dy - 1, ww = w + dx - 1;
                if (hh >= 0 && hh < 64 && ww >= 0 && ww < 64)
                    acc += scw[ci * 9 + dy * 3 + dx] * smb[ci * 4096 + hh * 64 + ww];
            }
    float A = rsqrtf(bv[0] + 1e-5f) * bs[0];
    g_att[b * 4096 + p] = (acc + scb[0] - bm[0]) * A + bbi[0];
}

// ---------------- softmax over W (rows of 64) -> g_a ----------------
__global__ __launch_bounds__(64) void k_rowsoftmax() {
    int row = blockIdx.x;
    int tid = threadIdx.x;
    float v = g_att[row * 64 + tid];
    __shared__ float red[64];
    red[tid] = v; __syncthreads();
    for (int s = 32; s > 0; s >>= 1) {
        if (tid < s) red[tid] = fmaxf(red[tid], red[tid + s]);
        __syncthreads();
    }
    float mx = red[0]; __syncthreads();
    float e = expf(v - mx);
    red[tid] = e; __syncthreads();
    for (int s = 32; s > 0; s >>= 1) {
        if (tid < s) red[tid] += red[tid + s];
        __syncthreads();
    }
    g_a[row * 64 + tid] = e / red[0];
}

// ---------------- spatialA[b,c,h,k] = sum_w x[b,c,h,w] * a[b,w,k] ----------------
__global__ __launch_bounds__(256) void k_spatial(const float* __restrict__ x) {
    int b = blockIdx.y, h = blockIdx.x;
    __shared__ float a_s[64 * 64];
    __shared__ float xs[4][64];
    int tid = threadIdx.x;
    for (int i = tid; i < 4096; i += 256) a_s[i] = g_a[b * 4096 + i];
    int cg = tid / 64, k = tid % 64;
    const float* xb = x + (size_t)b * CC * HW + h * 64;
    float* ob = g_spA + (size_t)b * CC * HW + h * 64;
    for (int c0 = 0; c0 < 256; c0 += 4) {
        __syncthreads();
        xs[cg][k] = xb[(size_t)(c0 + cg) * HW + k];
        __syncthreads();
        float acc = 0.f;
#pragma unroll 8
        for (int w = 0; w < 64; w++) acc += xs[cg][w] * a_s[w * 64 + k];
        ob[(size_t)(c0 + cg) * HW + k] = acc;
    }
}

// ---------------- K6 (bf16 wmma + cp.async 2-stage): out = gamma*(v@aff^T)+x*(1+gate)+spA
// Block tile 128(c) x 128(n), BK=64, double-buffered cp.async.
// warps: 2(c) x 4(n), warp tile 64x32 -> acc[4][2] of 16x16.
// dyn smem: stage s at s*36864: A[128][72]bf16 (18432B) then B[128][72]bf16.
// epilogue reuses smem as Cs[128][132] fp32 (67584B <= 73728B).
#define K6_LDS 72
#define K6_STAGE 36864
#define K6_LDC 132
__global__ void __launch_bounds__(256, 2) k_attn_out(
    const float* __restrict__ x, const float* __restrict__ gamma, float* __restrict__ out)
{
    extern __shared__ __align__(16) char dsm[];
    uint32_t smem_u32 = smem_to_u32(dsm);

    int b  = blockIdx.z;
    int c0 = blockIdx.y * 128;
    int n0 = blockIdx.x * 128;
    int tid = threadIdx.x;
    int wid = tid / 32;
    int wr = wid / 4;   // 0..1  c-direction (64 rows each)
    int wc = wid % 4;   // 0..3  n-direction (32 cols each)

    const __nv_bfloat16* vb = g_vh + (size_t)b * CC * HW + (size_t)c0 * HW;
    const __nv_bfloat16* ab = g_affh + (size_t)b * HW * HW + (size_t)n0 * HW;

    // per-thread staging slots: 4 x 16B for A, 4 for B per chunk
    int r_[4], q_[4];
#pragma unroll
    for (int t = 0; t < 4; t++) {
        int idx = t * 256 + tid;          // 0..1023
        r_[t] = idx >> 3;                 // row 0..127
        q_[t] = idx & 7;                  // 16B unit within 128B row
    }

    // issue chunk ck's loads into stage (ck & 1)
    auto stage = [&](int ck) {
        uint32_t base = smem_u32 + (ck & 1) * K6_STAGE;
        int m0 = ck * 64;
#pragma unroll
        for (int t = 0; t < 4; t++) {
            uint32_t off = (uint32_t)(r_[t] * K6_LDS + q_[t] * 8) * 2;  // bf16 bytes
            CP_ASYNC_16(base + off, (const void*)&vb[(size_t)r_[t] * HW + m0 + q_[t] * 8]);
            CP_ASYNC_16(base + 18432 + off, (const void*)&ab[(size_t)r_[t] * HW + m0 + q_[t] * 8]);
        }
        CP_ASYNC_COMMIT();
    };

    wmma::fragment<wmma::accumulator, 16, 16, 16, float> acc[4][2];
#pragma unroll
    for (int i = 0; i < 4; i++)
#pragma unroll
        for (int j = 0; j < 2; j++) wmma::fill_fragment(acc[i][j], 0.f);

    stage(0);

    for (int ck = 0; ck < 64; ck++) {
        if (ck + 1 < 64) { stage(ck + 1); CP_ASYNC_WAIT_1(); }
        else             { CP_ASYNC_WAIT_0(); }
        __syncthreads();

        const __nv_bfloat16* As = (const __nv_bfloat16*)(dsm + (ck & 1) * K6_STAGE);
        const __nv_bfloat16* Bs = (const __nv_bfloat16*)(dsm + (ck & 1) * K6_STAGE + 18432);

#pragma unroll
        for (int kk = 0; kk < 64; kk += 16) {
            wmma::fragment<wmma::matrix_a, 16, 16, 16, __nv_bfloat16, wmma::row_major> af[4];
            wmma::fragment<wmma::matrix_b, 16, 16, 16, __nv_bfloat16, wmma::col_major> bf[2];
#pragma unroll
            for (int i = 0; i < 4; i++)
                wmma::load_matrix_sync(af[i], &As[(wr * 64 + i * 16) * K6_LDS + kk], K6_LDS);
#pragma unroll
            for (int j = 0; j < 2; j++)
                wmma::load_matrix_sync(bf[j], &Bs[(wc * 32 + j * 16) * K6_LDS + kk], K6_LDS);
#pragma unroll
            for (int i = 0; i < 4; i++)
#pragma unroll
                for (int j = 0; j < 2; j++)
                    wmma::mma_sync(acc[i][j], af[i], bf[j], acc[i][j]);
        }
        __syncthreads();   // all warps done reading this stage before it is refilled
    }

    // stage accumulators to smem union: Cs[128][132] fp32
    float* Cs = (float*)dsm;
#pragma unroll
    for (int i = 0; i < 4; i++)
#pragma unroll
        for (int j = 0; j < 2; j++)
            wmma::store_matrix_sync(&Cs[(wr * 64 + i * 16) * K6_LDC + wc * 32 + j * 16],
                                    acc[i][j], K6_LDC, wmma::mem_row_major);
    __syncthreads();

    // fused epilogue: 128 c x 128 n = 4096 float4 (16/thread)
    float g = gamma[0];
    const float* xb = x + (size_t)b * CC * HW;
    const float* sb = g_spA + (size_t)b * CC * HW;
#pragma unroll
    for (int i = tid; i < 4096; i += 256) {
        int r = i / 32, q = i % 32;
        int c = c0 + r;
        int nn = n0 + q * 4;
        float gt = 1.f + g_gate[b * 256 + c];
        float4 w4 = *(const float4*)&Cs[r * K6_LDC + q * 4];
        float4 xv = *(const float4*)&xb[(size_t)c * HW + nn];
        float4 sv = *(const float4*)&sb[(size_t)c * HW + nn];
        float4 o;
        o.x = g * w4.x + xv.x * gt + sv.x;
        o.y = g * w4.y + xv.y * gt + sv.y;
        o.z = g * w4.z + xv.z * gt + sv.z;
        o.w = g * w4.w + xv.w * gt + sv.w;
        *(float4*)&out[((size_t)b * CC + c) * HW + nn] = o;
    }
}

// ---------------- launch ----------------
extern "C" void kernel_launch(void* const* d_in, const int* in_sizes, int n_in,
                              void* d_out, int out_size) {
    const float* x     = (const float*)d_in[0];
    const float* q_w   = (const float*)d_in[1];
    const float* q_b   = (const float*)d_in[2];
    const float* q_bs  = (const float*)d_in[3];
    const float* q_bb  = (const float*)d_in[4];
    const float* q_bm  = (const float*)d_in[5];
    const float* q_bv  = (const float*)d_in[6];
    const float* k_w   = (const float*)d_in[7];
    const float* k_b   = (const float*)d_in[8];
    const float* k_bs  = (const float*)d_in[9];
    const float* k_bb  = (const float*)d_in[10];
    const float* k_bm  = (const float*)d_in[11];
    const float* k_bv  = (const float*)d_in[12];
    const float* v_w   = (const float*)d_in[13];
    const float* v_b   = (const float*)d_in[14];
    const float* gamma = (const float*)d_in[15];
    const float* c_w1  = (const float*)d_in[16];
    const float* c_b1  = (const float*)d_in[17];
    const float* c_w2  = (const float*)d_in[18];
    const float* c_b2  = (const float*)d_in[19];
    const float* s_vw  = (const float*)d_in[20];
    const float* s_vb  = (const float*)d_in[21];
    const float* s_cw  = (const float*)d_in[22];
    const float* s_cb  = (const float*)d_in[23];
    const float* s_bs  = (const float*)d_in[24];
    const float* s_bb  = (const float*)d_in[25];
    const float* s_bm  = (const float*)d_in[26];
    const float* s_bv  = (const float*)d_in[27];
    float* out = (float*)d_out;

    static bool attr_set = false;
    if (!attr_set) {
        cudaFuncSetAttribute(k_attn_out, cudaFuncAttributeMaxDynamicSharedMemorySize,
                             2 * K6_STAGE);
        attr_set = true;
    }

    k_wt<<<288, 256>>>(q_w, k_w);
    k_qkconv<<<dim3(4, 8, BB), dim3(16, 8)>>>(x,
        q_b, q_bs, q_bb, q_bm, q_bv,
        k_b, k_bs, k_bb, k_bm, k_bv);
    k_qk_gemm<<<dim3(32, 32, BB), 256>>>();
    k_softmax<<<BB * HW, 256>>>();
    k_1x1_fused<<<dim3(32, 8, BB), 256>>>(v_w, v_b, s_vw, s_vb, x);
    k_chanstats<<<BB * CC, 256>>>(x);
    k_gate<<<BB, 256>>>(c_w1, c_b1, c_w2, c_b2);
    k_smreduce<<<dim3(16, BB), 256>>>();
    k_sconv<<<dim3(16, BB), 256>>>(s_cw, s_cb, s_bs, s_bb, s_bm, s_bv);
    k_rowsoftmax<<<BB * 64, 64>>>();
    k_spatial<<<dim3(64, BB), 256>>>(x);
    // final bf16 wmma GEMM (128x128 tiles, cp.async pipeline) + fused epilogue
    k_attn_out<<<dim3(32, 2, BB), 256, 2 * K6_STAGE>>>(x, gamma, out);
    (void)in_sizes; (void)n_in; (void)out_size;
}

// round 15
// speedup vs baseline: 2.6473x; 1.3472x over previous
#include <cuda_runtime.h>
#include <cuda_bf16.h>
#include <mma.h>
#include <math.h>
#include <stdint.h>

using namespace nvcuda;

// Shapes (fixed): B=4, C=256, H=W=64, HW=4096, C8=32, C2=128
#define BB 4
#define CC 256
#define HW 4096
#define C8 32
#define C2 128

// ---------------- device scratch (allocation-free) ----------------
__device__ float g_q[BB * C8 * HW];                      // 2 MB
__device__ float g_k[BB * C8 * HW];                      // 2 MB
__device__ __nv_bfloat16 g_vh[BB * CC * HW];             // 8 MB  (v in bf16)
__device__ float g_v2[BB * CC * HW];                     // 16 MB
__device__ float g_spA[BB * CC * HW];                    // 16 MB
__device__ float g_aff[(size_t)BB * HW * HW];            // 268 MB (logits, fp32)
__device__ __nv_bfloat16 g_affh[(size_t)BB * HW * HW];   // 134 MB (softmax out, bf16)
__device__ float g_wt[256 * 9 * 64];                     // transposed q/k conv weights
__device__ float g_part[4 * BB * 64 * HW];               // 16 MB conv partial sums
__device__ float g_gate[BB * CC];
__device__ float g_cmean[BB * CC];
__device__ float g_cmax[BB * CC];
__device__ float g_sm[BB * 2 * HW];
__device__ float g_att[BB * HW];
__device__ float g_a[BB * 64 * 64];

__device__ __forceinline__ uint32_t smem_to_u32(const void* p) {
    uint32_t a;
    asm("{ .reg .u64 t; cvta.to.shared.u64 t, %1; cvt.u32.u64 %0, t; }" : "=r"(a) : "l"(p));
    return a;
}
#define CP_ASYNC_16(dst_u32, src_ptr) \
    asm volatile("cp.async.cg.shared.global [%0], [%1], 16;" :: "r"(dst_u32), "l"(src_ptr))
#define CP_ASYNC_COMMIT() asm volatile("cp.async.commit_group;" ::: "memory")
#define CP_ASYNC_WAIT_1() asm volatile("cp.async.wait_group 1;" ::: "memory")
#define CP_ASYNC_WAIT_0() asm volatile("cp.async.wait_group 0;" ::: "memory")

// ---------------- K0: transpose conv weights to [ic][tap][64oc] ----------------
__global__ void k_wt(const float* __restrict__ qw, const float* __restrict__ kw) {
    int i = blockIdx.x * blockDim.x + threadIdx.x;
    if (i >= 256 * 9 * 32) return;
    int oc = i % 32;
    int t  = (i / 32) % 9;
    int ic = i / (32 * 9);
    g_wt[(ic * 9 + t) * 64 + oc]      = qw[(oc * 256 + ic) * 9 + t];
    g_wt[(ic * 9 + t) * 64 + 32 + oc] = kw[(oc * 256 + ic) * 9 + t];
}

// ---------------- K1: q/k conv3x3 partial sums (4-way ic split) ----------------
// blockIdx.z = b*4 + s; ic range [s*64, s*64+64). Partial accumulators to g_part.
__global__ __launch_bounds__(128) void k_qkconv(const float* __restrict__ x)
{
    __shared__ float xt[10][18];
    __shared__ float wsm[576];
    int bz = blockIdx.z;
    int b  = bz >> 2;
    int s  = bz & 3;
    int ic0 = s * 64;
    int th = blockIdx.y;
    int tw = blockIdx.x;
    int tx = threadIdx.x, ty = threadIdx.y;
    int tid = ty * 16 + tx;

    float acc[64];
#pragma unroll
    for (int i = 0; i < 64; i++) acc[i] = 0.f;

    const float* xb = x + (size_t)b * CC * HW;

    for (int ic = ic0; ic < ic0 + 64; ic++) {
        for (int i = tid; i < 180; i += 128) {
            int r = i / 18, c = i % 18;
            int gh = th * 8 + r - 1, gw = tw * 16 + c - 1;
            float v = 0.f;
            if (gh >= 0 && gh < 64 && gw >= 0 && gw < 64)
                v = xb[ic * HW + gh * 64 + gw];
            xt[r][c] = v;
        }
        for (int i = tid; i < 144; i += 128)
            ((float4*)wsm)[i] = ((const float4*)(g_wt + ic * 576))[i];
        __syncthreads();

        float xv[9];
#pragma unroll
        for (int dy = 0; dy < 3; dy++)
#pragma unroll
            for (int dx = 0; dx < 3; dx++)
                xv[dy * 3 + dx] = xt[ty + dy][tx + dx];

#pragma unroll
        for (int t = 0; t < 9; t++) {
            float xvt = xv[t];
            const float4* wrow = (const float4*)(wsm + t * 64);
#pragma unroll
            for (int o4 = 0; o4 < 16; o4++) {
                float4 wv = wrow[o4];
                acc[o4 * 4 + 0] += xvt * wv.x;
                acc[o4 * 4 + 1] += xvt * wv.y;
                acc[o4 * 4 + 2] += xvt * wv.z;
                acc[o4 * 4 + 3] += xvt * wv.w;
            }
        }
        __syncthreads();
    }

    int h = th * 8 + ty, w = tw * 16 + tx;
    int p = h * 64 + w;
    float* pp = g_part + ((size_t)(s * BB + b) * 64) * HW + p;
#pragma unroll
    for (int oc = 0; oc < 64; oc++)
        pp[(size_t)oc * HW] = acc[oc];
}

// ---------------- K1b: sum partials + BN + ReLU -> g_q / g_k ----------------
__global__ __launch_bounds__(256) void k_qkbn(
    const float* __restrict__ qb, const float* __restrict__ qs,
    const float* __restrict__ qbb, const float* __restrict__ qm, const float* __restrict__ qv,
    const float* __restrict__ kb, const float* __restrict__ ks_,
    const float* __restrict__ kbb, const float* __restrict__ km, const float* __restrict__ kv)
{
    int oc = blockIdx.y;   // 0..63
    int b  = blockIdx.z;
    int p  = blockIdx.x * 256 + threadIdx.x;
    size_t off = ((size_t)b * 64 + oc) * HW + p;
    float acc = g_part[off] + g_part[(size_t)BB * 64 * HW + off]
              + g_part[(size_t)2 * BB * 64 * HW + off]
              + g_part[(size_t)3 * BB * 64 * HW + off];
    if (oc < 32) {
        float A  = rsqrtf(qv[oc] + 1e-5f) * qs[oc];
        float Bc = (qb[oc] - qm[oc]) * A + qbb[oc];
        g_q[((size_t)b * 32 + oc) * HW + p] = fmaxf(acc * A + Bc, 0.f);
    } else {
        int o = oc - 32;
        float A  = rsqrtf(kv[o] + 1e-5f) * ks_[o];
        float Bc = (kb[o] - km[o]) * A + kbb[o];
        g_k[((size_t)b * 32 + o) * HW + p] = fmaxf(acc * A + Bc, 0.f);
    }
}

// ---------------- K2 (tf32 wmma): S[b][n][m] = sum_c q[b][c][n] * k[b][c][m] --------
// tf32 rounding applied once at smem staging (numerics identical to per-frag cvt).
#define K2_LD 132
__global__ __launch_bounds__(256) void k_qk_gemm() {
    __shared__ float Qs[32 * K2_LD];
    __shared__ float Ks[32 * K2_LD];
    int b  = blockIdx.z;
    int n0 = blockIdx.y * 128;
    int m0 = blockIdx.x * 128;
    int tid = threadIdx.x;
    const float* qbp = g_q + (size_t)b * C8 * HW;
    const float* kbp = g_k + (size_t)b * C8 * HW;

#pragma unroll
    for (int i = tid; i < 1024; i += 256) {
        int r = i / 32, q4 = i % 32;
        float4 qv = *(const float4*)&qbp[r * HW + n0 + q4 * 4];
        float4 kv = *(const float4*)&kbp[r * HW + m0 + q4 * 4];
        qv.x = wmma::__float_to_tf32(qv.x); qv.y = wmma::__float_to_tf32(qv.y);
        qv.z = wmma::__float_to_tf32(qv.z); qv.w = wmma::__float_to_tf32(qv.w);
        kv.x = wmma::__float_to_tf32(kv.x); kv.y = wmma::__float_to_tf32(kv.y);
        kv.z = wmma::__float_to_tf32(kv.z); kv.w = wmma::__float_to_tf32(kv.w);
        *(float4*)&Qs[r * K2_LD + q4 * 4] = qv;
        *(float4*)&Ks[r * K2_LD + q4 * 4] = kv;
    }
    __syncthreads();

    int wid = tid / 32;
    int wn = wid % 2;
    int wm = wid / 2;

    wmma::fragment<wmma::accumulator, 16, 16, 8, float> acc[4][2];
#pragma unroll
    for (int i = 0; i < 4; i++)
#pragma unroll
        for (int j = 0; j < 2; j++) wmma::fill_fragment(acc[i][j], 0.f);

#pragma unroll
    for (int kk = 0; kk < 32; kk += 8) {
        wmma::fragment<wmma::matrix_a, 16, 16, 8, wmma::precision::tf32, wmma::col_major> af[4];
        wmma::fragment<wmma::matrix_b, 16, 16, 8, wmma::precision::tf32, wmma::row_major> bf[2];
#pragma unroll
        for (int i = 0; i < 4; i++)
            wmma::load_matrix_sync(af[i], &Qs[kk * K2_LD + wn * 64 + i * 16], K2_LD);
#pragma unroll
        for (int j = 0; j < 2; j++)
            wmma::load_matrix_sync(bf[j], &Ks[kk * K2_LD + wm * 32 + j * 16], K2_LD);
#pragma unroll
        for (int i = 0; i < 4; i++)
#pragma unroll
            for (int j = 0; j < 2; j++)
                wmma::mma_sync(acc[i][j], af[i], bf[j], acc[i][j]);
    }

    float* outp = g_aff + (size_t)b * HW * HW;
#pragma unroll
    for (int i = 0; i < 4; i++)
#pragma unroll
        for (int j = 0; j < 2; j++)
            wmma::store_matrix_sync(
                &outp[(size_t)(n0 + wn * 64 + i * 16) * HW + m0 + wm * 32 + j * 16],
                acc[i][j], HW, wmma::mem_row_major);
}

// ---------------- K3: row softmax of aff (rows of 4096), fp32 in -> bf16 out ----------------
__global__ __launch_bounds__(256) void k_softmax() {
    size_t row = blockIdx.x;
    const float* p = g_aff + row * HW;
    __nv_bfloat162* ph = (__nv_bfloat162*)(g_affh + row * HW);
    int tid = threadIdx.x;
    __shared__ float red[256];

    float4 v[4];
#pragma unroll
    for (int i = 0; i < 4; i++) v[i] = ((const float4*)p)[i * 256 + tid];

    float mx = -INFINITY;
#pragma unroll
    for (int i = 0; i < 4; i++) {
        mx = fmaxf(mx, fmaxf(fmaxf(v[i].x, v[i].y), fmaxf(v[i].z, v[i].w)));
    }
    red[tid] = mx; __syncthreads();
    for (int s = 128; s > 0; s >>= 1) {
        if (tid < s) red[tid] = fmaxf(red[tid], red[tid + s]);
        __syncthreads();
    }
    mx = red[0]; __syncthreads();

    float sum = 0.f;
#pragma unroll
    for (int i = 0; i < 4; i++) {
        v[i].x = expf(v[i].x - mx); v[i].y = expf(v[i].y - mx);
        v[i].z = expf(v[i].z - mx); v[i].w = expf(v[i].w - mx);
        sum += v[i].x + v[i].y + v[i].z + v[i].w;
    }
    red[tid] = sum; __syncthreads();
    for (int s = 128; s > 0; s >>= 1) {
        if (tid < s) red[tid] += red[tid + s];
        __syncthreads();
    }
    float inv = 1.f / red[0];
#pragma unroll
    for (int i = 0; i < 4; i++) {
        int idx = i * 512 + tid * 2;
        ph[idx]     = __floats2bfloat162_rn(v[i].x * inv, v[i].y * inv);
        ph[idx + 1] = __floats2bfloat162_rn(v[i].z * inv, v[i].w * inv);
    }
}

// ---------------- K4 (tf32 wmma, fused): [v ; v2] = [v_w ; s_vw] @ x + bias ----------
#define K4_LDA 36
#define K4_LDB 132
__global__ __launch_bounds__(256) void k_1x1_fused(
    const float* __restrict__ vw, const float* __restrict__ vb,
    const float* __restrict__ sw, const float* __restrict__ sb,
    const float* __restrict__ x)
{
    __shared__ __align__(16) float smem[64 * K4_LDB];
    float* As = smem;
    float* Bs = smem + 64 * K4_LDA;
    float* Cs = smem;

    int b  = blockIdx.z;
    int m0 = blockIdx.y * 64;
    int n0 = blockIdx.x * 128;
    int tid = threadIdx.x;
    int wid = tid / 32;
    int wm = wid % 2;
    int wn = wid / 2;

    bool vhalf = (m0 < 256);
    const float* W  = vhalf ? (vw + m0 * 256) : (sw + (m0 - 256) * 256);
    const float* bi = vhalf ? (vb + m0) : (sb + (m0 - 256));
    const float* xb = x + (size_t)b * CC * HW;

    wmma::fragment<wmma::accumulator, 16, 16, 8, float> acc[2][2];
#pragma unroll
    for (int i = 0; i < 2; i++)
#pragma unroll
        for (int j = 0; j < 2; j++) wmma::fill_fragment(acc[i][j], 0.f);

    for (int k0 = 0; k0 < 256; k0 += 32) {
#pragma unroll
        for (int i = tid; i < 512; i += 256) {
            int r = i / 8, q = i % 8;
            float4 wv = *(const float4*)&W[r * 256 + k0 + q * 4];
            wv.x = wmma::__float_to_tf32(wv.x); wv.y = wmma::__float_to_tf32(wv.y);
            wv.z = wmma::__float_to_tf32(wv.z); wv.w = wmma::__float_to_tf32(wv.w);
            *(float4*)&As[r * K4_LDA + q * 4] = wv;
        }
#pragma unroll
        for (int i = tid; i < 1024; i += 256) {
            int r = i / 32, q = i % 32;
            float4 xv = *(const float4*)&xb[(size_t)(k0 + r) * HW + n0 + q * 4];
            xv.x = wmma::__float_to_tf32(xv.x); xv.y = wmma::__float_to_tf32(xv.y);
            xv.z = wmma::__float_to_tf32(xv.z); xv.w = wmma::__float_to_tf32(xv.w);
            *(float4*)&Bs[r * K4_LDB + q * 4] = xv;
        }
        __syncthreads();

#pragma unroll
        for (int kk = 0; kk < 32; kk += 8) {
            wmma::fragment<wmma::matrix_a, 16, 16, 8, wmma::precision::tf32, wmma::row_major> af[2];
            wmma::fragment<wmma::matrix_b, 16, 16, 8, wmma::precision::tf32, wmma::row_major> bf[2];
#pragma unroll
            for (int i = 0; i < 2; i++)
                wmma::load_matrix_sync(af[i], &As[(wm * 32 + i * 16) * K4_LDA + kk], K4_LDA);
#pragma unroll
            for (int j = 0; j < 2; j++)
                wmma::load_matrix_sync(bf[j], &Bs[kk * K4_LDB + wn * 32 + j * 16], K4_LDB);
#pragma unroll
            for (int i = 0; i < 2; i++)
#pragma unroll
                for (int j = 0; j < 2; j++)
                    wmma::mma_sync(acc[i][j], af[i], bf[j], acc[i][j]);
        }
        __syncthreads();
    }

#pragma unroll
    for (int i = 0; i < 2; i++)
#pragma unroll
        for (int j = 0; j < 2; j++)
            wmma::store_matrix_sync(&Cs[(wm * 32 + i * 16) * K4_LDB + wn * 32 + j * 16],
                                    acc[i][j], K4_LDB, wmma::mem_row_major);
    __syncthreads();

    if (vhalf) {
        __nv_bfloat16* ob = g_vh + (size_t)b * CC * HW;
#pragma unroll
        for (int i = tid; i < 2048; i += 256) {
            int r = i / 32, q = i % 32;
            float bo = bi[r];
            float4 c4 = *(const float4*)&Cs[r * K4_LDB + q * 4];
            __nv_bfloat162* d = (__nv_bfloat162*)&ob[(size_t)(m0 + r) * HW + n0 + q * 4];
            d[0] = __floats2bfloat162_rn(c4.x + bo, c4.y + bo);
            d[1] = __floats2bfloat162_rn(c4.z + bo, c4.w + bo);
        }
    } else {
        float* ob = g_v2 + (size_t)b * CC * HW;
#pragma unroll
        for (int i = tid; i < 2048; i += 256) {
            int r = i / 32, q = i % 32;
            float bo = bi[r];
            float4 c4 = *(const float4*)&Cs[r * K4_LDB + q * 4];
            float4 o = make_float4(c4.x + bo, c4.y + bo, c4.z + bo, c4.w + bo);
            *(float4*)&ob[(size_t)(m0 - 256 + r) * HW + n0 + q * 4] = o;
        }
    }
}

// ---------------- channel stats ----------------
__global__ __launch_bounds__(256) void k_chanstats(const float* __restrict__ x) {
    int bc = blockIdx.x;
    const float* p = x + (size_t)bc * HW;
    int tid = threadIdx.x;
    float s = 0.f, m = -INFINITY;
#pragma unroll
    for (int i = 0; i < 4; i++) {
        float4 v = ((const float4*)p)[i * 256 + tid];
        s += v.x + v.y + v.z + v.w;
        m = fmaxf(m, fmaxf(fmaxf(v.x, v.y), fmaxf(v.z, v.w)));
    }
    __shared__ float rs[256], rm[256];
    rs[tid] = s; rm[tid] = m; __syncthreads();
    for (int st = 128; st > 0; st >>= 1) {
        if (tid < st) { rs[tid] += rs[tid + st]; rm[tid] = fmaxf(rm[tid], rm[tid + st]); }
        __syncthreads();
    }
    if (tid == 0) { g_cmean[bc] = rs[0] * (1.f / 4096.f); g_cmax[bc] = rm[0]; }
}

// ---------------- channel gate FC ----------------
__global__ __launch_bounds__(256) void k_gate(
    const float* __restrict__ cw1, const float* __restrict__ cb1,
    const float* __restrict__ cw2, const float* __restrict__ cb2)
{
    int b = blockIdx.x;
    __shared__ float hsum[128];
    __shared__ float sme[256], sma[256];
    int tid = threadIdx.x;
    sme[tid] = g_cmean[b * 256 + tid];
    sma[tid] = g_cmax[b * 256 + tid];
    __syncthreads();
    if (tid < 128) {
        float am = cb1[tid], ax = cb1[tid];
        const float* wr = cw1 + tid * 256;
        for (int c = 0; c < 256; c++) { float w = wr[c]; am += w * sme[c]; ax += w * sma[c]; }
        hsum[tid] = fmaxf(am, 0.f) + fmaxf(ax, 0.f);
    }
    __syncthreads();
    float o = 2.f * cb2[tid];
    const float* wr = cw2 + tid * 128;
    for (int j = 0; j < 128; j++) o += wr[j] * hsum[j];
    g_gate[b * 256 + tid] = 1.f / (1.f + expf(-o));
}

// ---------------- v2 channel max/mean per pixel ----------------
__global__ __launch_bounds__(256) void k_smreduce() {
    int b = blockIdx.y;
    int p = blockIdx.x * 256 + threadIdx.x;
    const float* v2 = g_v2 + (size_t)b * CC * HW + p;
    float mx = -INFINITY, s = 0.f;
    for (int c = 0; c < 256; c++) {
        float v = v2[(size_t)c * HW];
        mx = fmaxf(mx, v); s += v;
    }
    g_sm[b * 8192 + p] = mx;
    g_sm[b * 8192 + 4096 + p] = s * (1.f / 256.f);
}

// ---------------- spatial conv 3x3 (2->1) + BN ----------------
__global__ __launch_bounds__(256) void k_sconv(
    const float* __restrict__ scw, const float* __restrict__ scb,
    const float* __restrict__ bs, const float* __restrict__ bbi,
    const float* __restrict__ bm, const float* __restrict__ bv)
{
    int b = blockIdx.y;
    int p = blockIdx.x * 256 + threadIdx.x;
    int h = p / 64, w = p % 64;
    float acc = 0.f;
    const float* smb = g_sm + b * 8192;
    for (int ci = 0; ci < 2; ci++)
#pragma unroll
        for (int dy = 0; dy < 3; dy++)
#pragma unroll
            for (int dx = 0; dx < 3; dx++) {
                int hh = h + dy - 1, ww = w + dx - 1;
                if (hh >= 0 && hh < 64 && ww >= 0 && ww < 64)
                    acc += scw[ci * 9 + dy * 3 + dx] * smb[ci * 4096 + hh * 64 + ww];
            }
    float A = rsqrtf(bv[0] + 1e-5f) * bs[0];
    g_att[b * 4096 + p] = (acc + scb[0] - bm[0]) * A + bbi[0];
}

// ---------------- softmax over W (rows of 64) -> g_a ----------------
__global__ __launch_bounds__(64) void k_rowsoftmax() {
    int row = blockIdx.x;
    int tid = threadIdx.x;
    float v = g_att[row * 64 + tid];
    __shared__ float red[64];
    red[tid] = v; __syncthreads();
    for (int s = 32; s > 0; s >>= 1) {
        if (tid < s) red[tid] = fmaxf(red[tid], red[tid + s]);
        __syncthreads();
    }
    float mx = red[0]; __syncthreads();
    float e = expf(v - mx);
    red[tid] = e; __syncthreads();
    for (int s = 32; s > 0; s >>= 1) {
        if (tid < s) red[tid] += red[tid + s];
        __syncthreads();
    }
    g_a[row * 64 + tid] = e / red[0];
}

// ---------------- spatialA[b,c,h,k] = sum_w x[b,c,h,w] * a[b,w,k] ----------------
__global__ __launch_bounds__(256) void k_spatial(const float* __restrict__ x) {
    int b = blockIdx.y, h = blockIdx.x;
    __shared__ float a_s[64 * 64];
    __shared__ float xs[4][64];
    int tid = threadIdx.x;
    for (int i = tid; i < 4096; i += 256) a_s[i] = g_a[b * 4096 + i];
    int cg = tid / 64, k = tid % 64;
    const float* xb = x + (size_t)b * CC * HW + h * 64;
    float* ob = g_spA + (size_t)b * CC * HW + h * 64;
    for (int c0 = 0; c0 < 256; c0 += 4) {
        __syncthreads();
        xs[cg][k] = xb[(size_t)(c0 + cg) * HW + k];
        __syncthreads();
        float acc = 0.f;
#pragma unroll 8
        for (int w = 0; w < 64; w++) acc += xs[cg][w] * a_s[w * 64 + k];
        ob[(size_t)(c0 + cg) * HW + k] = acc;
    }
}

// ---------------- K6 (bf16 wmma + cp.async 3-stage): out = gamma*(v@aff^T)+x*(1+gate)+spA
// Block tile 128(c) x 128(n), BK=64, 3-stage cp.async pipeline, ONE sync per chunk.
// Refill of buffer (ck+2)%3 is issued after the sync, which also guarantees all warps
// finished reading buffer (ck-1)%3 == (ck+2)%3 in the previous iteration.
// dyn smem: 3 stages x 36864B; epilogue reuses smem as Cs[128][132] fp32.
#define K6_LDS 72
#define K6_STAGE 36864
#define K6_LDC 132
__global__ void __launch_bounds__(256, 2) k_attn_out(
    const float* __restrict__ x, const float* __restrict__ gamma, float* __restrict__ out)
{
    extern __shared__ __align__(16) char dsm[];
    uint32_t smem_u32 = smem_to_u32(dsm);

    int b  = blockIdx.z;
    int c0 = blockIdx.y * 128;
    int n0 = blockIdx.x * 128;
    int tid = threadIdx.x;
    int wid = tid / 32;
    int wr = wid / 4;   // 0..1  c-direction (64 rows each)
    int wc = wid % 4;   // 0..3  n-direction (32 cols each)

    const __nv_bfloat16* vb = g_vh + (size_t)b * CC * HW + (size_t)c0 * HW;
    const __nv_bfloat16* ab = g_affh + (size_t)b * HW * HW + (size_t)n0 * HW;

    int r_[4], q_[4];
#pragma unroll
    for (int t = 0; t < 4; t++) {
        int idx = t * 256 + tid;          // 0..1023
        r_[t] = idx >> 3;                 // row 0..127
        q_[t] = idx & 7;                  // 16B unit within 128B row
    }

    auto stage = [&](int ck) {
        uint32_t base = smem_u32 + (ck % 3) * K6_STAGE;
        int m0 = ck * 64;
#pragma unroll
        for (int t = 0; t < 4; t++) {
            uint32_t off = (uint32_t)(r_[t] * K6_LDS + q_[t] * 8) * 2;  // bf16 bytes
            CP_ASYNC_16(base + off, (const void*)&vb[(size_t)r_[t] * HW + m0 + q_[t] * 8]);
            CP_ASYNC_16(base + 18432 + off, (const void*)&ab[(size_t)r_[t] * HW + m0 + q_[t] * 8]);
        }
        CP_ASYNC_COMMIT();
    };

    wmma::fragment<wmma::accumulator, 16, 16, 16, float> acc[4][2];
#pragma unroll
    for (int i = 0; i < 4; i++)
#pragma unroll
        for (int j = 0; j < 2; j++) wmma::fill_fragment(acc[i][j], 0.f);

    stage(0);
    stage(1);

    for (int ck = 0; ck < 64; ck++) {
        if (ck < 63) CP_ASYNC_WAIT_1();    // pending {ck, ck+1} -> ck complete
        else         CP_ASYNC_WAIT_0();
        __syncthreads();                    // data ready + prev-iter reads of (ck+2)%3 done
        if (ck + 2 < 64) stage(ck + 2);     // refills buffer (ck-1)%3, safe post-sync

        const __nv_bfloat16* As = (const __nv_bfloat16*)(dsm + (ck % 3) * K6_STAGE);
        const __nv_bfloat16* Bs = (const __nv_bfloat16*)(dsm + (ck % 3) * K6_STAGE + 18432);

#pragma unroll
        for (int kk = 0; kk < 64; kk += 16) {
            wmma::fragment<wmma::matrix_a, 16, 16, 16, __nv_bfloat16, wmma::row_major> af[4];
            wmma::fragment<wmma::matrix_b, 16, 16, 16, __nv_bfloat16, wmma::col_major> bf[2];
#pragma unroll
            for (int i = 0; i < 4; i++)
                wmma::load_matrix_sync(af[i], &As[(wr * 64 + i * 16) * K6_LDS + kk], K6_LDS);
#pragma unroll
            for (int j = 0; j < 2; j++)
                wmma::load_matrix_sync(bf[j], &Bs[(wc * 32 + j * 16) * K6_LDS + kk], K6_LDS);
#pragma unroll
            for (int i = 0; i < 4; i++)
#pragma unroll
                for (int j = 0; j < 2; j++)
                    wmma::mma_sync(acc[i][j], af[i], bf[j], acc[i][j]);
        }
    }
    __syncthreads();   // all mma reads done before Cs overwrites stage memory

    float* Cs = (float*)dsm;
#pragma unroll
    for (int i = 0; i < 4; i++)
#pragma unroll
        for (int j = 0; j < 2; j++)
            wmma::store_matrix_sync(&Cs[(wr * 64 + i * 16) * K6_LDC + wc * 32 + j * 16],
                                    acc[i][j], K6_LDC, wmma::mem_row_major);
    __syncthreads();

    float g = gamma[0];
    const float* xb = x + (size_t)b * CC * HW;
    const float* sb = g_spA + (size_t)b * CC * HW;
#pragma unroll
    for (int i = tid; i < 4096; i += 256) {
        int r = i / 32, q = i % 32;
        int c = c0 + r;
        int nn = n0 + q * 4;
        float gt = 1.f + g_gate[b * 256 + c];
        float4 w4 = *(const float4*)&Cs[r * K6_LDC + q * 4];
        float4 xv = *(const float4*)&xb[(size_t)c * HW + nn];
        float4 sv = *(const float4*)&sb[(size_t)c * HW + nn];
        float4 o;
        o.x = g * w4.x + xv.x * gt + sv.x;
        o.y = g * w4.y + xv.y * gt + sv.y;
        o.z = g * w4.z + xv.z * gt + sv.z;
        o.w = g * w4.w + xv.w * gt + sv.w;
        *(float4*)&out[((size_t)b * CC + c) * HW + nn] = o;
    }
}

// ---------------- launch ----------------
extern "C" void kernel_launch(void* const* d_in, const int* in_sizes, int n_in,
                              void* d_out, int out_size) {
    const float* x     = (const float*)d_in[0];
    const float* q_w   = (const float*)d_in[1];
    const float* q_b   = (const float*)d_in[2];
    const float* q_bs  = (const float*)d_in[3];
    const float* q_bb  = (const float*)d_in[4];
    const float* q_bm  = (const float*)d_in[5];
    const float* q_bv  = (const float*)d_in[6];
    const float* k_w   = (const float*)d_in[7];
    const float* k_b   = (const float*)d_in[8];
    const float* k_bs  = (const float*)d_in[9];
    const float* k_bb  = (const float*)d_in[10];
    const float* k_bm  = (const float*)d_in[11];
    const float* k_bv  = (const float*)d_in[12];
    const float* v_w   = (const float*)d_in[13];
    const float* v_b   = (const float*)d_in[14];
    const float* gamma = (const float*)d_in[15];
    const float* c_w1  = (const float*)d_in[16];
    const float* c_b1  = (const float*)d_in[17];
    const float* c_w2  = (const float*)d_in[18];
    const float* c_b2  = (const float*)d_in[19];
    const float* s_vw  = (const float*)d_in[20];
    const float* s_vb  = (const float*)d_in[21];
    const float* s_cw  = (const float*)d_in[22];
    const float* s_cb  = (const float*)d_in[23];
    const float* s_bs  = (const float*)d_in[24];
    const float* s_bb  = (const float*)d_in[25];
    const float* s_bm  = (const float*)d_in[26];
    const float* s_bv  = (const float*)d_in[27];
    float* out = (float*)d_out;

    static bool attr_set = false;
    if (!attr_set) {
        cudaFuncSetAttribute(k_attn_out, cudaFuncAttributeMaxDynamicSharedMemorySize,
                             3 * K6_STAGE);
        attr_set = true;
    }

    k_wt<<<288, 256>>>(q_w, k_w);
    // conv partial sums (4-way ic split, 512 blocks) + fused BN/ReLU reduce
    k_qkconv<<<dim3(4, 8, BB * 4), dim3(16, 8)>>>(x);
    k_qkbn<<<dim3(16, 64, BB), 256>>>(q_b, q_bs, q_bb, q_bm, q_bv,
                                      k_b, k_bs, k_bb, k_bm, k_bv);
    k_qk_gemm<<<dim3(32, 32, BB), 256>>>();
    k_softmax<<<BB * HW, 256>>>();
    k_1x1_fused<<<dim3(32, 8, BB), 256>>>(v_w, v_b, s_vw, s_vb, x);
    k_chanstats<<<BB * CC, 256>>>(x);
    k_gate<<<BB, 256>>>(c_w1, c_b1, c_w2, c_b2);
    k_smreduce<<<dim3(16, BB), 256>>>();
    k_sconv<<<dim3(16, BB), 256>>>(s_cw, s_cb, s_bs, s_bb, s_bm, s_bv);
    k_rowsoftmax<<<BB * 64, 64>>>();
    k_spatial<<<dim3(64, BB), 256>>>(x);
    // final bf16 wmma GEMM (3-stage cp.async pipeline) + fused epilogue
    k_attn_out<<<dim3(32, 2, BB), 256, 3 * K6_STAGE>>>(x, gamma, out);
    (void)in_sizes; (void)n_in; (void)out_size;
}

// round 16
// speedup vs baseline: 2.7914x; 1.0544x over previous
#include <cuda_runtime.h>
#include <cuda_bf16.h>
#include <mma.h>
#include <math.h>
#include <stdint.h>

using namespace nvcuda;

// Shapes (fixed): B=4, C=256, H=W=64, HW=4096, C8=32, C2=128
#define BB 4
#define CC 256
#define HW 4096
#define C8 32
#define C2 128

// ---------------- device scratch (allocation-free) ----------------
__device__ float g_q[BB * C8 * HW];                      // 2 MB
__device__ float g_k[BB * C8 * HW];                      // 2 MB
__device__ __nv_bfloat16 g_vh[BB * CC * HW];             // 8 MB  (v in bf16)
__device__ float g_v2[BB * CC * HW];                     // 16 MB
__device__ float g_spA[BB * CC * HW];                    // 16 MB
__device__ float g_aff[(size_t)BB * HW * HW];            // 268 MB (logits, fp32)
__device__ __nv_bfloat16 g_affh[(size_t)BB * HW * HW];   // 134 MB (softmax out, bf16)
__device__ float g_wt[256 * 9 * 64];                     // transposed q/k conv weights
__device__ float g_part[4 * BB * 64 * HW];               // 16 MB conv partial sums
__device__ float g_gate[BB * CC];
__device__ float g_cmean[BB * CC];
__device__ float g_cmax[BB * CC];
__device__ float g_sm[BB * 2 * HW];
__device__ float g_att[BB * HW];
__device__ float g_a[BB * 64 * 64];

__device__ __forceinline__ uint32_t smem_to_u32(const void* p) {
    uint32_t a;
    asm("{ .reg .u64 t; cvta.to.shared.u64 t, %1; cvt.u32.u64 %0, t; }" : "=r"(a) : "l"(p));
    return a;
}
#define CP_ASYNC_16(dst_u32, src_ptr) \
    asm volatile("cp.async.cg.shared.global [%0], [%1], 16;" :: "r"(dst_u32), "l"(src_ptr))
#define CP_ASYNC_COMMIT() asm volatile("cp.async.commit_group;" ::: "memory")
#define CP_ASYNC_WAIT_1() asm volatile("cp.async.wait_group 1;" ::: "memory")
#define CP_ASYNC_WAIT_0() asm volatile("cp.async.wait_group 0;" ::: "memory")

// ---------------- K0: transpose conv weights to [ic][tap][64oc] ----------------
__global__ void k_wt(const float* __restrict__ qw, const float* __restrict__ kw) {
    int i = blockIdx.x * blockDim.x + threadIdx.x;
    if (i >= 256 * 9 * 32) return;
    int oc = i % 32;
    int t  = (i / 32) % 9;
    int ic = i / (32 * 9);
    g_wt[(ic * 9 + t) * 64 + oc]      = qw[(oc * 256 + ic) * 9 + t];
    g_wt[(ic * 9 + t) * 64 + 32 + oc] = kw[(oc * 256 + ic) * 9 + t];
}

// ---------------- K1: q/k conv3x3 partial sums (4-way ic split) ----------------
__global__ __launch_bounds__(128) void k_qkconv(const float* __restrict__ x)
{
    __shared__ float xt[10][18];
    __shared__ float wsm[576];
    int bz = blockIdx.z;
    int b  = bz >> 2;
    int s  = bz & 3;
    int ic0 = s * 64;
    int th = blockIdx.y;
    int tw = blockIdx.x;
    int tx = threadIdx.x, ty = threadIdx.y;
    int tid = ty * 16 + tx;

    float acc[64];
#pragma unroll
    for (int i = 0; i < 64; i++) acc[i] = 0.f;

    const float* xb = x + (size_t)b * CC * HW;

    for (int ic = ic0; ic < ic0 + 64; ic++) {
        for (int i = tid; i < 180; i += 128) {
            int r = i / 18, c = i % 18;
            int gh = th * 8 + r - 1, gw = tw * 16 + c - 1;
            float v = 0.f;
            if (gh >= 0 && gh < 64 && gw >= 0 && gw < 64)
                v = xb[ic * HW + gh * 64 + gw];
            xt[r][c] = v;
        }
        for (int i = tid; i < 144; i += 128)
            ((float4*)wsm)[i] = ((const float4*)(g_wt + ic * 576))[i];
        __syncthreads();

        float xv[9];
#pragma unroll
        for (int dy = 0; dy < 3; dy++)
#pragma unroll
            for (int dx = 0; dx < 3; dx++)
                xv[dy * 3 + dx] = xt[ty + dy][tx + dx];

#pragma unroll
        for (int t = 0; t < 9; t++) {
            float xvt = xv[t];
            const float4* wrow = (const float4*)(wsm + t * 64);
#pragma unroll
            for (int o4 = 0; o4 < 16; o4++) {
                float4 wv = wrow[o4];
                acc[o4 * 4 + 0] += xvt * wv.x;
                acc[o4 * 4 + 1] += xvt * wv.y;
                acc[o4 * 4 + 2] += xvt * wv.z;
                acc[o4 * 4 + 3] += xvt * wv.w;
            }
        }
        __syncthreads();
    }

    int h = th * 8 + ty, w = tw * 16 + tx;
    int p = h * 64 + w;
    float* pp = g_part + ((size_t)(s * BB + b) * 64) * HW + p;
#pragma unroll
    for (int oc = 0; oc < 64; oc++)
        pp[(size_t)oc * HW] = acc[oc];
}

// ---------------- K1b: sum partials + BN + ReLU -> g_q / g_k ----------------
__global__ __launch_bounds__(256) void k_qkbn(
    const float* __restrict__ qb, const float* __restrict__ qs,
    const float* __restrict__ qbb, const float* __restrict__ qm, const float* __restrict__ qv,
    const float* __restrict__ kb, const float* __restrict__ ks_,
    const float* __restrict__ kbb, const float* __restrict__ km, const float* __restrict__ kv)
{
    int oc = blockIdx.y;   // 0..63
    int b  = blockIdx.z;
    int p  = blockIdx.x * 256 + threadIdx.x;
    size_t off = ((size_t)b * 64 + oc) * HW + p;
    float acc = g_part[off] + g_part[(size_t)BB * 64 * HW + off]
              + g_part[(size_t)2 * BB * 64 * HW + off]
              + g_part[(size_t)3 * BB * 64 * HW + off];
    if (oc < 32) {
        float A  = rsqrtf(qv[oc] + 1e-5f) * qs[oc];
        float Bc = (qb[oc] - qm[oc]) * A + qbb[oc];
        g_q[((size_t)b * 32 + oc) * HW + p] = fmaxf(acc * A + Bc, 0.f);
    } else {
        int o = oc - 32;
        float A  = rsqrtf(kv[o] + 1e-5f) * ks_[o];
        float Bc = (kb[o] - km[o]) * A + kbb[o];
        g_k[((size_t)b * 32 + o) * HW + p] = fmaxf(acc * A + Bc, 0.f);
    }
}

// ---------------- K2 (tf32 wmma): S[b][n][m] = sum_c q[b][c][n] * k[b][c][m] --------
// 2 blocks/SM via reg cap; C staged in smem union for coalesced float4 stores.
#define K2_LD 132
__global__ void __launch_bounds__(256, 2) k_qk_gemm() {
    extern __shared__ __align__(16) char k2raw[];
    float* Qs = (float*)k2raw;                       // [32][132]
    float* Ks = (float*)k2raw + 32 * K2_LD;          // [32][132]
    float* Cs = (float*)k2raw;                       // [128][132] (union, post-mma)

    int b  = blockIdx.z;
    int n0 = blockIdx.y * 128;
    int m0 = blockIdx.x * 128;
    int tid = threadIdx.x;
    const float* qbp = g_q + (size_t)b * C8 * HW;
    const float* kbp = g_k + (size_t)b * C8 * HW;

#pragma unroll
    for (int i = tid; i < 1024; i += 256) {
        int r = i / 32, q4 = i % 32;
        float4 qv = *(const float4*)&qbp[r * HW + n0 + q4 * 4];
        float4 kv = *(const float4*)&kbp[r * HW + m0 + q4 * 4];
        qv.x = wmma::__float_to_tf32(qv.x); qv.y = wmma::__float_to_tf32(qv.y);
        qv.z = wmma::__float_to_tf32(qv.z); qv.w = wmma::__float_to_tf32(qv.w);
        kv.x = wmma::__float_to_tf32(kv.x); kv.y = wmma::__float_to_tf32(kv.y);
        kv.z = wmma::__float_to_tf32(kv.z); kv.w = wmma::__float_to_tf32(kv.w);
        *(float4*)&Qs[r * K2_LD + q4 * 4] = qv;
        *(float4*)&Ks[r * K2_LD + q4 * 4] = kv;
    }
    __syncthreads();

    int wid = tid / 32;
    int wn = wid % 2;
    int wm = wid / 2;

    wmma::fragment<wmma::accumulator, 16, 16, 8, float> acc[4][2];
#pragma unroll
    for (int i = 0; i < 4; i++)
#pragma unroll
        for (int j = 0; j < 2; j++) wmma::fill_fragment(acc[i][j], 0.f);

#pragma unroll
    for (int kk = 0; kk < 32; kk += 8) {
        wmma::fragment<wmma::matrix_a, 16, 16, 8, wmma::precision::tf32, wmma::col_major> af[4];
        wmma::fragment<wmma::matrix_b, 16, 16, 8, wmma::precision::tf32, wmma::row_major> bf[2];
#pragma unroll
        for (int i = 0; i < 4; i++)
            wmma::load_matrix_sync(af[i], &Qs[kk * K2_LD + wn * 64 + i * 16], K2_LD);
#pragma unroll
        for (int j = 0; j < 2; j++)
            wmma::load_matrix_sync(bf[j], &Ks[kk * K2_LD + wm * 32 + j * 16], K2_LD);
#pragma unroll
        for (int i = 0; i < 4; i++)
#pragma unroll
            for (int j = 0; j < 2; j++)
                wmma::mma_sync(acc[i][j], af[i], bf[j], acc[i][j]);
    }
    __syncthreads();   // all mma reads of Qs/Ks done before Cs overwrites them

#pragma unroll
    for (int i = 0; i < 4; i++)
#pragma unroll
        for (int j = 0; j < 2; j++)
            wmma::store_matrix_sync(&Cs[(wn * 64 + i * 16) * K2_LD + wm * 32 + j * 16],
                                    acc[i][j], K2_LD, wmma::mem_row_major);
    __syncthreads();

    // coalesced write: 128 rows x 128 floats = 4096 float4 (16/thread)
    float* outp = g_aff + (size_t)b * HW * HW;
#pragma unroll
    for (int i = tid; i < 4096; i += 256) {
        int r = i / 32, q = i % 32;
        *(float4*)&outp[(size_t)(n0 + r) * HW + m0 + q * 4] = *(float4*)&Cs[r * K2_LD + q * 4];
    }
}

// ---------------- K3: row softmax of aff (rows of 4096), fp32 in -> bf16 out ----------------
__global__ __launch_bounds__(256) void k_softmax() {
    size_t row = blockIdx.x;
    const float* p = g_aff + row * HW;
    __nv_bfloat162* ph = (__nv_bfloat162*)(g_affh + row * HW);
    int tid = threadIdx.x;
    __shared__ float red[256];

    float4 v[4];
#pragma unroll
    for (int i = 0; i < 4; i++) v[i] = ((const float4*)p)[i * 256 + tid];

    float mx = -INFINITY;
#pragma unroll
    for (int i = 0; i < 4; i++) {
        mx = fmaxf(mx, fmaxf(fmaxf(v[i].x, v[i].y), fmaxf(v[i].z, v[i].w)));
    }
    red[tid] = mx; __syncthreads();
    for (int s = 128; s > 0; s >>= 1) {
        if (tid < s) red[tid] = fmaxf(red[tid], red[tid + s]);
        __syncthreads();
    }
    mx = red[0]; __syncthreads();

    float sum = 0.f;
#pragma unroll
    for (int i = 0; i < 4; i++) {
        v[i].x = expf(v[i].x - mx); v[i].y = expf(v[i].y - mx);
        v[i].z = expf(v[i].z - mx); v[i].w = expf(v[i].w - mx);
        sum += v[i].x + v[i].y + v[i].z + v[i].w;
    }
    red[tid] = sum; __syncthreads();
    for (int s = 128; s > 0; s >>= 1) {
        if (tid < s) red[tid] += red[tid + s];
        __syncthreads();
    }
    float inv = 1.f / red[0];
#pragma unroll
    for (int i = 0; i < 4; i++) {
        int idx = i * 512 + tid * 2;
        ph[idx]     = __floats2bfloat162_rn(v[i].x * inv, v[i].y * inv);
        ph[idx + 1] = __floats2bfloat162_rn(v[i].z * inv, v[i].w * inv);
    }
}

// ---------------- K4 (bf16 wmma, fused): [v ; v2] = [v_w ; s_vw] @ x + bias ----------
// bf16 operands (rounded at smem staging), fp32 accumulate; v path already consumed
// as bf16 so input-rounding is the same error scale.
#define K4_LDA 40    // bf16 elems per A row (32 used)
#define K4_LDB 136   // bf16 elems per B row (128 used)
#define K4_LDC 132   // fp32 elems per C row
__global__ __launch_bounds__(256) void k_1x1_fused(
    const float* __restrict__ vw, const float* __restrict__ vb,
    const float* __restrict__ sw, const float* __restrict__ sb,
    const float* __restrict__ x)
{
    __shared__ __align__(32) char smemraw[64 * K4_LDC * 4];  // 33792B union
    __nv_bfloat16* As = (__nv_bfloat16*)smemraw;                       // [64][40]
    __nv_bfloat16* Bs = (__nv_bfloat16*)(smemraw + 64 * K4_LDA * 2);   // [32][136]
    float* Cs = (float*)smemraw;                                       // [64][132]

    int b  = blockIdx.z;
    int m0 = blockIdx.y * 64;
    int n0 = blockIdx.x * 128;
    int tid = threadIdx.x;
    int wid = tid / 32;
    int wm = wid % 2;
    int wn = wid / 2;

    bool vhalf = (m0 < 256);
    const float* W  = vhalf ? (vw + m0 * 256) : (sw + (m0 - 256) * 256);
    const float* bi = vhalf ? (vb + m0) : (sb + (m0 - 256));
    const float* xb = x + (size_t)b * CC * HW;

    wmma::fragment<wmma::accumulator, 16, 16, 16, float> acc[2][2];
#pragma unroll
    for (int i = 0; i < 2; i++)
#pragma unroll
        for (int j = 0; j < 2; j++) wmma::fill_fragment(acc[i][j], 0.f);

    for (int k0 = 0; k0 < 256; k0 += 32) {
        // As: 64 rows x 32 k (512 float4 sources, 2/thread)
#pragma unroll
        for (int i = tid; i < 512; i += 256) {
            int r = i / 8, q = i % 8;
            float4 wv = *(const float4*)&W[r * 256 + k0 + q * 4];
            __nv_bfloat162* d = (__nv_bfloat162*)&As[r * K4_LDA + q * 4];
            d[0] = __floats2bfloat162_rn(wv.x, wv.y);
            d[1] = __floats2bfloat162_rn(wv.z, wv.w);
        }
        // Bs: 32 rows x 128 n (1024 float4 sources, 4/thread)
#pragma unroll
        for (int i = tid; i < 1024; i += 256) {
            int r = i / 32, q = i % 32;
            float4 xv = *(const float4*)&xb[(size_t)(k0 + r) * HW + n0 + q * 4];
            __nv_bfloat162* d = (__nv_bfloat162*)&Bs[r * K4_LDB + q * 4];
            d[0] = __floats2bfloat162_rn(xv.x, xv.y);
            d[1] = __floats2bfloat162_rn(xv.z, xv.w);
        }
        __syncthreads();

#pragma unroll
        for (int kk = 0; kk < 32; kk += 16) {
            wmma::fragment<wmma::matrix_a, 16, 16, 16, __nv_bfloat16, wmma::row_major> af[2];
            wmma::fragment<wmma::matrix_b, 16, 16, 16, __nv_bfloat16, wmma::row_major> bf[2];
#pragma unroll
            for (int i = 0; i < 2; i++)
                wmma::load_matrix_sync(af[i], &As[(wm * 32 + i * 16) * K4_LDA + kk], K4_LDA);
#pragma unroll
            for (int j = 0; j < 2; j++)
                wmma::load_matrix_sync(bf[j], &Bs[kk * K4_LDB + wn * 32 + j * 16], K4_LDB);
#pragma unroll
            for (int i = 0; i < 2; i++)
#pragma unroll
                for (int j = 0; j < 2; j++)
                    wmma::mma_sync(acc[i][j], af[i], bf[j], acc[i][j]);
        }
        __syncthreads();
    }

#pragma unroll
    for (int i = 0; i < 2; i++)
#pragma unroll
        for (int j = 0; j < 2; j++)
            wmma::store_matrix_sync(&Cs[(wm * 32 + i * 16) * K4_LDC + wn * 32 + j * 16],
                                    acc[i][j], K4_LDC, wmma::mem_row_major);
    __syncthreads();

    if (vhalf) {
        __nv_bfloat16* ob = g_vh + (size_t)b * CC * HW;
#pragma unroll
        for (int i = tid; i < 2048; i += 256) {
            int r = i / 32, q = i % 32;
            float bo = bi[r];
            float4 c4 = *(const float4*)&Cs[r * K4_LDC + q * 4];
            __nv_bfloat162* d = (__nv_bfloat162*)&ob[(size_t)(m0 + r) * HW + n0 + q * 4];
            d[0] = __floats2bfloat162_rn(c4.x + bo, c4.y + bo);
            d[1] = __floats2bfloat162_rn(c4.z + bo, c4.w + bo);
        }
    } else {
        float* ob = g_v2 + (size_t)b * CC * HW;
#pragma unroll
        for (int i = tid; i < 2048; i += 256) {
            int r = i / 32, q = i % 32;
            float bo = bi[r];
            float4 c4 = *(const float4*)&Cs[r * K4_LDC + q * 4];
            float4 o = make_float4(c4.x + bo, c4.y + bo, c4.z + bo, c4.w + bo);
            *(float4*)&ob[(size_t)(m0 - 256 + r) * HW + n0 + q * 4] = o;
        }
    }
}

// ---------------- channel stats ----------------
__global__ __launch_bounds__(256) void k_chanstats(const float* __restrict__ x) {
    int bc = blockIdx.x;
    const float* p = x + (size_t)bc * HW;
    int tid = threadIdx.x;
    float s = 0.f, m = -INFINITY;
#pragma unroll
    for (int i = 0; i < 4; i++) {
        float4 v = ((const float4*)p)[i * 256 + tid];
        s += v.x + v.y + v.z + v.w;
        m = fmaxf(m, fmaxf(fmaxf(v.x, v.y), fmaxf(v.z, v.w)));
    }
    __shared__ float rs[256], rm[256];
    rs[tid] = s; rm[tid] = m; __syncthreads();
    for (int st = 128; st > 0; st >>= 1) {
        if (tid < st) { rs[tid] += rs[tid + st]; rm[tid] = fmaxf(rm[tid], rm[tid + st]); }
        __syncthreads();
    }
    if (tid == 0) { g_cmean[bc] = rs[0] * (1.f / 4096.f); g_cmax[bc] = rm[0]; }
}

// ---------------- channel gate FC ----------------
__global__ __launch_bounds__(256) void k_gate(
    const float* __restrict__ cw1, const float* __restrict__ cb1,
    const float* __restrict__ cw2, const float* __restrict__ cb2)
{
    int b = blockIdx.x;
    __shared__ float hsum[128];
    __shared__ float sme[256], sma[256];
    int tid = threadIdx.x;
    sme[tid] = g_cmean[b * 256 + tid];
    sma[tid] = g_cmax[b * 256 + tid];
    __syncthreads();
    if (tid < 128) {
        float am = cb1[tid], ax = cb1[tid];
        const float* wr = cw1 + tid * 256;
        for (int c = 0; c < 256; c++) { float w = wr[c]; am += w * sme[c]; ax += w * sma[c]; }
        hsum[tid] = fmaxf(am, 0.f) + fmaxf(ax, 0.f);
    }
    __syncthreads();
    float o = 2.f * cb2[tid];
    const float* wr = cw2 + tid * 128;
    for (int j = 0; j < 128; j++) o += wr[j] * hsum[j];
    g_gate[b * 256 + tid] = 1.f / (1.f + expf(-o));
}

// ---------------- v2 channel max/mean per pixel ----------------
__global__ __launch_bounds__(256) void k_smreduce() {
    int b = blockIdx.y;
    int p = blockIdx.x * 256 + threadIdx.x;
    const float* v2 = g_v2 + (size_t)b * CC * HW + p;
    float mx = -INFINITY, s = 0.f;
    for (int c = 0; c < 256; c++) {
        float v = v2[(size_t)c * HW];
        mx = fmaxf(mx, v); s += v;
    }
    g_sm[b * 8192 + p] = mx;
    g_sm[b * 8192 + 4096 + p] = s * (1.f / 256.f);
}

// ---------------- spatial conv 3x3 (2->1) + BN ----------------
__global__ __launch_bounds__(256) void k_sconv(
    const float* __restrict__ scw, const float* __restrict__ scb,
    const float* __restrict__ bs, const float* __restrict__ bbi,
    const float* __restrict__ bm, const float* __restrict__ bv)
{
    int b = blockIdx.y;
    int p = blockIdx.x * 256 + threadIdx.x;
    int h = p / 64, w = p % 64;
    float acc = 0.f;
    const float* smb = g_sm + b * 8192;
    for (int ci = 0; ci < 2; ci++)
#pragma unroll
        for (int dy = 0; dy < 3; dy++)
#pragma unroll
            for (int dx = 0; dx < 3; dx++) {
                int hh = h + dy - 1, ww = w + dx - 1;
                if (hh >= 0 && hh < 64 && ww >= 0 && ww < 64)
                    acc += scw[ci * 9 + dy * 3 + dx] * smb[ci * 4096 + hh * 64 + ww];
            }
    float A = rsqrtf(bv[0] + 1e-5f) * bs[0];
    g_att[b * 4096 + p] = (acc + scb[0] - bm[0]) * A + bbi[0];
}

// ---------------- softmax over W (rows of 64) -> g_a ----------------
__global__ __launch_bounds__(64) void k_rowsoftmax() {
    int row = blockIdx.x;
    int tid = threadIdx.x;
    float v = g_att[row * 64 + tid];
    __shared__ float red[64];
    red[tid] = v; __syncthreads();
    for (int s = 32; s > 0; s >>= 1) {
        if (tid < s) red[tid] = fmaxf(red[tid], red[tid + s]);
        __syncthreads();
    }
    float mx = red[0]; __syncthreads();
    float e = expf(v - mx);
    red[tid] = e; __syncthreads();
    for (int s = 32; s > 0; s >>= 1) {
        if (tid < s) red[tid] += red[tid + s];
        __syncthreads();
    }
    g_a[row * 64 + tid] = e / red[0];
}

// ---------------- spatialA[b,c,h,k] = sum_w x[b,c,h,w] * a[b,w,k] ----------------
__global__ __launch_bounds__(256) void k_spatial(const float* __restrict__ x) {
    int b = blockIdx.y, h = blockIdx.x;
    __shared__ float a_s[64 * 64];
    __shared__ float xs[4][64];
    int tid = threadIdx.x;
    for (int i = tid; i < 4096; i += 256) a_s[i] = g_a[b * 4096 + i];
    int cg = tid / 64, k = tid % 64;
    const float* xb = x + (size_t)b * CC * HW + h * 64;
    float* ob = g_spA + (size_t)b * CC * HW + h * 64;
    for (int c0 = 0; c0 < 256; c0 += 4) {
        __syncthreads();
        xs[cg][k] = xb[(size_t)(c0 + cg) * HW + k];
        __syncthreads();
        float acc = 0.f;
#pragma unroll 8
        for (int w = 0; w < 64; w++) acc += xs[cg][w] * a_s[w * 64 + k];
        ob[(size_t)(c0 + cg) * HW + k] = acc;
    }
}

// ---------------- K6 (bf16 wmma + cp.async 3-stage): out = gamma*(v@aff^T)+x*(1+gate)+spA
#define K6_LDS 72
#define K6_STAGE 36864
#define K6_LDC 132
__global__ void __launch_bounds__(256, 2) k_attn_out(
    const float* __restrict__ x, const float* __restrict__ gamma, float* __restrict__ out)
{
    extern __shared__ __align__(16) char dsm[];
    uint32_t smem_u32 = smem_to_u32(dsm);

    int b  = blockIdx.z;
    int c0 = blockIdx.y * 128;
    int n0 = blockIdx.x * 128;
    int tid = threadIdx.x;
    int wid = tid / 32;
    int wr = wid / 4;   // 0..1  c-direction (64 rows each)
    int wc = wid % 4;   // 0..3  n-direction (32 cols each)

    const __nv_bfloat16* vb = g_vh + (size_t)b * CC * HW + (size_t)c0 * HW;
    const __nv_bfloat16* ab = g_affh + (size_t)b * HW * HW + (size_t)n0 * HW;

    int r_[4], q_[4];
#pragma unroll
    for (int t = 0; t < 4; t++) {
        int idx = t * 256 + tid;
        r_[t] = idx >> 3;
        q_[t] = idx & 7;
    }

    auto stage = [&](int ck) {
        uint32_t base = smem_u32 + (ck % 3) * K6_STAGE;
        int m0 = ck * 64;
#pragma unroll
        for (int t = 0; t < 4; t++) {
            uint32_t off = (uint32_t)(r_[t] * K6_LDS + q_[t] * 8) * 2;
            CP_ASYNC_16(base + off, (const void*)&vb[(size_t)r_[t] * HW + m0 + q_[t] * 8]);
            CP_ASYNC_16(base + 18432 + off, (const void*)&ab[(size_t)r_[t] * HW + m0 + q_[t] * 8]);
        }
        CP_ASYNC_COMMIT();
    };

    wmma::fragment<wmma::accumulator, 16, 16, 16, float> acc[4][2];
#pragma unroll
    for (int i = 0; i < 4; i++)
#pragma unroll
        for (int j = 0; j < 2; j++) wmma::fill_fragment(acc[i][j], 0.f);

    stage(0);
    stage(1);

    for (int ck = 0; ck < 64; ck++) {
        if (ck < 63) CP_ASYNC_WAIT_1();
        else         CP_ASYNC_WAIT_0();
        __syncthreads();
        if (ck + 2 < 64) stage(ck + 2);

        const __nv_bfloat16* As = (const __nv_bfloat16*)(dsm + (ck % 3) * K6_STAGE);
        const __nv_bfloat16* Bs = (const __nv_bfloat16*)(dsm + (ck % 3) * K6_STAGE + 18432);

#pragma unroll
        for (int kk = 0; kk < 64; kk += 16) {
            wmma::fragment<wmma::matrix_a, 16, 16, 16, __nv_bfloat16, wmma::row_major> af[4];
            wmma::fragment<wmma::matrix_b, 16, 16, 16, __nv_bfloat16, wmma::col_major> bf[2];
#pragma unroll
            for (int i = 0; i < 4; i++)
                wmma::load_matrix_sync(af[i], &As[(wr * 64 + i * 16) * K6_LDS + kk], K6_LDS);
#pragma unroll
            for (int j = 0; j < 2; j++)
                wmma::load_matrix_sync(bf[j], &Bs[(wc * 32 + j * 16) * K6_LDS + kk], K6_LDS);
#pragma unroll
            for (int i = 0; i < 4; i++)
#pragma unroll
                for (int j = 0; j < 2; j++)
                    wmma::mma_sync(acc[i][j], af[i], bf[j], acc[i][j]);
        }
    }
    __syncthreads();

    float* Cs = (float*)dsm;
#pragma unroll
    for (int i = 0; i < 4; i++)
#pragma unroll
        for (int j = 0; j < 2; j++)
            wmma::store_matrix_sync(&Cs[(wr * 64 + i * 16) * K6_LDC + wc * 32 + j * 16],
                                    acc[i][j], K6_LDC, wmma::mem_row_major);
    __syncthreads();

    float g = gamma[0];
    const float* xb = x + (size_t)b * CC * HW;
    const float* sb = g_spA + (size_t)b * CC * HW;
#pragma unroll
    for (int i = tid; i < 4096; i += 256) {
        int r = i / 32, q = i % 32;
        int c = c0 + r;
        int nn = n0 + q * 4;
        float gt = 1.f + g_gate[b * 256 + c];
        float4 w4 = *(const float4*)&Cs[r * K6_LDC + q * 4];
        float4 xv = *(const float4*)&xb[(size_t)c * HW + nn];
        float4 sv = *(const float4*)&sb[(size_t)c * HW + nn];
        float4 o;
        o.x = g * w4.x + xv.x * gt + sv.x;
        o.y = g * w4.y + xv.y * gt + sv.y;
        o.z = g * w4.z + xv.z * gt + sv.z;
        o.w = g * w4.w + xv.w * gt + sv.w;
        *(float4*)&out[((size_t)b * CC + c) * HW + nn] = o;
    }
}

// ---------------- launch ----------------
extern "C" void kernel_launch(void* const* d_in, const int* in_sizes, int n_in,
                              void* d_out, int out_size) {
    const float* x     = (const float*)d_in[0];
    const float* q_w   = (const float*)d_in[1];
    const float* q_b   = (const float*)d_in[2];
    const float* q_bs  = (const float*)d_in[3];
    const float* q_bb  = (const float*)d_in[4];
    const float* q_bm  = (const float*)d_in[5];
    const float* q_bv  = (const float*)d_in[6];
    const float* k_w   = (const float*)d_in[7];
    const float* k_b   = (const float*)d_in[8];
    const float* k_bs  = (const float*)d_in[9];
    const float* k_bb  = (const float*)d_in[10];
    const float* k_bm  = (const float*)d_in[11];
    const float* k_bv  = (const float*)d_in[12];
    const float* v_w   = (const float*)d_in[13];
    const float* v_b   = (const float*)d_in[14];
    const float* gamma = (const float*)d_in[15];
    const float* c_w1  = (const float*)d_in[16];
    const float* c_b1  = (const float*)d_in[17];
    const float* c_w2  = (const float*)d_in[18];
    const float* c_b2  = (const float*)d_in[19];
    const float* s_vw  = (const float*)d_in[20];
    const float* s_vb  = (const float*)d_in[21];
    const float* s_cw  = (const float*)d_in[22];
    const float* s_cb  = (const float*)d_in[23];
    const float* s_bs  = (const float*)d_in[24];
    const float* s_bb  = (const float*)d_in[25];
    const float* s_bm  = (const float*)d_in[26];
    const float* s_bv  = (const float*)d_in[27];
    float* out = (float*)d_out;

    static bool attr_set = false;
    if (!attr_set) {
        cudaFuncSetAttribute(k_attn_out, cudaFuncAttributeMaxDynamicSharedMemorySize,
                             3 * K6_STAGE);
        cudaFuncSetAttribute(k_qk_gemm, cudaFuncAttributeMaxDynamicSharedMemorySize,
                             128 * K2_LD * 4);
        attr_set = true;
    }

    k_wt<<<288, 256>>>(q_w, k_w);
    k_qkconv<<<dim3(4, 8, BB * 4), dim3(16, 8)>>>(x);
    k_qkbn<<<dim3(16, 64, BB), 256>>>(q_b, q_bs, q_bb, q_bm, q_bv,
                                      k_b, k_bs, k_bb, k_bm, k_bv);
    // S = q^T k (tf32, 2 blocks/SM, coalesced store via smem)
    k_qk_gemm<<<dim3(32, 32, BB), 256, 128 * K2_LD * 4>>>();
    k_softmax<<<BB * HW, 256>>>();
    // fused v (bf16) + v2 (fp32) 1x1 convs on bf16 tensor path
    k_1x1_fused<<<dim3(32, 8, BB), 256>>>(v_w, v_b, s_vw, s_vb, x);
    k_chanstats<<<BB * CC, 256>>>(x);
    k_gate<<<BB, 256>>>(c_w1, c_b1, c_w2, c_b2);
    k_smreduce<<<dim3(16, BB), 256>>>();
    k_sconv<<<dim3(16, BB), 256>>>(s_cw, s_cb, s_bs, s_bb, s_bm, s_bv);
    k_rowsoftmax<<<BB * 64, 64>>>();
    k_spatial<<<dim3(64, BB), 256>>>(x);
    k_attn_out<<<dim3(32, 2, BB), 256, 3 * K6_STAGE>>>(x, gamma, out);
    (void)in_sizes; (void)n_in; (void)out_size;
}

// round 17
// speedup vs baseline: 2.7969x; 1.0020x over previous
#include <cuda_runtime.h>
#include <cuda_bf16.h>
#include <mma.h>
#include <math.h>
#include <stdint.h>

using namespace nvcuda;

// Shapes (fixed): B=4, C=256, H=W=64, HW=4096, C8=32, C2=128
#define BB 4
#define CC 256
#define HW 4096
#define C8 32
#define C2 128

// ---------------- device scratch (allocation-free) ----------------
__device__ float g_q[BB * C8 * HW];                      // 2 MB
__device__ float g_k[BB * C8 * HW];                      // 2 MB
__device__ __nv_bfloat16 g_vh[BB * CC * HW];             // 8 MB  (v in bf16)
__device__ float g_v2[BB * CC * HW];                     // 16 MB
__device__ float g_spA[BB * CC * HW];                    // 16 MB
__device__ float g_aff[(size_t)BB * HW * HW];            // 268 MB (logits, fp32)
__device__ __nv_bfloat16 g_affh[(size_t)BB * HW * HW];   // 134 MB (softmax out, bf16)
__device__ float g_wt[256 * 9 * 64];                     // transposed q/k conv weights
__device__ float g_part[4 * BB * 64 * HW];               // 16 MB conv partial sums
__device__ float g_gate[BB * CC];
__device__ float g_cmean[BB * CC];
__device__ float g_cmax[BB * CC];
__device__ float g_sm[BB * 2 * HW];
__device__ float g_att[BB * HW];
__device__ float g_a[BB * 64 * 64];

__device__ __forceinline__ uint32_t smem_to_u32(const void* p) {
    uint32_t a;
    asm("{ .reg .u64 t; cvta.to.shared.u64 t, %1; cvt.u32.u64 %0, t; }" : "=r"(a) : "l"(p));
    return a;
}
#define CP_ASYNC_16(dst_u32, src_ptr) \
    asm volatile("cp.async.cg.shared.global [%0], [%1], 16;" :: "r"(dst_u32), "l"(src_ptr))
#define CP_ASYNC_COMMIT() asm volatile("cp.async.commit_group;" ::: "memory")
#define CP_ASYNC_WAIT_1() asm volatile("cp.async.wait_group 1;" ::: "memory")
#define CP_ASYNC_WAIT_0() asm volatile("cp.async.wait_group 0;" ::: "memory")

// ---------------- K0: transpose conv weights to [ic][tap][64oc] ----------------
__global__ void k_wt(const float* __restrict__ qw, const float* __restrict__ kw) {
    int i = blockIdx.x * blockDim.x + threadIdx.x;
    if (i >= 256 * 9 * 32) return;
    int oc = i % 32;
    int t  = (i / 32) % 9;
    int ic = i / (32 * 9);
    g_wt[(ic * 9 + t) * 64 + oc]      = qw[(oc * 256 + ic) * 9 + t];
    g_wt[(ic * 9 + t) * 64 + 32 + oc] = kw[(oc * 256 + ic) * 9 + t];
}

// ---------------- K1: q/k conv3x3 partial sums (4-way ic split) ----------------
__global__ __launch_bounds__(128) void k_qkconv(const float* __restrict__ x)
{
    __shared__ float xt[10][18];
    __shared__ float wsm[576];
    int bz = blockIdx.z;
    int b  = bz >> 2;
    int s  = bz & 3;
    int ic0 = s * 64;
    int th = blockIdx.y;
    int tw = blockIdx.x;
    int tx = threadIdx.x, ty = threadIdx.y;
    int tid = ty * 16 + tx;

    float acc[64];
#pragma unroll
    for (int i = 0; i < 64; i++) acc[i] = 0.f;

    const float* xb = x + (size_t)b * CC * HW;

    for (int ic = ic0; ic < ic0 + 64; ic++) {
        for (int i = tid; i < 180; i += 128) {
            int r = i / 18, c = i % 18;
            int gh = th * 8 + r - 1, gw = tw * 16 + c - 1;
            float v = 0.f;
            if (gh >= 0 && gh < 64 && gw >= 0 && gw < 64)
                v = xb[ic * HW + gh * 64 + gw];
            xt[r][c] = v;
        }
        for (int i = tid; i < 144; i += 128)
            ((float4*)wsm)[i] = ((const float4*)(g_wt + ic * 576))[i];
        __syncthreads();

        float xv[9];
#pragma unroll
        for (int dy = 0; dy < 3; dy++)
#pragma unroll
            for (int dx = 0; dx < 3; dx++)
                xv[dy * 3 + dx] = xt[ty + dy][tx + dx];

#pragma unroll
        for (int t = 0; t < 9; t++) {
            float xvt = xv[t];
            const float4* wrow = (const float4*)(wsm + t * 64);
#pragma unroll
            for (int o4 = 0; o4 < 16; o4++) {
                float4 wv = wrow[o4];
                acc[o4 * 4 + 0] += xvt * wv.x;
                acc[o4 * 4 + 1] += xvt * wv.y;
                acc[o4 * 4 + 2] += xvt * wv.z;
                acc[o4 * 4 + 3] += xvt * wv.w;
            }
        }
        __syncthreads();
    }

    int h = th * 8 + ty, w = tw * 16 + tx;
    int p = h * 64 + w;
    float* pp = g_part + ((size_t)(s * BB + b) * 64) * HW + p;
#pragma unroll
    for (int oc = 0; oc < 64; oc++)
        pp[(size_t)oc * HW] = acc[oc];
}

// ---------------- K1b: sum partials + BN + ReLU -> g_q / g_k ----------------
__global__ __launch_bounds__(256) void k_qkbn(
    const float* __restrict__ qb, const float* __restrict__ qs,
    const float* __restrict__ qbb, const float* __restrict__ qm, const float* __restrict__ qv,
    const float* __restrict__ kb, const float* __restrict__ ks_,
    const float* __restrict__ kbb, const float* __restrict__ km, const float* __restrict__ kv)
{
    int oc = blockIdx.y;   // 0..63
    int b  = blockIdx.z;
    int p  = blockIdx.x * 256 + threadIdx.x;
    size_t off = ((size_t)b * 64 + oc) * HW + p;
    float acc = g_part[off] + g_part[(size_t)BB * 64 * HW + off]
              + g_part[(size_t)2 * BB * 64 * HW + off]
              + g_part[(size_t)3 * BB * 64 * HW + off];
    if (oc < 32) {
        float A  = rsqrtf(qv[oc] + 1e-5f) * qs[oc];
        float Bc = (qb[oc] - qm[oc]) * A + qbb[oc];
        g_q[((size_t)b * 32 + oc) * HW + p] = fmaxf(acc * A + Bc, 0.f);
    } else {
        int o = oc - 32;
        float A  = rsqrtf(kv[o] + 1e-5f) * ks_[o];
        float Bc = (kb[o] - km[o]) * A + kbb[o];
        g_k[((size_t)b * 32 + o) * HW + p] = fmaxf(acc * A + Bc, 0.f);
    }
}

// ---------------- K2 (tf32 wmma): S[b][n][m] = sum_c q[b][c][n] * k[b][c][m] --------
// 2 blocks/SM via reg cap; C staged in smem union for coalesced float4 stores.
#define K2_LD 132
__global__ void __launch_bounds__(256, 2) k_qk_gemm() {
    extern __shared__ __align__(16) char k2raw[];
    float* Qs = (float*)k2raw;                       // [32][132]
    float* Ks = (float*)k2raw + 32 * K2_LD;          // [32][132]
    float* Cs = (float*)k2raw;                       // [128][132] (union, post-mma)

    int b  = blockIdx.z;
    int n0 = blockIdx.y * 128;
    int m0 = blockIdx.x * 128;
    int tid = threadIdx.x;
    const float* qbp = g_q + (size_t)b * C8 * HW;
    const float* kbp = g_k + (size_t)b * C8 * HW;

#pragma unroll
    for (int i = tid; i < 1024; i += 256) {
        int r = i / 32, q4 = i % 32;
        float4 qv = *(const float4*)&qbp[r * HW + n0 + q4 * 4];
        float4 kv = *(const float4*)&kbp[r * HW + m0 + q4 * 4];
        qv.x = wmma::__float_to_tf32(qv.x); qv.y = wmma::__float_to_tf32(qv.y);
        qv.z = wmma::__float_to_tf32(qv.z); qv.w = wmma::__float_to_tf32(qv.w);
        kv.x = wmma::__float_to_tf32(kv.x); kv.y = wmma::__float_to_tf32(kv.y);
        kv.z = wmma::__float_to_tf32(kv.z); kv.w = wmma::__float_to_tf32(kv.w);
        *(float4*)&Qs[r * K2_LD + q4 * 4] = qv;
        *(float4*)&Ks[r * K2_LD + q4 * 4] = kv;
    }
    __syncthreads();

    int wid = tid / 32;
    int wn = wid % 2;
    int wm = wid / 2;

    wmma::fragment<wmma::accumulator, 16, 16, 8, float> acc[4][2];
#pragma unroll
    for (int i = 0; i < 4; i++)
#pragma unroll
        for (int j = 0; j < 2; j++) wmma::fill_fragment(acc[i][j], 0.f);

#pragma unroll
    for (int kk = 0; kk < 32; kk += 8) {
        wmma::fragment<wmma::matrix_a, 16, 16, 8, wmma::precision::tf32, wmma::col_major> af[4];
        wmma::fragment<wmma::matrix_b, 16, 16, 8, wmma::precision::tf32, wmma::row_major> bf[2];
#pragma unroll
        for (int i = 0; i < 4; i++)
            wmma::load_matrix_sync(af[i], &Qs[kk * K2_LD + wn * 64 + i * 16], K2_LD);
#pragma unroll
        for (int j = 0; j < 2; j++)
            wmma::load_matrix_sync(bf[j], &Ks[kk * K2_LD + wm * 32 + j * 16], K2_LD);
#pragma unroll
        for (int i = 0; i < 4; i++)
#pragma unroll
            for (int j = 0; j < 2; j++)
                wmma::mma_sync(acc[i][j], af[i], bf[j], acc[i][j]);
    }
    __syncthreads();   // all mma reads of Qs/Ks done before Cs overwrites them

#pragma unroll
    for (int i = 0; i < 4; i++)
#pragma unroll
        for (int j = 0; j < 2; j++)
            wmma::store_matrix_sync(&Cs[(wn * 64 + i * 16) * K2_LD + wm * 32 + j * 16],
                                    acc[i][j], K2_LD, wmma::mem_row_major);
    __syncthreads();

    // coalesced write: 128 rows x 128 floats = 4096 float4 (16/thread)
    float* outp = g_aff + (size_t)b * HW * HW;
#pragma unroll
    for (int i = tid; i < 4096; i += 256) {
        int r = i / 32, q = i % 32;
        *(float4*)&outp[(size_t)(n0 + r) * HW + m0 + q * 4] = *(float4*)&Cs[r * K2_LD + q * 4];
    }
}

// ---------------- K3: row softmax of aff (rows of 4096), fp32 in -> bf16 out ----------------
__global__ __launch_bounds__(256) void k_softmax() {
    size_t row = blockIdx.x;
    const float* p = g_aff + row * HW;
    __nv_bfloat162* ph = (__nv_bfloat162*)(g_affh + row * HW);
    int tid = threadIdx.x;
    __shared__ float red[256];

    float4 v[4];
#pragma unroll
    for (int i = 0; i < 4; i++) v[i] = ((const float4*)p)[i * 256 + tid];

    float mx = -INFINITY;
#pragma unroll
    for (int i = 0; i < 4; i++) {
        mx = fmaxf(mx, fmaxf(fmaxf(v[i].x, v[i].y), fmaxf(v[i].z, v[i].w)));
    }
    red[tid] = mx; __syncthreads();
    for (int s = 128; s > 0; s >>= 1) {
        if (tid < s) red[tid] = fmaxf(red[tid], red[tid + s]);
        __syncthreads();
    }
    mx = red[0]; __syncthreads();

    float sum = 0.f;
#pragma unroll
    for (int i = 0; i < 4; i++) {
        v[i].x = expf(v[i].x - mx); v[i].y = expf(v[i].y - mx);
        v[i].z = expf(v[i].z - mx); v[i].w = expf(v[i].w - mx);
        sum += v[i].x + v[i].y + v[i].z + v[i].w;
    }
    red[tid] = sum; __syncthreads();
    for (int s = 128; s > 0; s >>= 1) {
        if (tid < s) red[tid] += red[tid + s];
        __syncthreads();
    }
    float inv = 1.f / red[0];
#pragma unroll
    for (int i = 0; i < 4; i++) {
        int idx = i * 512 + tid * 2;
        ph[idx]     = __floats2bfloat162_rn(v[i].x * inv, v[i].y * inv);
        ph[idx + 1] = __floats2bfloat162_rn(v[i].z * inv, v[i].w * inv);
    }
}

// ---------------- K4 (bf16 wmma, fused): [v ; v2] = [v_w ; s_vw] @ x + bias ----------
// bf16 operands (rounded at smem staging), fp32 accumulate; v path already consumed
// as bf16 so input-rounding is the same error scale.
#define K4_LDA 40    // bf16 elems per A row (32 used)
#define K4_LDB 136   // bf16 elems per B row (128 used)
#define K4_LDC 132   // fp32 elems per C row
__global__ __launch_bounds__(256) void k_1x1_fused(
    const float* __restrict__ vw, const float* __restrict__ vb,
    const float* __restrict__ sw, const float* __restrict__ sb,
    const float* __restrict__ x)
{
    __shared__ __align__(32) char smemraw[64 * K4_LDC * 4];  // 33792B union
    __nv_bfloat16* As = (__nv_bfloat16*)smemraw;                       // [64][40]
    __nv_bfloat16* Bs = (__nv_bfloat16*)(smemraw + 64 * K4_LDA * 2);   // [32][136]
    float* Cs = (float*)smemraw;                                       // [64][132]

    int b  = blockIdx.z;
    int m0 = blockIdx.y * 64;
    int n0 = blockIdx.x * 128;
    int tid = threadIdx.x;
    int wid = tid / 32;
    int wm = wid % 2;
    int wn = wid / 2;

    bool vhalf = (m0 < 256);
    const float* W  = vhalf ? (vw + m0 * 256) : (sw + (m0 - 256) * 256);
    const float* bi = vhalf ? (vb + m0) : (sb + (m0 - 256));
    const float* xb = x + (size_t)b * CC * HW;

    wmma::fragment<wmma::accumulator, 16, 16, 16, float> acc[2][2];
#pragma unroll
    for (int i = 0; i < 2; i++)
#pragma unroll
        for (int j = 0; j < 2; j++) wmma::fill_fragment(acc[i][j], 0.f);

    for (int k0 = 0; k0 < 256; k0 += 32) {
        // As: 64 rows x 32 k (512 float4 sources, 2/thread)
#pragma unroll
        for (int i = tid; i < 512; i += 256) {
            int r = i / 8, q = i % 8;
            float4 wv = *(const float4*)&W[r * 256 + k0 + q * 4];
            __nv_bfloat162* d = (__nv_bfloat162*)&As[r * K4_LDA + q * 4];
            d[0] = __floats2bfloat162_rn(wv.x, wv.y);
            d[1] = __floats2bfloat162_rn(wv.z, wv.w);
        }
        // Bs: 32 rows x 128 n (1024 float4 sources, 4/thread)
#pragma unroll
        for (int i = tid; i < 1024; i += 256) {
            int r = i / 32, q = i % 32;
            float4 xv = *(const float4*)&xb[(size_t)(k0 + r) * HW + n0 + q * 4];
            __nv_bfloat162* d = (__nv_bfloat162*)&Bs[r * K4_LDB + q * 4];
            d[0] = __floats2bfloat162_rn(xv.x, xv.y);
            d[1] = __floats2bfloat162_rn(xv.z, xv.w);
        }
        __syncthreads();

#pragma unroll
        for (int kk = 0; kk < 32; kk += 16) {
            wmma::fragment<wmma::matrix_a, 16, 16, 16, __nv_bfloat16, wmma::row_major> af[2];
            wmma::fragment<wmma::matrix_b, 16, 16, 16, __nv_bfloat16, wmma::row_major> bf[2];
#pragma unroll
            for (int i = 0; i < 2; i++)
                wmma::load_matrix_sync(af[i], &As[(wm * 32 + i * 16) * K4_LDA + kk], K4_LDA);
#pragma unroll
            for (int j = 0; j < 2; j++)
                wmma::load_matrix_sync(bf[j], &Bs[kk * K4_LDB + wn * 32 + j * 16], K4_LDB);
#pragma unroll
            for (int i = 0; i < 2; i++)
#pragma unroll
                for (int j = 0; j < 2; j++)
                    wmma::mma_sync(acc[i][j], af[i], bf[j], acc[i][j]);
        }
        __syncthreads();
    }

#pragma unroll
    for (int i = 0; i < 2; i++)
#pragma unroll
        for (int j = 0; j < 2; j++)
            wmma::store_matrix_sync(&Cs[(wm * 32 + i * 16) * K4_LDC + wn * 32 + j * 16],
                                    acc[i][j], K4_LDC, wmma::mem_row_major);
    __syncthreads();

    if (vhalf) {
        __nv_bfloat16* ob = g_vh + (size_t)b * CC * HW;
#pragma unroll
        for (int i = tid; i < 2048; i += 256) {
            int r = i / 32, q = i % 32;
            float bo = bi[r];
            float4 c4 = *(const float4*)&Cs[r * K4_LDC + q * 4];
            __nv_bfloat162* d = (__nv_bfloat162*)&ob[(size_t)(m0 + r) * HW + n0 + q * 4];
            d[0] = __floats2bfloat162_rn(c4.x + bo, c4.y + bo);
            d[1] = __floats2bfloat162_rn(c4.z + bo, c4.w + bo);
        }
    } else {
        float* ob = g_v2 + (size_t)b * CC * HW;
#pragma unroll
        for (int i = tid; i < 2048; i += 256) {
            int r = i / 32, q = i % 32;
            float bo = bi[r];
            float4 c4 = *(const float4*)&Cs[r * K4_LDC + q * 4];
            float4 o = make_float4(c4.x + bo, c4.y + bo, c4.z + bo, c4.w + bo);
            *(float4*)&ob[(size_t)(m0 - 256 + r) * HW + n0 + q * 4] = o;
        }
    }
}

// ---------------- channel stats ----------------
__global__ __launch_bounds__(256) void k_chanstats(const float* __restrict__ x) {
    int bc = blockIdx.x;
    const float* p = x + (size_t)bc * HW;
    int tid = threadIdx.x;
    float s = 0.f, m = -INFINITY;
#pragma unroll
    for (int i = 0; i < 4; i++) {
        float4 v = ((const float4*)p)[i * 256 + tid];
        s += v.x + v.y + v.z + v.w;
        m = fmaxf(m, fmaxf(fmaxf(v.x, v.y), fmaxf(v.z, v.w)));
    }
    __shared__ float rs[256], rm[256];
    rs[tid] = s; rm[tid] = m; __syncthreads();
    for (int st = 128; st > 0; st >>= 1) {
        if (tid < st) { rs[tid] += rs[tid + st]; rm[tid] = fmaxf(rm[tid], rm[tid + st]); }
        __syncthreads();
    }
    if (tid == 0) { g_cmean[bc] = rs[0] * (1.f / 4096.f); g_cmax[bc] = rm[0]; }
}

// ---------------- channel gate FC ----------------
__global__ __launch_bounds__(256) void k_gate(
    const float* __restrict__ cw1, const float* __restrict__ cb1,
    const float* __restrict__ cw2, const float* __restrict__ cb2)
{
    int b = blockIdx.x;
    __shared__ float hsum[128];
    __shared__ float sme[256], sma[256];
    int tid = threadIdx.x;
    sme[tid] = g_cmean[b * 256 + tid];
    sma[tid] = g_cmax[b * 256 + tid];
    __syncthreads();
    if (tid < 128) {
        float am = cb1[tid], ax = cb1[tid];
        const float* wr = cw1 + tid * 256;
        for (int c = 0; c < 256; c++) { float w = wr[c]; am += w * sme[c]; ax += w * sma[c]; }
        hsum[tid] = fmaxf(am, 0.f) + fmaxf(ax, 0.f);
    }
    __syncthreads();
    float o = 2.f * cb2[tid];
    const float* wr = cw2 + tid * 128;
    for (int j = 0; j < 128; j++) o += wr[j] * hsum[j];
    g_gate[b * 256 + tid] = 1.f / (1.f + expf(-o));
}

// ---------------- v2 channel max/mean per pixel ----------------
__global__ __launch_bounds__(256) void k_smreduce() {
    int b = blockIdx.y;
    int p = blockIdx.x * 256 + threadIdx.x;
    const float* v2 = g_v2 + (size_t)b * CC * HW + p;
    float mx = -INFINITY, s = 0.f;
    for (int c = 0; c < 256; c++) {
        float v = v2[(size_t)c * HW];
        mx = fmaxf(mx, v); s += v;
    }
    g_sm[b * 8192 + p] = mx;
    g_sm[b * 8192 + 4096 + p] = s * (1.f / 256.f);
}

// ---------------- spatial conv 3x3 (2->1) + BN ----------------
__global__ __launch_bounds__(256) void k_sconv(
    const float* __restrict__ scw, const float* __restrict__ scb,
    const float* __restrict__ bs, const float* __restrict__ bbi,
    const float* __restrict__ bm, const float* __restrict__ bv)
{
    int b = blockIdx.y;
    int p = blockIdx.x * 256 + threadIdx.x;
    int h = p / 64, w = p % 64;
    float acc = 0.f;
    const float* smb = g_sm + b * 8192;
    for (int ci = 0; ci < 2; ci++)
#pragma unroll
        for (int dy = 0; dy < 3; dy++)
#pragma unroll
            for (int dx = 0; dx < 3; dx++) {
                int hh = h + dy - 1, ww = w + dx - 1;
                if (hh >= 0 && hh < 64 && ww >= 0 && ww < 64)
                    acc += scw[ci * 9 + dy * 3 + dx] * smb[ci * 4096 + hh * 64 + ww];
            }
    float A = rsqrtf(bv[0] + 1e-5f) * bs[0];
    g_att[b * 4096 + p] = (acc + scb[0] - bm[0]) * A + bbi[0];
}

// ---------------- softmax over W (rows of 64) -> g_a ----------------
__global__ __launch_bounds__(64) void k_rowsoftmax() {
    int row = blockIdx.x;
    int tid = threadIdx.x;
    float v = g_att[row * 64 + tid];
    __shared__ float red[64];
    red[tid] = v; __syncthreads();
    for (int s = 32; s > 0; s >>= 1) {
        if (tid < s) red[tid] = fmaxf(red[tid], red[tid + s]);
        __syncthreads();
    }
    float mx = red[0]; __syncthreads();
    float e = expf(v - mx);
    red[tid] = e; __syncthreads();
    for (int s = 32; s > 0; s >>= 1) {
        if (tid < s) red[tid] += red[tid + s];
        __syncthreads();
    }
    g_a[row * 64 + tid] = e / red[0];
}

// ---------------- spatialA[b,c,h,k] = sum_w x[b,c,h,w] * a[b,w,k] ----------------
__global__ __launch_bounds__(256) void k_spatial(const float* __restrict__ x) {
    int b = blockIdx.y, h = blockIdx.x;
    __shared__ float a_s[64 * 64];
    __shared__ float xs[4][64];
    int tid = threadIdx.x;
    for (int i = tid; i < 4096; i += 256) a_s[i] = g_a[b * 4096 + i];
    int cg = tid / 64, k = tid % 64;
    const float* xb = x + (size_t)b * CC * HW + h * 64;
    float* ob = g_spA + (size_t)b * CC * HW + h * 64;
    for (int c0 = 0; c0 < 256; c0 += 4) {
        __syncthreads();
        xs[cg][k] = xb[(size_t)(c0 + cg) * HW + k];
        __syncthreads();
        float acc = 0.f;
#pragma unroll 8
        for (int w = 0; w < 64; w++) acc += xs[cg][w] * a_s[w * 64 + k];
        ob[(size_t)(c0 + cg) * HW + k] = acc;
    }
}

// ---------------- K6 (bf16 wmma + cp.async 3-stage): out = gamma*(v@aff^T)+x*(1+gate)+spA
#define K6_LDS 72
#define K6_STAGE 36864
#define K6_LDC 132
__global__ void __launch_bounds__(256, 2) k_attn_out(
    const float* __restrict__ x, const float* __restrict__ gamma, float* __restrict__ out)
{
    extern __shared__ __align__(16) char dsm[];
    uint32_t smem_u32 = smem_to_u32(dsm);

    int b  = blockIdx.z;
    int c0 = blockIdx.y * 128;
    int n0 = blockIdx.x * 128;
    int tid = threadIdx.x;
    int wid = tid / 32;
    int wr = wid / 4;   // 0..1  c-direction (64 rows each)
    int wc = wid % 4;   // 0..3  n-direction (32 cols each)

    const __nv_bfloat16* vb = g_vh + (size_t)b * CC * HW + (size_t)c0 * HW;
    const __nv_bfloat16* ab = g_affh + (size_t)b * HW * HW + (size_t)n0 * HW;

    int r_[4], q_[4];
#pragma unroll
    for (int t = 0; t < 4; t++) {
        int idx = t * 256 + tid;
        r_[t] = idx >> 3;
        q_[t] = idx & 7;
    }

    auto stage = [&](int ck) {
        uint32_t base = smem_u32 + (ck % 3) * K6_STAGE;
        int m0 = ck * 64;
#pragma unroll
        for (int t = 0; t < 4; t++) {
            uint32_t off = (uint32_t)(r_[t] * K6_LDS + q_[t] * 8) * 2;
            CP_ASYNC_16(base + off, (const void*)&vb[(size_t)r_[t] * HW + m0 + q_[t] * 8]);
            CP_ASYNC_16(base + 18432 + off, (const void*)&ab[(size_t)r_[t] * HW + m0 + q_[t] * 8]);
        }
        CP_ASYNC_COMMIT();
    };

    wmma::fragment<wmma::accumulator, 16, 16, 16, float> acc[4][2];
#pragma unroll
    for (int i = 0; i < 4; i++)
#pragma unroll
        for (int j = 0; j < 2; j++) wmma::fill_fragment(acc[i][j], 0.f);

    stage(0);
    stage(1);

    for (int ck = 0; ck < 64; ck++) {
        if (ck < 63) CP_ASYNC_WAIT_1();
        else         CP_ASYNC_WAIT_0();
        __syncthreads();
        if (ck + 2 < 64) stage(ck + 2);

        const __nv_bfloat16* As = (const __nv_bfloat16*)(dsm + (ck % 3) * K6_STAGE);
        const __nv_bfloat16* Bs = (const __nv_bfloat16*)(dsm + (ck % 3) * K6_STAGE + 18432);

#pragma unroll
        for (int kk = 0; kk < 64; kk += 16) {
            wmma::fragment<wmma::matrix_a, 16, 16, 16, __nv_bfloat16, wmma::row_major> af[4];
            wmma::fragment<wmma::matrix_b, 16, 16, 16, __nv_bfloat16, wmma::col_major> bf[2];
#pragma unroll
            for (int i = 0; i < 4; i++)
                wmma::load_matrix_sync(af[i], &As[(wr * 64 + i * 16) * K6_LDS + kk], K6_LDS);
#pragma unroll
            for (int j = 0; j < 2; j++)
                wmma::load_matrix_sync(bf[j], &Bs[(wc * 32 + j * 16) * K6_LDS + kk], K6_LDS);
#pragma unroll
            for (int i = 0; i < 4; i++)
#pragma unroll
                for (int j = 0; j < 2; j++)
                    wmma::mma_sync(acc[i][j], af[i], bf[j], acc[i][j]);
        }
    }
    __syncthreads();

    float* Cs = (float*)dsm;
#pragma unroll
    for (int i = 0; i < 4; i++)
#pragma unroll
        for (int j = 0; j < 2; j++)
            wmma::store_matrix_sync(&Cs[(wr * 64 + i * 16) * K6_LDC + wc * 32 + j * 16],
                                    acc[i][j], K6_LDC, wmma::mem_row_major);
    __syncthreads();

    float g = gamma[0];
    const float* xb = x + (size_t)b * CC * HW;
    const float* sb = g_spA + (size_t)b * CC * HW;
#pragma unroll
    for (int i = tid; i < 4096; i += 256) {
        int r = i / 32, q = i % 32;
        int c = c0 + r;
        int nn = n0 + q * 4;
        float gt = 1.f + g_gate[b * 256 + c];
        float4 w4 = *(const float4*)&Cs[r * K6_LDC + q * 4];
        float4 xv = *(const float4*)&xb[(size_t)c * HW + nn];
        float4 sv = *(const float4*)&sb[(size_t)c * HW + nn];
        float4 o;
        o.x = g * w4.x + xv.x * gt + sv.x;
        o.y = g * w4.y + xv.y * gt + sv.y;
        o.z = g * w4.z + xv.z * gt + sv.z;
        o.w = g * w4.w + xv.w * gt + sv.w;
        *(float4*)&out[((size_t)b * CC + c) * HW + nn] = o;
    }
}

// ---------------- launch ----------------
extern "C" void kernel_launch(void* const* d_in, const int* in_sizes, int n_in,
                              void* d_out, int out_size) {
    const float* x     = (const float*)d_in[0];
    const float* q_w   = (const float*)d_in[1];
    const float* q_b   = (const float*)d_in[2];
    const float* q_bs  = (const float*)d_in[3];
    const float* q_bb  = (const float*)d_in[4];
    const float* q_bm  = (const float*)d_in[5];
    const float* q_bv  = (const float*)d_in[6];
    const float* k_w   = (const float*)d_in[7];
    const float* k_b   = (const float*)d_in[8];
    const float* k_bs  = (const float*)d_in[9];
    const float* k_bb  = (const float*)d_in[10];
    const float* k_bm  = (const float*)d_in[11];
    const float* k_bv  = (const float*)d_in[12];
    const float* v_w   = (const float*)d_in[13];
    const float* v_b   = (const float*)d_in[14];
    const float* gamma = (const float*)d_in[15];
    const float* c_w1  = (const float*)d_in[16];
    const float* c_b1  = (const float*)d_in[17];
    const float* c_w2  = (const float*)d_in[18];
    const float* c_b2  = (const float*)d_in[19];
    const float* s_vw  = (const float*)d_in[20];
    const float* s_vb  = (const float*)d_in[21];
    const float* s_cw  = (const float*)d_in[22];
    const float* s_cb  = (const float*)d_in[23];
    const float* s_bs  = (const float*)d_in[24];
    const float* s_bb  = (const float*)d_in[25];
    const float* s_bm  = (const float*)d_in[26];
    const float* s_bv  = (const float*)d_in[27];
    float* out = (float*)d_out;

    static bool attr_set = false;
    if (!attr_set) {
        cudaFuncSetAttribute(k_attn_out, cudaFuncAttributeMaxDynamicSharedMemorySize,
                             3 * K6_STAGE);
        cudaFuncSetAttribute(k_qk_gemm, cudaFuncAttributeMaxDynamicSharedMemorySize,
                             128 * K2_LD * 4);
        attr_set = true;
    }

    k_wt<<<288, 256>>>(q_w, k_w);
    k_qkconv<<<dim3(4, 8, BB * 4), dim3(16, 8)>>>(x);
    k_qkbn<<<dim3(16, 64, BB), 256>>>(q_b, q_bs, q_bb, q_bm, q_bv,
                                      k_b, k_bs, k_bb, k_bm, k_bv);
    // S = q^T k (tf32, 2 blocks/SM, coalesced store via smem)
    k_qk_gemm<<<dim3(32, 32, BB), 256, 128 * K2_LD * 4>>>();
    k_softmax<<<BB * HW, 256>>>();
    // fused v (bf16) + v2 (fp32) 1x1 convs on bf16 tensor path
    k_1x1_fused<<<dim3(32, 8, BB), 256>>>(v_w, v_b, s_vw, s_vb, x);
    k_chanstats<<<BB * CC, 256>>>(x);
    k_gate<<<BB, 256>>>(c_w1, c_b1, c_w2, c_b2);
    k_smreduce<<<dim3(16, BB), 256>>>();
    k_sconv<<<dim3(16, BB), 256>>>(s_cw, s_cb, s_bs, s_bb, s_bm, s_bv);
    k_rowsoftmax<<<BB * 64, 64>>>();
    k_spatial<<<dim3(64, BB), 256>>>(x);
    k_attn_out<<<dim3(32, 2, BB), 256, 3 * K6_STAGE>>>(x, gamma, out);
    (void)in_sizes; (void)n_in; (void)out_size;
}